// round 7
// baseline (speedup 1.0000x reference)
#include <cuda_runtime.h>
#include <cuda_bf16.h>

#define NB 4
#define NL 2048
#define ND 1024
#define NH 16
#define DH 64

#define QT  16    // query rows per attention CTA
#define SS  2052  // S row stride: %32==4 (bank spread), %4==0 (float4 ok)
#define KC  512   // phase-1 k-rows per chunk (16 dd wide per quarter)
#define KSP 20    // phase-1 chunk row stride (16 dd + 4 pad; phase-bank clean)
#define VC  128   // phase-3 v-rows per chunk (64 dd wide)
#define VSP 68    // phase-3 chunk row stride
#define QSP 68    // Q tile row stride
#define BUFW (KC*KSP)    // 10240 floats per ping-pong buffer (>= VC*VSP = 8704)
#define SMEM_FLOATS (QT*SS + 2*BUFW + QT*QSP + 16)

// ---- packed f32x2 helpers (SASS FFMA2 — only reachable via PTX) ----
__device__ __forceinline__ unsigned long long pk2(float v) {
    unsigned long long r;
    asm("mov.b64 %0, {%1, %2};" : "=l"(r) : "f"(v), "f"(v));
    return r;
}
__device__ __forceinline__ void fma2(unsigned long long& d,
                                     unsigned long long a, unsigned long long b) {
    asm("fma.rn.f32x2 %0, %1, %2, %0;" : "+l"(d) : "l"(a), "l"(b));
}
__device__ __forceinline__ void unpk(unsigned long long v, float& lo, float& hi) {
    asm("mov.b64 {%0, %1}, %2;" : "=f"(lo), "=f"(hi) : "l"(v));
}
// ---- cp.async helpers ----
__device__ __forceinline__ void cpasync16(unsigned dst, const float* src) {
    asm volatile("cp.async.cg.shared.global [%0], [%1], 16;" :: "r"(dst), "l"(src) : "memory");
}
__device__ __forceinline__ void cp_commit() {
    asm volatile("cp.async.commit_group;" ::: "memory");
}
__device__ __forceinline__ void cp_wait0() {
    asm volatile("cp.async.wait_group 0;" ::: "memory");
}
__device__ __forceinline__ void cp_wait1() {
    asm volatile("cp.async.wait_group 1;" ::: "memory");
}

// Scratch (device globals — no allocation allowed in kernel_launch)
__device__ float g_k[(size_t)NB * NH * NL * DH];
__device__ float g_v[(size_t)NB * NH * NL * DH];
__device__ float g_q[(size_t)NB * NH * NL * DH];
__device__ float g_ctx[(size_t)NB * NL * ND];

// ---------------------------------------------------------------------------
// SGEMM: dst = (A[M,1024] @ W[1024,1024] + bias) * scale   (packed FFMA2)
// 128x128 block tile, 8x8 microtile, K-tile 16, double-buffered smem with
// register prefetch. (unchanged — known good)
// ---------------------------------------------------------------------------
__global__ __launch_bounds__(256, 2) void sgemm_bias_kernel(
    const float* __restrict__ A, const float* __restrict__ W,
    const float* __restrict__ bias, float* __restrict__ dst,
    float scale, int scatter)
{
    __shared__ float As[2][16][128];
    __shared__ float Bs[2][16][128];

    const int t  = threadIdx.x;
    const int m0 = blockIdx.y * 128;
    const int n0 = blockIdx.x * 128;
    const int ty = t >> 4, tx = t & 15;

    unsigned long long acc2[4][8];
#pragma unroll
    for (int ip = 0; ip < 4; ip++)
#pragma unroll
        for (int j = 0; j < 8; j++) acc2[ip][j] = 0ull;

    float4 pa[2], pb[2];
#pragma unroll
    for (int i = 0; i < 2; i++) {
        const int idx = t + i * 256;
        pa[i] = *(const float4*)(A + (size_t)(m0 + (idx >> 2)) * ND + ((idx & 3) * 4));
        pb[i] = *(const float4*)(W + (size_t)(idx >> 5) * ND + n0 + (idx & 31) * 4);
    }
#pragma unroll
    for (int i = 0; i < 2; i++) {
        const int idx = t + i * 256;
        const int r = idx >> 2, c = (idx & 3) * 4;
        As[0][c + 0][r] = pa[i].x; As[0][c + 1][r] = pa[i].y;
        As[0][c + 2][r] = pa[i].z; As[0][c + 3][r] = pa[i].w;
        *(float4*)&Bs[0][idx >> 5][(idx & 31) * 4] = pb[i];
    }
    __syncthreads();

    int cur = 0;
    for (int k0 = 0; k0 < ND; k0 += 16) {
        const int has_next = (k0 + 16 < ND);
        if (has_next) {
#pragma unroll
            for (int i = 0; i < 2; i++) {
                const int idx = t + i * 256;
                pa[i] = *(const float4*)(A + (size_t)(m0 + (idx >> 2)) * ND + k0 + 16 + ((idx & 3) * 4));
                pb[i] = *(const float4*)(W + (size_t)(k0 + 16 + (idx >> 5)) * ND + n0 + (idx & 31) * 4);
            }
        }
#pragma unroll
        for (int kk = 0; kk < 16; kk++) {
            const ulonglong2 ap0 = *(const ulonglong2*)&As[cur][kk][ty * 8];
            const ulonglong2 ap1 = *(const ulonglong2*)&As[cur][kk][ty * 8 + 4];
            const float4 b0 = *(const float4*)&Bs[cur][kk][tx * 8];
            const float4 b1 = *(const float4*)&Bs[cur][kk][tx * 8 + 4];
            unsigned long long bd[8];
            bd[0] = pk2(b0.x); bd[1] = pk2(b0.y); bd[2] = pk2(b0.z); bd[3] = pk2(b0.w);
            bd[4] = pk2(b1.x); bd[5] = pk2(b1.y); bd[6] = pk2(b1.z); bd[7] = pk2(b1.w);
#pragma unroll
            for (int j = 0; j < 8; j++) {
                fma2(acc2[0][j], ap0.x, bd[j]);
                fma2(acc2[1][j], ap0.y, bd[j]);
                fma2(acc2[2][j], ap1.x, bd[j]);
                fma2(acc2[3][j], ap1.y, bd[j]);
            }
        }
        if (has_next) {
            const int nxt = cur ^ 1;
#pragma unroll
            for (int i = 0; i < 2; i++) {
                const int idx = t + i * 256;
                const int r = idx >> 2, c = (idx & 3) * 4;
                As[nxt][c + 0][r] = pa[i].x; As[nxt][c + 1][r] = pa[i].y;
                As[nxt][c + 2][r] = pa[i].z; As[nxt][c + 3][r] = pa[i].w;
                *(float4*)&Bs[nxt][idx >> 5][(idx & 31) * 4] = pb[i];
            }
        }
        __syncthreads();
        cur ^= 1;
    }

#pragma unroll
    for (int ip = 0; ip < 4; ip++) {
#pragma unroll
        for (int j = 0; j < 8; j++) {
            float lo, hi;
            unpk(acc2[ip][j], lo, hi);
            const int c = n0 + tx * 8 + j;
            const float bias_c = bias[c];
#pragma unroll
            for (int s = 0; s < 2; s++) {
                const int r = m0 + ty * 8 + ip * 2 + s;
                const float v = ((s ? hi : lo) + bias_c) * scale;
                if (scatter) {
                    const int b = r >> 11, l = r & (NL - 1);
                    const int h = c >> 6,  d = c & 63;
                    dst[((size_t)(b * NH + h) * NL + l) * DH + d] = v;
                } else {
                    dst[(size_t)r * ND + c] = v;
                }
            }
        }
    }
}

// ---------------------------------------------------------------------------
// Attention: per (b, h, 16-query tile), 256 threads.
// Phase 1: S = Q@K^T; chunks of 512 k-rows x 16 dd (4 quarters per kt-block),
//          per-thread tile 8q x 4k (acc[8][4] ull, 1.33:1 FMA:LDS).
// Phase 2: single-pass masked exp + row sums (normalization deferred).
// Phase 3: ctx = P@V, 16 chunks of 128 rows x 64 dd, ksplit x8 + reduction.
// All K/V streaming via 2-stage cp.async ping-pong.
// ---------------------------------------------------------------------------
__global__ __launch_bounds__(256, 1) void attn_kernel(
    const int* __restrict__ mask, float* __restrict__ attn_out)
{
    extern __shared__ float sm[];
    float* S    = sm;                    // QT * SS
    float* bufp[2];
    bufp[0] = S + QT * SS;               // BUFW
    bufp[1] = bufp[0] + BUFW;            // BUFW
    float* Qs   = bufp[1] + BUFW;        // QT * QSP
    float* invs = Qs + QT * QSP;         // 16

    unsigned bufa[2];
    bufa[0] = (unsigned)__cvta_generic_to_shared(bufp[0]);
    bufa[1] = (unsigned)__cvta_generic_to_shared(bufp[1]);

    const int t  = threadIdx.x;
    const int q0 = blockIdx.x * QT;
    const int h  = blockIdx.y;
    const int b  = blockIdx.z;

    const float* qptr = g_q + (size_t)(b * NH + h) * NL * DH;
    const float* kptr = g_k + (size_t)(b * NH + h) * NL * DH;
    const float* vptr = g_v + (size_t)(b * NH + h) * NL * DH;

    // Load Q tile [16][64] (visible after first pipeline sync)
    for (int idx = t; idx < QT * DH; idx += 256) {
        const int q = idx >> 6, d = idx & 63;
        Qs[q * QSP + d] = qptr[(size_t)(q0 + q) * DH + d];
    }

    // ---------------- Phase 1: S = Q @ K^T (pipelined) ----------------
    {
        const int qg = t >> 7;       // 0..1 : 8 q-rows (warp-uniform)
        const int kg = t & 127;      // k-rows kg + 128j, j=0..3

        unsigned long long acc[8][4];
#pragma unroll
        for (int i = 0; i < 8; i++)
#pragma unroll
            for (int j = 0; j < 4; j++) acc[i][j] = 0ull;

        // chunk c: kt = (c>>2)*KC, dd-quarter dh0 = (c&3)*16
        // issue chunk 0
#pragma unroll
        for (int i2 = 0; i2 < 8; i2++) {
            const int idx = t + i2 * 256;
            const int row = idx >> 2, cc = (idx & 3) * 4;
            cpasync16(bufa[0] + (unsigned)(row * KSP + cc) * 4,
                      kptr + (size_t)row * DH + cc);
        }
        cp_commit();

        for (int c = 0; c < 16; c++) {
            if (c + 1 < 16) {
                const int kt1 = ((c + 1) >> 2) * KC, dh1 = ((c + 1) & 3) * 16;
                const unsigned ba = bufa[(c + 1) & 1];
#pragma unroll
                for (int i2 = 0; i2 < 8; i2++) {
                    const int idx = t + i2 * 256;
                    const int row = idx >> 2, cc = (idx & 3) * 4;
                    cpasync16(ba + (unsigned)(row * KSP + cc) * 4,
                              kptr + (size_t)(kt1 + row) * DH + dh1 + cc);
                }
                cp_commit();
                cp_wait1();
            } else {
                cp_wait0();
            }
            __syncthreads();

            const float* bcur = bufp[c & 1];
            const int dh0c = (c & 3) * 16;
#pragma unroll 2
            for (int dd4 = 0; dd4 < 16; dd4 += 4) {
                ulonglong2 kv[4];
#pragma unroll
                for (int j = 0; j < 4; j++)
                    kv[j] = *(const ulonglong2*)(bcur + (kg + 128 * j) * KSP + dd4);
#pragma unroll
                for (int i = 0; i < 8; i++) {
                    const ulonglong2 qv =
                        *(const ulonglong2*)(Qs + (qg * 8 + i) * QSP + dh0c + dd4);
#pragma unroll
                    for (int j = 0; j < 4; j++) {
                        fma2(acc[i][j], qv.x, kv[j].x);
                        fma2(acc[i][j], qv.y, kv[j].y);
                    }
                }
            }
            if ((c & 3) == 3) {   // all 4 dd-quarters of this kt done -> flush
                const int kt = (c >> 2) * KC;
#pragma unroll
                for (int i = 0; i < 8; i++) {
#pragma unroll
                    for (int j = 0; j < 4; j++) {
                        float lo, hi;
                        unpk(acc[i][j], lo, hi);
                        S[(qg * 8 + i) * SS + kt + kg + 128 * j] = lo + hi;
                        acc[i][j] = 0ull;
                    }
                }
            }
            __syncthreads();
        }
    }

    // prefetch phase-3 V chunk 0 (overlaps the whole softmax)
#pragma unroll
    for (int i2 = 0; i2 < 8; i2++) {
        const int idx = t + i2 * 256;
        const int row = idx >> 4, cc = (idx & 15) * 4;
        cpasync16(bufa[0] + (unsigned)(row * VSP + cc) * 4,
                  vptr + (size_t)row * DH + cc);
    }
    cp_commit();

    // ---------------- Phase 2: masked exp + sums (single pass) ----------------
    {
        const int w = t >> 5, lane = t & 31;
#pragma unroll
        for (int rr = 0; rr < 2; rr++) {
            const int r  = w * 2 + rr;
            const int qq = q0 + r;
            const int4* mrow4 = (const int4*)(mask + ((size_t)b * NL + qq) * NL);
            float4* srow4 = (float4*)(S + r * SS);

            float sum = 0.f;
            for (int i = lane; i < NL / 4; i += 32) {
                const float4 s = srow4[i];
                const int4   m = mrow4[i];
                float4 p;
                p.x = m.x ? 0.f : __expf(s.x);
                p.y = m.y ? 0.f : __expf(s.y);
                p.z = m.z ? 0.f : __expf(s.z);
                p.w = m.w ? 0.f : __expf(s.w);
                srow4[i] = p;
                sum += p.x + p.y + p.z + p.w;
            }
#pragma unroll
            for (int o = 16; o > 0; o >>= 1)
                sum += __shfl_xor_sync(0xffffffffu, sum, o);

            const float inv = 1.f / sum;
            if (lane == 0) invs[r] = inv;
            if (h == 0) {
                float4* arow4 = (float4*)(attn_out + ((size_t)b * NL + qq) * NL);
                for (int i = lane; i < NL / 4; i += 32) {
                    float4 p = srow4[i];
                    p.x *= inv; p.y *= inv; p.z *= inv; p.w *= inv;
                    arow4[i] = p;
                }
            }
        }
    }
    __syncthreads();

    // ---------------- Phase 3: ctx = P @ V (pipelined, ksplit x8) ----------------
    {
        const int ks = t >> 5;        // 0..7 : 16-row k-chunk within each 128-row tile
        const int qg = (t >> 4) & 1;  // 0..1 : 8 q-rows each
        const int dg = t & 15;        // 0..15: d columns dg*4 .. dg*4+3

        unsigned long long acc[8][2];
#pragma unroll
        for (int i = 0; i < 8; i++) { acc[i][0] = 0ull; acc[i][1] = 0ull; }

        for (int c = 0; c < 16; c++) {
            if (c + 1 < 16) {
                const unsigned ba = bufa[(c + 1) & 1];
#pragma unroll
                for (int i2 = 0; i2 < 8; i2++) {
                    const int idx = t + i2 * 256;
                    const int row = idx >> 4, cc = (idx & 15) * 4;
                    cpasync16(ba + (unsigned)(row * VSP + cc) * 4,
                              vptr + (size_t)((c + 1) * VC + row) * DH + cc);
                }
                cp_commit();
                cp_wait1();
            } else {
                cp_wait0();
            }
            __syncthreads();

            const float* bcur = bufp[c & 1];
#pragma unroll
            for (int kk4 = 0; kk4 < 16; kk4 += 4) {
                float4 pv[8];
#pragma unroll
                for (int i = 0; i < 8; i++)
                    pv[i] = *(const float4*)(S + (qg * 8 + i) * SS + c * VC + ks * 16 + kk4);
#pragma unroll
                for (int kk = 0; kk < 4; kk++) {
                    const ulonglong2 vv =
                        *(const ulonglong2*)(bcur + (ks * 16 + kk4 + kk) * VSP + dg * 4);
#pragma unroll
                    for (int i = 0; i < 8; i++) {
                        const float pf = (kk == 0) ? pv[i].x : (kk == 1) ? pv[i].y
                                       : (kk == 2) ? pv[i].z : pv[i].w;
                        const unsigned long long pd = pk2(pf);
                        fma2(acc[i][0], pd, vv.x);
                        fma2(acc[i][1], pd, vv.y);
                    }
                }
            }
            __syncthreads();
        }

        // reduction across the 8 k-split groups (red aliased onto buffers)
        float* red = bufp[0];
#pragma unroll
        for (int i = 0; i < 8; i++) {
            float* rb = red + ((ks * QT) + qg * 8 + i) * DH + dg * 4;
            *(unsigned long long*)(rb)     = acc[i][0];
            *(unsigned long long*)(rb + 2) = acc[i][1];
        }
        __syncthreads();

        float* ctx = g_ctx + (size_t)(b * NL + q0) * ND + h * DH;
        for (int idx = t; idx < QT * DH; idx += 256) {
            const int q = idx >> 6, d = idx & 63;
            float s = 0.f;
#pragma unroll
            for (int g = 0; g < 8; g++) s += red[(g * QT + q) * DH + d];
            ctx[(size_t)q * ND + d] = s * invs[q];
        }
    }
}

// ---------------------------------------------------------------------------
extern "C" void kernel_launch(void* const* d_in, const int* in_sizes, int n_in,
                              void* d_out, int out_size)
{
    const float* key   = (const float*)d_in[0];
    const float* value = (const float*)d_in[1];
    const float* query = (const float*)d_in[2];
    const int*   mask  = (const int*)d_in[3];
    const float* Wk = (const float*)d_in[4];
    const float* bk = (const float*)d_in[5];
    const float* Wv = (const float*)d_in[6];
    const float* bv = (const float*)d_in[7];
    const float* Wq = (const float*)d_in[8];
    const float* bq = (const float*)d_in[9];
    const float* Wo = (const float*)d_in[10];
    const float* bo = (const float*)d_in[11];

    float* out      = (float*)d_out;
    float* attn_out = out + (size_t)NB * NL * ND;

    float *gk, *gv, *gq, *gctx;
    cudaGetSymbolAddress((void**)&gk,   g_k);
    cudaGetSymbolAddress((void**)&gv,   g_v);
    cudaGetSymbolAddress((void**)&gq,   g_q);
    cudaGetSymbolAddress((void**)&gctx, g_ctx);

    static int attr_set = 0;
    if (!attr_set) {
        cudaFuncSetAttribute(attn_kernel,
                             cudaFuncAttributeMaxDynamicSharedMemorySize,
                             SMEM_FLOATS * (int)sizeof(float));
        attr_set = 1;
    }

    const dim3 gemm_grid(ND / 128, (NB * NL) / 128);  // 8 x 64
    sgemm_bias_kernel<<<gemm_grid, 256>>>(key,   Wk, bk, gk, 1.0f,   1);
    sgemm_bias_kernel<<<gemm_grid, 256>>>(value, Wv, bv, gv, 1.0f,   1);
    sgemm_bias_kernel<<<gemm_grid, 256>>>(query, Wq, bq, gq, 0.125f, 1);

    const dim3 attn_grid(NL / QT, NH, NB);            // 128 x 16 x 4
    attn_kernel<<<attn_grid, 256, SMEM_FLOATS * (int)sizeof(float)>>>(mask, attn_out);

    sgemm_bias_kernel<<<gemm_grid, 256>>>(gctx, Wo, bo, out, 1.0f, 0);
}

// round 9
// speedup vs baseline: 1.2994x; 1.2994x over previous
#include <cuda_runtime.h>
#include <cuda_bf16.h>

#define NB 4
#define NL 2048
#define ND 1024
#define NH 16
#define DH 64

// ---------------- attention tiling (round-4 proven config) ----------------
#define QT  16
#define SS  2052
#define KT1 512
#define KSP 36
#define KT3 256
#define VSP 68
#define QSP 68
#define BUFF (KT1*KSP)
#define SMEM_FLOATS (QT*SS + BUFF + QT*QSP)

// ---------------- mma.sync GEMM config ----------------
#define BK    32                 // k per chunk
#define ASTR  40                 // smem row stride in bf16 (80B: bank-clean)
#define TILE_B (128*ASTR*2)      // 10240 B per split tile
#define STAGE_B (4*TILE_B)       // 40960 B per stage (A0,A1,B0,B1)
#define GSMEM  (2*STAGE_B)       // 81920 B

// ---- packed f32x2 helpers (SASS FFMA2) ----
__device__ __forceinline__ unsigned long long pk2(float v) {
    unsigned long long r;
    asm("mov.b64 %0, {%1, %2};" : "=l"(r) : "f"(v), "f"(v));
    return r;
}
__device__ __forceinline__ void fma2(unsigned long long& d,
                                     unsigned long long a, unsigned long long b) {
    asm("fma.rn.f32x2 %0, %1, %2, %0;" : "+l"(d) : "l"(a), "l"(b));
}
__device__ __forceinline__ void unpk(unsigned long long v, float& lo, float& hi) {
    asm("mov.b64 {%0, %1}, %2;" : "=f"(lo), "=f"(hi) : "l"(v));
}
// ---- cp.async ----
__device__ __forceinline__ void cpasync16(unsigned dst, const void* src) {
    asm volatile("cp.async.cg.shared.global [%0], [%1], 16;" :: "r"(dst), "l"(src) : "memory");
}
__device__ __forceinline__ void cp_commit() { asm volatile("cp.async.commit_group;" ::: "memory"); }
__device__ __forceinline__ void cp_wait0()  { asm volatile("cp.async.wait_group 0;" ::: "memory"); }
__device__ __forceinline__ void cp_wait1()  { asm volatile("cp.async.wait_group 1;" ::: "memory"); }
__device__ __forceinline__ unsigned smem_u32(const void* p) {
    unsigned a;
    asm("{ .reg .u64 t; cvta.to.shared.u64 t, %1; cvt.u32.u64 %0, t; }" : "=r"(a) : "l"(p));
    return a;
}
// ---- tensor-core (baseline PTX, no sm_103a feature needed) ----
__device__ __forceinline__ void ldsm4(unsigned& r0, unsigned& r1,
                                      unsigned& r2, unsigned& r3, unsigned addr) {
    asm volatile("ldmatrix.sync.aligned.m8n8.x4.shared.b16 {%0,%1,%2,%3}, [%4];"
                 : "=r"(r0), "=r"(r1), "=r"(r2), "=r"(r3) : "r"(addr));
}
__device__ __forceinline__ void mma16816(float* d, const unsigned* a,
                                         unsigned b0, unsigned b1) {
    asm volatile(
        "mma.sync.aligned.m16n8k16.row.col.f32.bf16.bf16.f32 "
        "{%0,%1,%2,%3}, {%4,%5,%6,%7}, {%8,%9}, {%0,%1,%2,%3};"
        : "+f"(d[0]), "+f"(d[1]), "+f"(d[2]), "+f"(d[3])
        : "r"(a[0]), "r"(a[1]), "r"(a[2]), "r"(a[3]), "r"(b0), "r"(b1));
}

// Scratch device globals
__device__ float g_k[(size_t)NB * NH * NL * DH];
__device__ float g_v[(size_t)NB * NH * NL * DH];
__device__ float g_q[(size_t)NB * NH * NL * DH];
__device__ __nv_bfloat16 g_a0[(size_t)NB * NL * ND];
__device__ __nv_bfloat16 g_a1[(size_t)NB * NL * ND];
__device__ __nv_bfloat16 g_w0[(size_t)ND * ND];
__device__ __nv_bfloat16 g_w1[(size_t)ND * ND];

// ---------------------------------------------------------------------------
// convA: fp32 [M,1024] -> bf16 hi/lo splits in g_a0/g_a1
// ---------------------------------------------------------------------------
__global__ void convA_kernel(const float* __restrict__ src)
{
    const size_t i = ((size_t)blockIdx.x * 256 + threadIdx.x) * 4;
    const float4 v = *(const float4*)(src + i);
    __nv_bfloat16 h0 = __float2bfloat16(v.x), h1 = __float2bfloat16(v.y);
    __nv_bfloat16 h2 = __float2bfloat16(v.z), h3 = __float2bfloat16(v.w);
    __nv_bfloat162 hi01, hi23, lo01, lo23;
    hi01.x = h0; hi01.y = h1; hi23.x = h2; hi23.y = h3;
    lo01.x = __float2bfloat16(v.x - __bfloat162float(h0));
    lo01.y = __float2bfloat16(v.y - __bfloat162float(h1));
    lo23.x = __float2bfloat16(v.z - __bfloat162float(h2));
    lo23.y = __float2bfloat16(v.w - __bfloat162float(h3));
    *(__nv_bfloat162*)(g_a0 + i)     = hi01;
    *(__nv_bfloat162*)(g_a0 + i + 2) = hi23;
    *(__nv_bfloat162*)(g_a1 + i)     = lo01;
    *(__nv_bfloat162*)(g_a1 + i + 2) = lo23;
}

// ---------------------------------------------------------------------------
// convW: fp32 W[k][n] -> transposed bf16 splits g_w0/g_w1 [n][k]
// ---------------------------------------------------------------------------
__global__ void convW_kernel(const float* __restrict__ W)
{
    __shared__ float tile[32][33];
    const int k0 = blockIdx.y * 32, n0 = blockIdx.x * 32;
    for (int r = threadIdx.y; r < 32; r += 8)
        tile[r][threadIdx.x] = W[(size_t)(k0 + r) * ND + n0 + threadIdx.x];
    __syncthreads();
    for (int r = threadIdx.y; r < 32; r += 8) {
        const float v = tile[threadIdx.x][r];  // = W[k0+tx][n0+r]
        const size_t o = (size_t)(n0 + r) * ND + k0 + threadIdx.x;
        __nv_bfloat16 hi = __float2bfloat16(v);
        g_w0[o] = hi;
        g_w1[o] = __float2bfloat16(v - __bfloat162float(hi));
    }
}

// ---------------------------------------------------------------------------
// mma.sync GEMM: dst = (A @ W + bias) * scale.
// A via splits g_a0/g_a1 [M,K]; W via transposed splits g_w0/g_w1 [N,K].
// 3xBF16 (a0b0 + a0b1 + a1b0), fp32 acc. 128x128 CTA tile, 8 warps (4m x 2n),
// warp tile 32x64. cp.async double-buffered K=32 chunks; ldmatrix fragments.
// ---------------------------------------------------------------------------
__global__ void __launch_bounds__(256, 1) gemm_mma_kernel(
    const float* __restrict__ bias, float* __restrict__ dst,
    float scale, int scatter)
{
    extern __shared__ char smem[];
    const unsigned sb0 = smem_u32(smem);
    const int t = threadIdx.x, lane = t & 31, wid = t >> 5;
    const int wm = (wid & 3) * 32, wn = (wid >> 2) * 64;
    const int n0 = blockIdx.x * 128, m0 = blockIdx.y * 128;

    const __nv_bfloat16* srcs[4] = {
        g_a0 + (size_t)m0 * ND, g_a1 + (size_t)m0 * ND,
        g_w0 + (size_t)n0 * ND, g_w1 + (size_t)n0 * ND };

    float acc[2][8][4];
#pragma unroll
    for (int mt = 0; mt < 2; mt++)
#pragma unroll
        for (int nt = 0; nt < 8; nt++)
#pragma unroll
            for (int r = 0; r < 4; r++) acc[mt][nt][r] = 0.f;

    // ldmatrix per-lane source coords
    const int arow = (lane & 7) | (lane & 8);          // A: rows 0-15
    const int acol = (lane & 16) >> 1;                 // A: k +0 / +8
    const int brow = (lane & 7) | ((lane & 16) >> 1);  // B: n-rows 0-15
    const int bcol = lane & 8;                         // B: k +0 / +8

    // issue chunk c into stage c&1
#define ISSUE(c) do {                                                          \
    const unsigned sb = sb0 + ((c) & 1) * STAGE_B;                             \
    const int k0 = (c) * BK;                                                   \
    _Pragma("unroll")                                                          \
    for (int s = 0; s < 4; s++) {                                              \
        _Pragma("unroll")                                                      \
        for (int i = 0; i < 2; i++) {                                          \
            const int u = t + i * 256;                                         \
            const int row = u >> 2, seg = u & 3;                               \
            cpasync16(sb + s * TILE_B + (row * ASTR + seg * 8) * 2,            \
                      srcs[s] + (size_t)row * ND + k0 + seg * 8);              \
        }                                                                      \
    }                                                                          \
    cp_commit();                                                               \
} while (0)

    ISSUE(0);
    for (int c = 0; c < ND / BK; c++) {
        if (c + 1 < ND / BK) { ISSUE(c + 1); cp_wait1(); }
        else                 { cp_wait0(); }
        __syncthreads();

        const unsigned sb = sb0 + (c & 1) * STAGE_B;
#pragma unroll
        for (int ks = 0; ks < 2; ks++) {
            const int kc = ks * 16;
            unsigned af[2][2][4];   // [split][mtile][4]
#pragma unroll
            for (int sp = 0; sp < 2; sp++)
#pragma unroll
                for (int mt = 0; mt < 2; mt++)
                    ldsm4(af[sp][mt][0], af[sp][mt][1], af[sp][mt][2], af[sp][mt][3],
                          sb + sp * TILE_B +
                          (unsigned)(((wm + mt * 16 + arow) * ASTR + kc + acol) * 2));
            unsigned bf[2][4][4];   // [split][ntile-pair][4]
#pragma unroll
            for (int sp = 0; sp < 2; sp++)
#pragma unroll
                for (int np = 0; np < 4; np++)
                    ldsm4(bf[sp][np][0], bf[sp][np][1], bf[sp][np][2], bf[sp][np][3],
                          sb + (2 + sp) * TILE_B +
                          (unsigned)(((wn + np * 16 + brow) * ASTR + kc + bcol) * 2));
#pragma unroll
            for (int mt = 0; mt < 2; mt++)
#pragma unroll
                for (int nt = 0; nt < 8; nt++) {
                    const int np = nt >> 1, half = (nt & 1) * 2;
                    mma16816(acc[mt][nt], af[0][mt], bf[0][np][half], bf[0][np][half + 1]);
                    mma16816(acc[mt][nt], af[0][mt], bf[1][np][half], bf[1][np][half + 1]);
                    mma16816(acc[mt][nt], af[1][mt], bf[0][np][half], bf[0][np][half + 1]);
                }
        }
        __syncthreads();
    }
#undef ISSUE

    // epilogue: bias + scale (+ optional scatter to [B,H,L,dh])
#pragma unroll
    for (int mt = 0; mt < 2; mt++)
#pragma unroll
        for (int nt = 0; nt < 8; nt++)
#pragma unroll
            for (int r = 0; r < 4; r++) {
                const int row = wm + mt * 16 + (lane >> 2) + ((r >= 2) ? 8 : 0);
                const int col = wn + nt * 8 + (lane & 3) * 2 + (r & 1);
                const int m = m0 + row, cc = n0 + col;
                const float v = (acc[mt][nt][r] + bias[cc]) * scale;
                if (scatter) {
                    const int b = m >> 11, l = m & (NL - 1);
                    const int h = cc >> 6, d = cc & 63;
                    dst[((size_t)(b * NH + h) * NL + l) * DH + d] = v;
                } else {
                    dst[(size_t)m * ND + cc] = v;
                }
            }
}

// ---------------------------------------------------------------------------
// Attention (round-4 proven core): per (b,h,16-q tile), 256 threads.
// Epilogue writes ctx bf16 splits directly into g_a0/g_a1.
// ---------------------------------------------------------------------------
__global__ __launch_bounds__(256, 1) void attn_kernel(
    const int* __restrict__ mask, float* __restrict__ attn_out)
{
    extern __shared__ float sm[];
    float* S   = sm;
    float* buf = S + QT * SS;
    float* Qs  = buf + BUFF;

    const int t  = threadIdx.x;
    const int q0 = blockIdx.x * QT;
    const int h  = blockIdx.y;
    const int b  = blockIdx.z;

    const float* qptr = g_q + (size_t)(b * NH + h) * NL * DH;
    const float* kptr = g_k + (size_t)(b * NH + h) * NL * DH;
    const float* vptr = g_v + (size_t)(b * NH + h) * NL * DH;

    for (int idx = t; idx < QT * DH; idx += 256) {
        const int q = idx >> 6, d = idx & 63;
        Qs[q * QSP + d] = qptr[(size_t)(q0 + q) * DH + d];
    }

    {   // Phase 1: S = Q @ K^T
        const int qg = t >> 7;
        const int kg = t & 127;
        for (int kt = 0; kt < NL; kt += KT1) {
            unsigned long long acc[8][4];
#pragma unroll
            for (int i = 0; i < 8; i++)
#pragma unroll
                for (int j = 0; j < 4; j++) acc[i][j] = 0ull;
#pragma unroll
            for (int half = 0; half < 2; half++) {
                const int dh0 = half * 32;
                __syncthreads();
#pragma unroll
                for (int i = 0; i < 16; i++) {
                    const int idx = t + i * 256;
                    const int row = idx >> 3, c = (idx & 7) * 4;
                    const float4 v = *(const float4*)(kptr + (size_t)(kt + row) * DH + dh0 + c);
                    *(float4*)(buf + row * KSP + c) = v;
                }
                __syncthreads();
#pragma unroll
                for (int dd4 = 0; dd4 < 32; dd4 += 4) {
                    ulonglong2 kv[4];
#pragma unroll
                    for (int j = 0; j < 4; j++)
                        kv[j] = *(const ulonglong2*)(buf + (kg + 128 * j) * KSP + dd4);
#pragma unroll
                    for (int i = 0; i < 8; i++) {
                        const ulonglong2 qv =
                            *(const ulonglong2*)(Qs + (qg * 8 + i) * QSP + dh0 + dd4);
#pragma unroll
                        for (int j = 0; j < 4; j++) {
                            fma2(acc[i][j], qv.x, kv[j].x);
                            fma2(acc[i][j], qv.y, kv[j].y);
                        }
                    }
                }
            }
#pragma unroll
            for (int i = 0; i < 8; i++)
#pragma unroll
                for (int j = 0; j < 4; j++) {
                    float lo, hi;
                    unpk(acc[i][j], lo, hi);
                    S[(qg * 8 + i) * SS + kt + kg + 128 * j] = lo + hi;
                }
        }
    }
    __syncthreads();

    {   // Phase 2: masked softmax
        const int w = t >> 5, lane = t & 31;
#pragma unroll
        for (int rr = 0; rr < 2; rr++) {
            const int r  = w * 2 + rr;
            const int qq = q0 + r;
            const int4* mrow4 = (const int4*)(mask + ((size_t)b * NL + qq) * NL);
            float4* srow4 = (float4*)(S + r * SS);

            float mx = -3.0e38f;
            for (int i = lane; i < NL / 4; i += 32) {
                const float4 s = srow4[i];
                const int4   m = mrow4[i];
                mx = fmaxf(mx, m.x ? -1.0e18f : s.x);
                mx = fmaxf(mx, m.y ? -1.0e18f : s.y);
                mx = fmaxf(mx, m.z ? -1.0e18f : s.z);
                mx = fmaxf(mx, m.w ? -1.0e18f : s.w);
            }
#pragma unroll
            for (int o = 16; o > 0; o >>= 1)
                mx = fmaxf(mx, __shfl_xor_sync(0xffffffffu, mx, o));

            float sum = 0.f;
            for (int i = lane; i < NL / 4; i += 32) {
                const float4 s = srow4[i];
                const int4   m = mrow4[i];
                float4 p;
                p.x = m.x ? 0.f : __expf(s.x - mx);
                p.y = m.y ? 0.f : __expf(s.y - mx);
                p.z = m.z ? 0.f : __expf(s.z - mx);
                p.w = m.w ? 0.f : __expf(s.w - mx);
                srow4[i] = p;
                sum += p.x + p.y + p.z + p.w;
            }
#pragma unroll
            for (int o = 16; o > 0; o >>= 1)
                sum += __shfl_xor_sync(0xffffffffu, sum, o);

            const float inv = 1.f / sum;
            if (h == 0) {
                float4* arow4 = (float4*)(attn_out + ((size_t)b * NL + qq) * NL);
                for (int i = lane; i < NL / 4; i += 32) {
                    float4 p = srow4[i];
                    p.x *= inv; p.y *= inv; p.z *= inv; p.w *= inv;
                    srow4[i] = p;
                    arow4[i] = p;
                }
            } else {
                for (int i = lane; i < NL / 4; i += 32) {
                    float4 p = srow4[i];
                    p.x *= inv; p.y *= inv; p.z *= inv; p.w *= inv;
                    srow4[i] = p;
                }
            }
        }
    }

    {   // Phase 3: ctx = P @ V  (ksplit x4 + reduction)
        const int g  = t >> 6;
        const int u  = t & 63;
        const int uq = u >> 4;
        const int ud = u & 15;
        const int lrow = t >> 4;
        const int lcol = (t & 15) * 4;

        unsigned long long acc3[4][2];
#pragma unroll
        for (int i = 0; i < 4; i++) { acc3[i][0] = 0ull; acc3[i][1] = 0ull; }

        for (int kt = 0; kt < NL; kt += KT3) {
            __syncthreads();
#pragma unroll
            for (int it = 0; it < KT3 / 16; it++) {
                const int row = it * 16 + lrow;
                const float4 v4 = *(const float4*)(vptr + (size_t)(kt + row) * DH + lcol);
                *(float4*)(buf + row * VSP + lcol) = v4;
            }
            __syncthreads();

            const float* p0 = S + (uq * 4 + 0) * SS + kt + g * 64;
            const float* p1 = S + (uq * 4 + 1) * SS + kt + g * 64;
            const float* p2 = S + (uq * 4 + 2) * SS + kt + g * 64;
            const float* p3 = S + (uq * 4 + 3) * SS + kt + g * 64;
#pragma unroll 4
            for (int kk = 0; kk < 64; kk++) {
                const ulonglong2 vp = *(const ulonglong2*)(buf + (g * 64 + kk) * VSP + ud * 4);
                const unsigned long long pd0 = pk2(p0[kk]);
                const unsigned long long pd1 = pk2(p1[kk]);
                const unsigned long long pd2 = pk2(p2[kk]);
                const unsigned long long pd3 = pk2(p3[kk]);
                fma2(acc3[0][0], pd0, vp.x); fma2(acc3[0][1], pd0, vp.y);
                fma2(acc3[1][0], pd1, vp.x); fma2(acc3[1][1], pd1, vp.y);
                fma2(acc3[2][0], pd2, vp.x); fma2(acc3[2][1], pd2, vp.y);
                fma2(acc3[3][0], pd3, vp.x); fma2(acc3[3][1], pd3, vp.y);
            }
        }
        __syncthreads();
        float* red = buf;
#pragma unroll
        for (int i = 0; i < 4; i++) {
            float* rb = red + ((g * QT) + uq * 4 + i) * DH + ud * 4;
            *(unsigned long long*)(rb)     = acc3[i][0];
            *(unsigned long long*)(rb + 2) = acc3[i][1];
        }
        __syncthreads();

        for (int idx = t; idx < QT * DH; idx += 256) {
            const int q = idx >> 6, d = idx & 63;
            const float s = red[q * DH + d] + red[(QT + q) * DH + d] +
                            red[(2 * QT + q) * DH + d] + red[(3 * QT + q) * DH + d];
            const size_t o = (size_t)(b * NL + q0 + q) * ND + h * DH + d;
            const __nv_bfloat16 hi = __float2bfloat16(s);
            g_a0[o] = hi;
            g_a1[o] = __float2bfloat16(s - __bfloat162float(hi));
        }
    }
}

// ---------------------------------------------------------------------------
extern "C" void kernel_launch(void* const* d_in, const int* in_sizes, int n_in,
                              void* d_out, int out_size)
{
    const float* key   = (const float*)d_in[0];
    const float* value = (const float*)d_in[1];
    const float* query = (const float*)d_in[2];
    const int*   mask  = (const int*)d_in[3];
    const float* Wk = (const float*)d_in[4];
    const float* bk = (const float*)d_in[5];
    const float* Wv = (const float*)d_in[6];
    const float* bv = (const float*)d_in[7];
    const float* Wq = (const float*)d_in[8];
    const float* bq = (const float*)d_in[9];
    const float* Wo = (const float*)d_in[10];
    const float* bo = (const float*)d_in[11];

    float* out      = (float*)d_out;
    float* attn_out = out + (size_t)NB * NL * ND;

    float *gk, *gv, *gq;
    cudaGetSymbolAddress((void**)&gk, g_k);
    cudaGetSymbolAddress((void**)&gv, g_v);
    cudaGetSymbolAddress((void**)&gq, g_q);

    static int attr_set = 0;
    if (!attr_set) {
        cudaFuncSetAttribute(attn_kernel, cudaFuncAttributeMaxDynamicSharedMemorySize,
                             SMEM_FLOATS * (int)sizeof(float));
        cudaFuncSetAttribute(gemm_mma_kernel, cudaFuncAttributeMaxDynamicSharedMemorySize,
                             GSMEM);
        attr_set = 1;
    }

    const int convA_blocks = (NB * NL * ND) / (4 * 256);   // 8192
    const dim3 convW_grid(ND / 32, ND / 32);
    const dim3 convW_block(32, 8);
    const dim3 gemm_grid(ND / 128, (NB * NL) / 128);        // 8 x 64

    convA_kernel<<<convA_blocks, 256>>>(key);
    convW_kernel<<<convW_grid, convW_block>>>(Wk);
    gemm_mma_kernel<<<gemm_grid, 256, GSMEM>>>(bk, gk, 1.0f, 1);

    convA_kernel<<<convA_blocks, 256>>>(value);
    convW_kernel<<<convW_grid, convW_block>>>(Wv);
    gemm_mma_kernel<<<gemm_grid, 256, GSMEM>>>(bv, gv, 1.0f, 1);

    convA_kernel<<<convA_blocks, 256>>>(query);
    convW_kernel<<<convW_grid, convW_block>>>(Wq);
    gemm_mma_kernel<<<gemm_grid, 256, GSMEM>>>(bq, gq, 0.125f, 1);

    const dim3 attn_grid(NL / QT, NH, NB);                  // 128 x 16 x 4
    attn_kernel<<<attn_grid, 256, SMEM_FLOATS * (int)sizeof(float)>>>(mask, attn_out);

    convW_kernel<<<convW_grid, convW_block>>>(Wo);
    gemm_mma_kernel<<<gemm_grid, 256, GSMEM>>>(bo, out, 1.0f, 0);
}

// round 10
// speedup vs baseline: 2.5704x; 1.9781x over previous
#include <cuda_runtime.h>
#include <cuda_bf16.h>

#define NB 4
#define NL 2048
#define ND 1024
#define NH 16
#define DH 64

// ---------------- mma.sync GEMM config (round-9 proven) ----------------
#define BK    32
#define ASTR  40
#define TILE_B (128*ASTR*2)
#define STAGE_B (4*TILE_B)
#define GSMEM  (2*STAGE_B)

// ---------------- fused attention config ----------------
#define QT    32                  // q rows per CTA
#define KCH   128                 // k rows per chunk
#define KST   72                  // K smem row stride (bf16)
#define VST   136                 // V smem row stride (bf16)
#define KTILE (KCH*KST*2)         // 18432 B per split
#define VTILE (64*VST*2)          // 17408 B per split
#define MSK_OFF (2*KTILE + 2*VTILE)   // 71680
#define ASTAGE  (MSK_OFF + 512)       // 72192
#define QOFF    (2*ASTAGE)            // 144384
#define QSPL    (QT*KST*2)            // 4608 per split
#define RSPOFF  (QOFF + 2*QSPL)       // 153600
#define INVOFF  (RSPOFF + 8*QT*4)     // 154624
#define ASMEM   (INVOFF + QT*4)       // 154752

// ---- cp.async ----
__device__ __forceinline__ void cpasync16(unsigned dst, const void* src) {
    asm volatile("cp.async.cg.shared.global [%0], [%1], 16;" :: "r"(dst), "l"(src) : "memory");
}
__device__ __forceinline__ void cp_commit() { asm volatile("cp.async.commit_group;" ::: "memory"); }
__device__ __forceinline__ void cp_wait0()  { asm volatile("cp.async.wait_group 0;" ::: "memory"); }
__device__ __forceinline__ void cp_wait1()  { asm volatile("cp.async.wait_group 1;" ::: "memory"); }
__device__ __forceinline__ unsigned smem_u32(const void* p) {
    unsigned a;
    asm("{ .reg .u64 t; cvta.to.shared.u64 t, %1; cvt.u32.u64 %0, t; }" : "=r"(a) : "l"(p));
    return a;
}
// ---- tensor-core (baseline PTX) ----
__device__ __forceinline__ void ldsm4(unsigned& r0, unsigned& r1,
                                      unsigned& r2, unsigned& r3, unsigned addr) {
    asm volatile("ldmatrix.sync.aligned.m8n8.x4.shared.b16 {%0,%1,%2,%3}, [%4];"
                 : "=r"(r0), "=r"(r1), "=r"(r2), "=r"(r3) : "r"(addr));
}
__device__ __forceinline__ void mma16816(float* d, const unsigned* a,
                                         unsigned b0, unsigned b1) {
    asm volatile(
        "mma.sync.aligned.m16n8k16.row.col.f32.bf16.bf16.f32 "
        "{%0,%1,%2,%3}, {%4,%5,%6,%7}, {%8,%9}, {%0,%1,%2,%3};"
        : "+f"(d[0]), "+f"(d[1]), "+f"(d[2]), "+f"(d[3])
        : "r"(a[0]), "r"(a[1]), "r"(a[2]), "r"(a[3]), "r"(b0), "r"(b1));
}
// pack two f32 into bf16x2 (lo = pe, hi = po)
__device__ __forceinline__ unsigned pkbf2(float pe, float po) {
    unsigned d;
    asm("cvt.rn.bf16x2.f32 %0, %1, %2;" : "=r"(d) : "f"(po), "f"(pe));
    return d;
}
// split pair (pe,po) -> hi word + residual lo word
__device__ __forceinline__ void split2(float pe, float po, unsigned& hi, unsigned& lo) {
    hi = pkbf2(pe, po);
    const float re = pe - __uint_as_float(hi << 16);
    const float ro = po - __uint_as_float(hi & 0xFFFF0000u);
    lo = pkbf2(re, ro);
}

// Scratch device globals
__device__ __nv_bfloat16 g_a0[(size_t)NB * NL * ND];
__device__ __nv_bfloat16 g_a1[(size_t)NB * NL * ND];
__device__ __nv_bfloat16 g_w0[(size_t)ND * ND];
__device__ __nv_bfloat16 g_w1[(size_t)ND * ND];
__device__ __nv_bfloat16 g_k0[(size_t)NB * NL * ND];
__device__ __nv_bfloat16 g_k1[(size_t)NB * NL * ND];
__device__ __nv_bfloat16 g_q0[(size_t)NB * NL * ND];
__device__ __nv_bfloat16 g_q1[(size_t)NB * NL * ND];
__device__ __nv_bfloat16 g_v0[(size_t)NB * NL * ND];
__device__ __nv_bfloat16 g_v1[(size_t)NB * NL * ND];
__device__ __nv_bfloat16 g_vt0[(size_t)NB * NL * ND];
__device__ __nv_bfloat16 g_vt1[(size_t)NB * NL * ND];
__device__ unsigned g_mbits[(size_t)NB * NL * (NL / 32)];
__device__ float    g_rsum[(size_t)NB * NL];

// ---------------------------------------------------------------------------
// convA: fp32 [M,1024] -> bf16 hi/lo splits in g_a0/g_a1
// ---------------------------------------------------------------------------
__global__ void convA_kernel(const float* __restrict__ src)
{
    const size_t i = ((size_t)blockIdx.x * 256 + threadIdx.x) * 4;
    const float4 v = *(const float4*)(src + i);
    unsigned h0, l0, h1, l1;
    split2(v.x, v.y, h0, l0);
    split2(v.z, v.w, h1, l1);
    *(unsigned*)(g_a0 + i)     = h0;
    *(unsigned*)(g_a0 + i + 2) = h1;
    *(unsigned*)(g_a1 + i)     = l0;
    *(unsigned*)(g_a1 + i + 2) = l1;
}

// ---------------------------------------------------------------------------
// convW: fp32 W[k][n] -> transposed bf16 splits g_w0/g_w1 [n][k]
// ---------------------------------------------------------------------------
__global__ void convW_kernel(const float* __restrict__ W)
{
    __shared__ float tile[32][33];
    const int k0 = blockIdx.y * 32, n0 = blockIdx.x * 32;
    for (int r = threadIdx.y; r < 32; r += 8)
        tile[r][threadIdx.x] = W[(size_t)(k0 + r) * ND + n0 + threadIdx.x];
    __syncthreads();
    for (int r = threadIdx.y; r < 32; r += 8) {
        const float v = tile[threadIdx.x][r];
        const size_t o = (size_t)(n0 + r) * ND + k0 + threadIdx.x;
        __nv_bfloat16 hi = __float2bfloat16(v);
        g_w0[o] = hi;
        g_w1[o] = __float2bfloat16(v - __bfloat162float(hi));
    }
}

// ---------------------------------------------------------------------------
// vtrans: g_v0/1 [bh][l][d] -> g_vt0/1 [bh][d][l]
// ---------------------------------------------------------------------------
__global__ void vtrans_kernel()
{
    __shared__ __nv_bfloat16 tl[2][64][65];
    const int bh = blockIdx.y;
    const int l0 = blockIdx.x * 64;
    const size_t pin = (size_t)bh * NL * DH;
#pragma unroll
    for (int s = 0; s < 2; s++) {
        const __nv_bfloat16* src = (s ? g_v1 : g_v0) + pin;
#pragma unroll
        for (int i = 0; i < 8; i++) {
            const int u = threadIdx.x + i * 256;
            const int li = u >> 5, dp = u & 31;
            const __nv_bfloat162 v = *(const __nv_bfloat162*)(src + (size_t)(l0 + li) * DH + dp * 2);
            tl[s][li][dp * 2]     = v.x;
            tl[s][li][dp * 2 + 1] = v.y;
        }
    }
    __syncthreads();
    const size_t pout = (size_t)bh * DH * NL;
#pragma unroll
    for (int s = 0; s < 2; s++) {
        __nv_bfloat16* dst = (s ? g_vt1 : g_vt0) + pout;
#pragma unroll
        for (int i = 0; i < 8; i++) {
            const int u = threadIdx.x + i * 256;
            const int d = u >> 5, lp = u & 31;
            __nv_bfloat162 v;
            v.x = tl[s][lp * 2][d];
            v.y = tl[s][lp * 2 + 1][d];
            *(__nv_bfloat162*)(dst + (size_t)d * NL + l0 + lp * 2) = v;
        }
    }
}

// ---------------------------------------------------------------------------
// mask2bits: int32 mask -> bit-packed words (bit k = mask[...,k] != 0)
// ---------------------------------------------------------------------------
__global__ void mask2bits_kernel(const int* __restrict__ mask)
{
    const int gw = (blockIdx.x * 256 + threadIdx.x) >> 5;
    const int lane = threadIdx.x & 31;
    const int nwords = NB * NL * (NL / 32);
    const int step = (gridDim.x * 256) >> 5;
    for (int wv = gw; wv < nwords; wv += step) {
        const int v = mask[(size_t)wv * 32 + lane];
        const unsigned bits = __ballot_sync(0xffffffffu, v != 0);
        if (lane == 0) g_mbits[wv] = bits;
    }
}

// ---------------------------------------------------------------------------
// norm_attn: attn_out rows /= rsum
// ---------------------------------------------------------------------------
__global__ void norm_attn_kernel(float* __restrict__ attn_out)
{
    const int row = blockIdx.x;
    const float inv = 1.f / g_rsum[row];
    float4* p = (float4*)(attn_out + (size_t)row * NL);
    for (int i = threadIdx.x; i < NL / 4; i += 256) {
        float4 v = p[i];
        v.x *= inv; v.y *= inv; v.z *= inv; v.w *= inv;
        p[i] = v;
    }
}

// ---------------------------------------------------------------------------
// mma.sync GEMM (round-9 core). mode 0: fp32 out [m][n] -> dstf.
// mode 1: bf16 split pair scatter [b,h,l,d] -> dst0/dst1.
// ---------------------------------------------------------------------------
__global__ void __launch_bounds__(256, 1) gemm_mma_kernel(
    const float* __restrict__ bias, float* __restrict__ dstf,
    __nv_bfloat16* __restrict__ dst0, __nv_bfloat16* __restrict__ dst1,
    float scale, int mode)
{
    extern __shared__ char smem[];
    const unsigned sb0 = smem_u32(smem);
    const int t = threadIdx.x, lane = t & 31, wid = t >> 5;
    const int wm = (wid & 3) * 32, wn = (wid >> 2) * 64;
    const int n0 = blockIdx.x * 128, m0 = blockIdx.y * 128;

    const __nv_bfloat16* srcs[4] = {
        g_a0 + (size_t)m0 * ND, g_a1 + (size_t)m0 * ND,
        g_w0 + (size_t)n0 * ND, g_w1 + (size_t)n0 * ND };

    float acc[2][8][4];
#pragma unroll
    for (int mt = 0; mt < 2; mt++)
#pragma unroll
        for (int nt = 0; nt < 8; nt++)
#pragma unroll
            for (int r = 0; r < 4; r++) acc[mt][nt][r] = 0.f;

    const int arow = (lane & 7) | (lane & 8);
    const int acol = (lane & 16) >> 1;
    const int brow = (lane & 7) | ((lane & 16) >> 1);
    const int bcol = lane & 8;

#define ISSUE(c) do {                                                          \
    const unsigned sb = sb0 + ((c) & 1) * STAGE_B;                             \
    const int k0 = (c) * BK;                                                   \
    _Pragma("unroll")                                                          \
    for (int s = 0; s < 4; s++) {                                              \
        _Pragma("unroll")                                                      \
        for (int i = 0; i < 2; i++) {                                          \
            const int u = t + i * 256;                                         \
            const int row = u >> 2, seg = u & 3;                               \
            cpasync16(sb + s * TILE_B + (row * ASTR + seg * 8) * 2,            \
                      srcs[s] + (size_t)row * ND + k0 + seg * 8);              \
        }                                                                      \
    }                                                                          \
    cp_commit();                                                               \
} while (0)

    ISSUE(0);
    for (int c = 0; c < ND / BK; c++) {
        if (c + 1 < ND / BK) { ISSUE(c + 1); cp_wait1(); }
        else                 { cp_wait0(); }
        __syncthreads();

        const unsigned sb = sb0 + (c & 1) * STAGE_B;
#pragma unroll
        for (int ks = 0; ks < 2; ks++) {
            const int kc = ks * 16;
            unsigned af[2][2][4];
#pragma unroll
            for (int sp = 0; sp < 2; sp++)
#pragma unroll
                for (int mt = 0; mt < 2; mt++)
                    ldsm4(af[sp][mt][0], af[sp][mt][1], af[sp][mt][2], af[sp][mt][3],
                          sb + sp * TILE_B +
                          (unsigned)(((wm + mt * 16 + arow) * ASTR + kc + acol) * 2));
            unsigned bf[2][4][4];
#pragma unroll
            for (int sp = 0; sp < 2; sp++)
#pragma unroll
                for (int np = 0; np < 4; np++)
                    ldsm4(bf[sp][np][0], bf[sp][np][1], bf[sp][np][2], bf[sp][np][3],
                          sb + (2 + sp) * TILE_B +
                          (unsigned)(((wn + np * 16 + brow) * ASTR + kc + bcol) * 2));
#pragma unroll
            for (int mt = 0; mt < 2; mt++)
#pragma unroll
                for (int nt = 0; nt < 8; nt++) {
                    const int np = nt >> 1, half = (nt & 1) * 2;
                    mma16816(acc[mt][nt], af[0][mt], bf[0][np][half], bf[0][np][half + 1]);
                    mma16816(acc[mt][nt], af[0][mt], bf[1][np][half], bf[1][np][half + 1]);
                    mma16816(acc[mt][nt], af[1][mt], bf[0][np][half], bf[0][np][half + 1]);
                }
        }
        __syncthreads();
    }
#undef ISSUE

#pragma unroll
    for (int mt = 0; mt < 2; mt++)
#pragma unroll
        for (int nt = 0; nt < 8; nt++) {
            const int cc = n0 + wn + nt * 8 + (lane & 3) * 2;
            const float b0 = bias[cc], b1 = bias[cc + 1];
            const float v0 = (acc[mt][nt][0] + b0) * scale;
            const float v1 = (acc[mt][nt][1] + b1) * scale;
            const float v2 = (acc[mt][nt][2] + b0) * scale;
            const float v3 = (acc[mt][nt][3] + b1) * scale;
            const int r0 = m0 + wm + mt * 16 + (lane >> 2);
            if (mode == 0) {
                dstf[(size_t)r0 * ND + cc]           = v0;
                dstf[(size_t)r0 * ND + cc + 1]       = v1;
                dstf[(size_t)(r0 + 8) * ND + cc]     = v2;
                dstf[(size_t)(r0 + 8) * ND + cc + 1] = v3;
            } else {
                const int bb = r0 >> 11, h = cc >> 6, d = cc & 63;
                unsigned hi, lo;
                split2(v0, v1, hi, lo);
                size_t o = ((size_t)(bb * NH + h) * NL + (r0 & (NL - 1))) * DH + d;
                *(unsigned*)(dst0 + o) = hi;
                *(unsigned*)(dst1 + o) = lo;
                split2(v2, v3, hi, lo);
                o = ((size_t)(bb * NH + h) * NL + ((r0 + 8) & (NL - 1))) * DH + d;
                *(unsigned*)(dst0 + o) = hi;
                *(unsigned*)(dst1 + o) = lo;
            }
        }
}

// ---------------------------------------------------------------------------
// Fused flash-style attention: per (b, h, 32-q tile), 256 threads, 8 warps.
// Per 128-k chunk: warp w computes S subtile [32 q][16 k] (k-cols w*16..+16)
// via 3-split bf16 mma, masks+exps in registers, repacks c-frags as PV
// a-frags (bf16 splits), multiplies by V chunk. Normalization deferred.
// ---------------------------------------------------------------------------
__global__ void __launch_bounds__(256, 1) attn_fused_kernel(
    float* __restrict__ attn_out)
{
    extern __shared__ char smem[];
    const unsigned sb = smem_u32(smem);
    const int t = threadIdx.x, lane = t & 31, w = t >> 5;
    const int q0 = blockIdx.x * QT;
    const int h = blockIdx.y, b = blockIdx.z;
    const int bh = b * NH + h;

    const __nv_bfloat16* kp0 = g_k0 + (size_t)bh * NL * DH;
    const __nv_bfloat16* kp1 = g_k1 + (size_t)bh * NL * DH;
    const __nv_bfloat16* vp0 = g_vt0 + (size_t)bh * DH * NL;
    const __nv_bfloat16* vp1 = g_vt1 + (size_t)bh * DH * NL;
    const __nv_bfloat16* qp0 = g_q0 + (size_t)bh * NL * DH;
    const __nv_bfloat16* qp1 = g_q1 + (size_t)bh * NL * DH;

    const int arow = (lane & 7) | (lane & 8);
    const int acol = (lane & 16) >> 1;
    const int brow = (lane & 7) | ((lane & 16) >> 1);
    const int bcol = lane & 8;

    // Q tile -> smem (joins chunk-0 cp.async group)
#pragma unroll
    for (int i = 0; i < 2; i++) {
        const int u = t + i * 256;
        const int s = u >> 8, r = (u >> 3) & 31, seg = u & 7;
        cpasync16(sb + QOFF + s * QSPL + r * (KST * 2) + seg * 16,
                  (s ? qp1 : qp0) + (size_t)(q0 + r) * DH + seg * 8);
    }

    const unsigned* mb = g_mbits;

#define AISSUE(c) do {                                                           \
    const unsigned st_ = sb + ((c) & 1) * ASTAGE;                                \
    const int kt_ = (c) * KCH;                                                   \
    _Pragma("unroll")                                                            \
    for (int i = 0; i < 8; i++) {                                                \
        const int u = t + i * 256;                                               \
        const int s = u >> 10, r = (u >> 3) & 127, seg = u & 7;                  \
        cpasync16(st_ + s * KTILE + r * (KST * 2) + seg * 16,                    \
                  (s ? kp1 : kp0) + (size_t)(kt_ + r) * DH + seg * 8);           \
    }                                                                            \
    _Pragma("unroll")                                                            \
    for (int i = 0; i < 8; i++) {                                                \
        const int u = t + i * 256;                                               \
        const int s = u >> 10, r = (u >> 4) & 63, seg = u & 15;                  \
        cpasync16(st_ + 2 * KTILE + s * VTILE + r * (VST * 2) + seg * 16,        \
                  (s ? vp1 : vp0) + (size_t)r * NL + kt_ + seg * 8);             \
    }                                                                            \
    if (t < QT)                                                                  \
        cpasync16(st_ + MSK_OFF + t * 16,                                        \
                  mb + ((size_t)b * NL + q0 + t) * (NL / 32) + (kt_ >> 5));      \
    cp_commit();                                                                 \
} while (0)

    float accv[2][8][4];
#pragma unroll
    for (int mt = 0; mt < 2; mt++)
#pragma unroll
        for (int nt = 0; nt < 8; nt++)
#pragma unroll
            for (int r = 0; r < 4; r++) accv[mt][nt][r] = 0.f;
    float rs[2][2] = {{0.f, 0.f}, {0.f, 0.f}};

    AISSUE(0);
    for (int c = 0; c < NL / KCH; c++) {
        if (c + 1 < NL / KCH) { AISSUE(c + 1); cp_wait1(); }
        else                  { cp_wait0(); }
        __syncthreads();
        const unsigned st = sb + (c & 1) * ASTAGE;
        const int kt = c * KCH;

        // ---- QK: S subtile [32][16] ----
        float accs[2][2][4];
#pragma unroll
        for (int mt = 0; mt < 2; mt++)
#pragma unroll
            for (int nt = 0; nt < 2; nt++)
#pragma unroll
                for (int r = 0; r < 4; r++) accs[mt][nt][r] = 0.f;

#pragma unroll
        for (int ks = 0; ks < 4; ks++) {
            const int kc = ks * 16;
            unsigned aq[2][2][4];
#pragma unroll
            for (int s = 0; s < 2; s++)
#pragma unroll
                for (int mt = 0; mt < 2; mt++)
                    ldsm4(aq[s][mt][0], aq[s][mt][1], aq[s][mt][2], aq[s][mt][3],
                          sb + QOFF + s * QSPL +
                          (unsigned)((mt * 16 + arow) * (KST * 2) + (kc + acol) * 2));
            unsigned bk[2][4];
#pragma unroll
            for (int s = 0; s < 2; s++)
                ldsm4(bk[s][0], bk[s][1], bk[s][2], bk[s][3],
                      st + s * KTILE +
                      (unsigned)((w * 16 + brow) * (KST * 2) + (kc + bcol) * 2));
#pragma unroll
            for (int mt = 0; mt < 2; mt++)
#pragma unroll
                for (int nt = 0; nt < 2; nt++) {
                    mma16816(accs[mt][nt], aq[0][mt], bk[0][nt * 2], bk[0][nt * 2 + 1]);
                    mma16816(accs[mt][nt], aq[0][mt], bk[1][nt * 2], bk[1][nt * 2 + 1]);
                    mma16816(accs[mt][nt], aq[1][mt], bk[0][nt * 2], bk[0][nt * 2 + 1]);
                }
        }

        // ---- mask + exp + repack to PV a-frags ----
        unsigned ap0[2][4], ap1[2][4];
#pragma unroll
        for (int mt = 0; mt < 2; mt++) {
            const int r = lane >> 2;
            const unsigned mw0 = *(const unsigned*)(smem + (c & 1) * ASTAGE + MSK_OFF +
                                                    (mt * 16 + r) * 16 + (w >> 1) * 4);
            const unsigned mw1 = *(const unsigned*)(smem + (c & 1) * ASTAGE + MSK_OFF +
                                                    (mt * 16 + r + 8) * 16 + (w >> 1) * 4);
            const int bbase = (w & 1) * 16;
            float p[2][4];
#pragma unroll
            for (int nt = 0; nt < 2; nt++) {
                const int xb = bbase + nt * 8 + 2 * (lane & 3);
                p[nt][0] = ((mw0 >> xb) & 1)       ? 0.f : __expf(accs[mt][nt][0]);
                p[nt][1] = ((mw0 >> (xb + 1)) & 1) ? 0.f : __expf(accs[mt][nt][1]);
                p[nt][2] = ((mw1 >> xb) & 1)       ? 0.f : __expf(accs[mt][nt][2]);
                p[nt][3] = ((mw1 >> (xb + 1)) & 1) ? 0.f : __expf(accs[mt][nt][3]);
            }
            rs[mt][0] += p[0][0] + p[0][1] + p[1][0] + p[1][1];
            rs[mt][1] += p[0][2] + p[0][3] + p[1][2] + p[1][3];
            if (h == 0) {
                const size_t base = ((size_t)b * NL + q0 + mt * 16 + r) * NL + kt + w * 16;
                const int cc = 2 * (lane & 3);
                *(float2*)(attn_out + base + cc)               = make_float2(p[0][0], p[0][1]);
                *(float2*)(attn_out + base + 8 + cc)           = make_float2(p[1][0], p[1][1]);
                *(float2*)(attn_out + base + (size_t)8 * NL + cc)     = make_float2(p[0][2], p[0][3]);
                *(float2*)(attn_out + base + (size_t)8 * NL + 8 + cc) = make_float2(p[1][2], p[1][3]);
            }
            split2(p[0][0], p[0][1], ap0[mt][0], ap1[mt][0]);
            split2(p[0][2], p[0][3], ap0[mt][1], ap1[mt][1]);
            split2(p[1][0], p[1][1], ap0[mt][2], ap1[mt][2]);
            split2(p[1][2], p[1][3], ap0[mt][3], ap1[mt][3]);
        }

        // ---- PV ----
        unsigned bv[2][4][4];
#pragma unroll
        for (int s = 0; s < 2; s++)
#pragma unroll
            for (int np = 0; np < 4; np++)
                ldsm4(bv[s][np][0], bv[s][np][1], bv[s][np][2], bv[s][np][3],
                      st + 2 * KTILE + s * VTILE +
                      (unsigned)((np * 16 + brow) * (VST * 2) + (w * 16 + bcol) * 2));
#pragma unroll
        for (int mt = 0; mt < 2; mt++)
#pragma unroll
            for (int nt = 0; nt < 8; nt++) {
                const int np = nt >> 1, hf = (nt & 1) * 2;
                mma16816(accv[mt][nt], ap0[mt], bv[0][np][hf], bv[0][np][hf + 1]);
                mma16816(accv[mt][nt], ap0[mt], bv[1][np][hf], bv[1][np][hf + 1]);
                mma16816(accv[mt][nt], ap1[mt], bv[0][np][hf], bv[0][np][hf + 1]);
            }
        __syncthreads();
    }
#undef AISSUE

    // ---- row-sum reduce ----
#pragma unroll
    for (int mt = 0; mt < 2; mt++)
#pragma unroll
        for (int hf = 0; hf < 2; hf++) {
            float v = rs[mt][hf];
            v += __shfl_xor_sync(0xffffffffu, v, 1);
            v += __shfl_xor_sync(0xffffffffu, v, 2);
            if ((lane & 3) == 0)
                *(float*)(smem + RSPOFF + (w * QT + mt * 16 + hf * 8 + (lane >> 2)) * 4) = v;
        }

    // ---- PV cross-warp reduce via swizzled smem (reuses stage 0 area) ----
    float* red = (float*)smem;
#pragma unroll
    for (int mt = 0; mt < 2; mt++)
#pragma unroll
        for (int nt = 0; nt < 8; nt++) {
            const int r0 = mt * 16 + (lane >> 2);
            const int cc = nt * 8 + 2 * (lane & 3);
            *(float2*)&red[(w * QT + r0) * 64 + (cc ^ ((r0 & 3) << 3))] =
                make_float2(accv[mt][nt][0], accv[mt][nt][1]);
            const int r1 = r0 + 8;
            *(float2*)&red[(w * QT + r1) * 64 + (cc ^ ((r1 & 3) << 3))] =
                make_float2(accv[mt][nt][2], accv[mt][nt][3]);
        }
    __syncthreads();

    float* invs = (float*)(smem + INVOFF);
    if (t < QT) {
        float s = 0.f;
#pragma unroll
        for (int ww = 0; ww < 8; ww++)
            s += *(float*)(smem + RSPOFF + (ww * QT + t) * 4);
        invs[t] = 1.f / s;
        if (h == 0) g_rsum[(size_t)b * NL + q0 + t] = s;
    }
    __syncthreads();

    for (int idx = t; idx < QT * DH / 2; idx += 256) {
        const int q = idx >> 5, dp = idx & 31;
        const int d0 = dp * 2, sw = (q & 3) << 3;
        float s0 = 0.f, s1 = 0.f;
#pragma unroll
        for (int ww = 0; ww < 8; ww++) {
            const float* rr = &red[(ww * QT + q) * 64];
            s0 += rr[d0 ^ sw];
            s1 += rr[(d0 + 1) ^ sw];
        }
        const float inv = invs[q];
        s0 *= inv; s1 *= inv;
        unsigned hi, lo;
        split2(s0, s1, hi, lo);
        const size_t off = ((size_t)(b * NL + q0 + q)) * ND + h * DH + d0;
        *(unsigned*)(g_a0 + off) = hi;
        *(unsigned*)(g_a1 + off) = lo;
    }
}

// ---------------------------------------------------------------------------
extern "C" void kernel_launch(void* const* d_in, const int* in_sizes, int n_in,
                              void* d_out, int out_size)
{
    const float* key   = (const float*)d_in[0];
    const float* value = (const float*)d_in[1];
    const float* query = (const float*)d_in[2];
    const int*   mask  = (const int*)d_in[3];
    const float* Wk = (const float*)d_in[4];
    const float* bk = (const float*)d_in[5];
    const float* Wv = (const float*)d_in[6];
    const float* bv = (const float*)d_in[7];
    const float* Wq = (const float*)d_in[8];
    const float* bq = (const float*)d_in[9];
    const float* Wo = (const float*)d_in[10];
    const float* bo = (const float*)d_in[11];

    float* out      = (float*)d_out;
    float* attn_out = out + (size_t)NB * NL * ND;

    __nv_bfloat16 *k0, *k1, *q0, *q1, *v0, *v1;
    cudaGetSymbolAddress((void**)&k0, g_k0);
    cudaGetSymbolAddress((void**)&k1, g_k1);
    cudaGetSymbolAddress((void**)&q0, g_q0);
    cudaGetSymbolAddress((void**)&q1, g_q1);
    cudaGetSymbolAddress((void**)&v0, g_v0);
    cudaGetSymbolAddress((void**)&v1, g_v1);

    static int attr_set = 0;
    if (!attr_set) {
        cudaFuncSetAttribute(gemm_mma_kernel, cudaFuncAttributeMaxDynamicSharedMemorySize, GSMEM);
        cudaFuncSetAttribute(attn_fused_kernel, cudaFuncAttributeMaxDynamicSharedMemorySize, ASMEM);
        attr_set = 1;
    }

    const int convA_blocks = (NB * NL * ND) / (4 * 256);
    const dim3 convW_grid(ND / 32, ND / 32);
    const dim3 convW_block(32, 8);
    const dim3 gemm_grid(ND / 128, (NB * NL) / 128);

    convA_kernel<<<convA_blocks, 256>>>(key);
    convW_kernel<<<convW_grid, convW_block>>>(Wk);
    gemm_mma_kernel<<<gemm_grid, 256, GSMEM>>>(bk, nullptr, k0, k1, 1.0f, 1);

    convA_kernel<<<convA_blocks, 256>>>(value);
    convW_kernel<<<convW_grid, convW_block>>>(Wv);
    gemm_mma_kernel<<<gemm_grid, 256, GSMEM>>>(bv, nullptr, v0, v1, 1.0f, 1);

    convA_kernel<<<convA_blocks, 256>>>(query);
    convW_kernel<<<convW_grid, convW_block>>>(Wq);
    gemm_mma_kernel<<<gemm_grid, 256, GSMEM>>>(bq, nullptr, q0, q1, 0.125f, 1);

    vtrans_kernel<<<dim3(NL / 64, NB * NH), 256>>>();
    mask2bits_kernel<<<1024, 256>>>(mask);

    const dim3 attn_grid(NL / QT, NH, NB);   // 64 x 16 x 4
    attn_fused_kernel<<<attn_grid, 256, ASMEM>>>(attn_out);
    norm_attn_kernel<<<NB * NL, 256>>>(attn_out);

    convW_kernel<<<convW_grid, convW_block>>>(Wo);
    gemm_mma_kernel<<<gemm_grid, 256, GSMEM>>>(bo, out, nullptr, nullptr, 1.0f, 0);
}

// round 11
// speedup vs baseline: 2.9513x; 1.1482x over previous
#include <cuda_runtime.h>
#include <cuda_bf16.h>

#define NB 4
#define NL 2048
#define ND 1024
#define NH 16
#define DH 64

// ---------------- mma.sync GEMM config (round-9 proven) ----------------
#define BK    32
#define ASTR  40
#define TILE_B (128*ASTR*2)
#define STAGE_B (4*TILE_B)
#define GSMEM  (2*STAGE_B)

// ---------------- fused attention config (QT=64) ----------------
#define QT    64                  // q rows per CTA
#define KCH   128                 // k rows per chunk
#define KST   72                  // K smem row stride (bf16)
#define VST   136                 // V smem row stride (bf16)
#define KTILE (KCH*KST*2)         // 18432 B per split
#define VTILE (64*VST*2)          // 17408 B per split
#define MSK_OFF (2*KTILE + 2*VTILE)   // 71680
#define ASTAGE  (MSK_OFF + QT*16)     // 72704
#define QOFF    (2*ASTAGE)            // 145408
#define QSPL    (QT*KST*2)            // 9216 per split
#define RSPOFF  (QOFF + 2*QSPL)       // 163840
#define INVOFF  (RSPOFF + 8*QT*4)     // 165888
#define ASMEM   (INVOFF + QT*4)       // 166144

// ---- cp.async ----
__device__ __forceinline__ void cpasync16(unsigned dst, const void* src) {
    asm volatile("cp.async.cg.shared.global [%0], [%1], 16;" :: "r"(dst), "l"(src) : "memory");
}
__device__ __forceinline__ void cp_commit() { asm volatile("cp.async.commit_group;" ::: "memory"); }
__device__ __forceinline__ void cp_wait0()  { asm volatile("cp.async.wait_group 0;" ::: "memory"); }
__device__ __forceinline__ void cp_wait1()  { asm volatile("cp.async.wait_group 1;" ::: "memory"); }
__device__ __forceinline__ unsigned smem_u32(const void* p) {
    unsigned a;
    asm("{ .reg .u64 t; cvta.to.shared.u64 t, %1; cvt.u32.u64 %0, t; }" : "=r"(a) : "l"(p));
    return a;
}
// ---- tensor-core (baseline PTX) ----
__device__ __forceinline__ void ldsm4(unsigned& r0, unsigned& r1,
                                      unsigned& r2, unsigned& r3, unsigned addr) {
    asm volatile("ldmatrix.sync.aligned.m8n8.x4.shared.b16 {%0,%1,%2,%3}, [%4];"
                 : "=r"(r0), "=r"(r1), "=r"(r2), "=r"(r3) : "r"(addr));
}
__device__ __forceinline__ void mma16816(float* d, const unsigned* a,
                                         unsigned b0, unsigned b1) {
    asm volatile(
        "mma.sync.aligned.m16n8k16.row.col.f32.bf16.bf16.f32 "
        "{%0,%1,%2,%3}, {%4,%5,%6,%7}, {%8,%9}, {%0,%1,%2,%3};"
        : "+f"(d[0]), "+f"(d[1]), "+f"(d[2]), "+f"(d[3])
        : "r"(a[0]), "r"(a[1]), "r"(a[2]), "r"(a[3]), "r"(b0), "r"(b1));
}
// pack two f32 into bf16x2 (lo = pe, hi = po)
__device__ __forceinline__ unsigned pkbf2(float pe, float po) {
    unsigned d;
    asm("cvt.rn.bf16x2.f32 %0, %1, %2;" : "=r"(d) : "f"(po), "f"(pe));
    return d;
}
// split pair (pe,po) -> hi word + residual lo word
__device__ __forceinline__ void split2(float pe, float po, unsigned& hi, unsigned& lo) {
    hi = pkbf2(pe, po);
    const float re = pe - __uint_as_float(hi << 16);
    const float ro = po - __uint_as_float(hi & 0xFFFF0000u);
    lo = pkbf2(re, ro);
}

// Scratch device globals
__device__ __nv_bfloat16 g_a0[(size_t)NB * NL * ND];
__device__ __nv_bfloat16 g_a1[(size_t)NB * NL * ND];
__device__ __nv_bfloat16 g_w0[(size_t)ND * ND];
__device__ __nv_bfloat16 g_w1[(size_t)ND * ND];
__device__ __nv_bfloat16 g_k0[(size_t)NB * NL * ND];
__device__ __nv_bfloat16 g_k1[(size_t)NB * NL * ND];
__device__ __nv_bfloat16 g_q0[(size_t)NB * NL * ND];
__device__ __nv_bfloat16 g_q1[(size_t)NB * NL * ND];
__device__ __nv_bfloat16 g_v0[(size_t)NB * NL * ND];
__device__ __nv_bfloat16 g_v1[(size_t)NB * NL * ND];
__device__ __nv_bfloat16 g_vt0[(size_t)NB * NL * ND];
__device__ __nv_bfloat16 g_vt1[(size_t)NB * NL * ND];
__device__ unsigned g_mbits[(size_t)NB * NL * (NL / 32)];
__device__ float    g_rsum[(size_t)NB * NL];

// ---------------------------------------------------------------------------
// convA: fp32 [M,1024] -> bf16 hi/lo splits in g_a0/g_a1
// ---------------------------------------------------------------------------
__global__ void convA_kernel(const float* __restrict__ src)
{
    const size_t i = ((size_t)blockIdx.x * 256 + threadIdx.x) * 4;
    const float4 v = *(const float4*)(src + i);
    unsigned h0, l0, h1, l1;
    split2(v.x, v.y, h0, l0);
    split2(v.z, v.w, h1, l1);
    *(unsigned*)(g_a0 + i)     = h0;
    *(unsigned*)(g_a0 + i + 2) = h1;
    *(unsigned*)(g_a1 + i)     = l0;
    *(unsigned*)(g_a1 + i + 2) = l1;
}

// ---------------------------------------------------------------------------
// convW: fp32 W[k][n] -> transposed bf16 splits g_w0/g_w1 [n][k]
// ---------------------------------------------------------------------------
__global__ void convW_kernel(const float* __restrict__ W)
{
    __shared__ float tile[32][33];
    const int k0 = blockIdx.y * 32, n0 = blockIdx.x * 32;
    for (int r = threadIdx.y; r < 32; r += 8)
        tile[r][threadIdx.x] = W[(size_t)(k0 + r) * ND + n0 + threadIdx.x];
    __syncthreads();
    for (int r = threadIdx.y; r < 32; r += 8) {
        const float v = tile[threadIdx.x][r];
        const size_t o = (size_t)(n0 + r) * ND + k0 + threadIdx.x;
        __nv_bfloat16 hi = __float2bfloat16(v);
        g_w0[o] = hi;
        g_w1[o] = __float2bfloat16(v - __bfloat162float(hi));
    }
}

// ---------------------------------------------------------------------------
// vtrans: g_v0/1 [bh][l][d] -> g_vt0/1 [bh][d][l]
// ---------------------------------------------------------------------------
__global__ void vtrans_kernel()
{
    __shared__ __nv_bfloat16 tl[2][64][65];
    const int bh = blockIdx.y;
    const int l0 = blockIdx.x * 64;
    const size_t pin = (size_t)bh * NL * DH;
#pragma unroll
    for (int s = 0; s < 2; s++) {
        const __nv_bfloat16* src = (s ? g_v1 : g_v0) + pin;
#pragma unroll
        for (int i = 0; i < 8; i++) {
            const int u = threadIdx.x + i * 256;
            const int li = u >> 5, dp = u & 31;
            const __nv_bfloat162 v = *(const __nv_bfloat162*)(src + (size_t)(l0 + li) * DH + dp * 2);
            tl[s][li][dp * 2]     = v.x;
            tl[s][li][dp * 2 + 1] = v.y;
        }
    }
    __syncthreads();
    const size_t pout = (size_t)bh * DH * NL;
#pragma unroll
    for (int s = 0; s < 2; s++) {
        __nv_bfloat16* dst = (s ? g_vt1 : g_vt0) + pout;
#pragma unroll
        for (int i = 0; i < 8; i++) {
            const int u = threadIdx.x + i * 256;
            const int d = u >> 5, lp = u & 31;
            __nv_bfloat162 v;
            v.x = tl[s][lp * 2][d];
            v.y = tl[s][lp * 2 + 1][d];
            *(__nv_bfloat162*)(dst + (size_t)d * NL + l0 + lp * 2) = v;
        }
    }
}

// ---------------------------------------------------------------------------
// mask2bits: int32 mask -> bit-packed words (bit k = mask[...,k] != 0)
// ---------------------------------------------------------------------------
__global__ void mask2bits_kernel(const int* __restrict__ mask)
{
    const int gw = (blockIdx.x * 256 + threadIdx.x) >> 5;
    const int lane = threadIdx.x & 31;
    const int nwords = NB * NL * (NL / 32);
    const int step = (gridDim.x * 256) >> 5;
    for (int wv = gw; wv < nwords; wv += step) {
        const int v = mask[(size_t)wv * 32 + lane];
        const unsigned bits = __ballot_sync(0xffffffffu, v != 0);
        if (lane == 0) g_mbits[wv] = bits;
    }
}

// ---------------------------------------------------------------------------
// norm_attn: attn_out rows /= rsum
// ---------------------------------------------------------------------------
__global__ void norm_attn_kernel(float* __restrict__ attn_out)
{
    const int row = blockIdx.x;
    const float inv = 1.f / g_rsum[row];
    float4* p = (float4*)(attn_out + (size_t)row * NL);
    for (int i = threadIdx.x; i < NL / 4; i += 256) {
        float4 v = p[i];
        v.x *= inv; v.y *= inv; v.z *= inv; v.w *= inv;
        p[i] = v;
    }
}

// ---------------------------------------------------------------------------
// mma.sync GEMM (round-9 core). mode 0: fp32 out [m][n] -> dstf.
// mode 1: bf16 split pair scatter [b,h,l,d] -> dst0/dst1.
// ---------------------------------------------------------------------------
__global__ void __launch_bounds__(256, 1) gemm_mma_kernel(
    const float* __restrict__ bias, float* __restrict__ dstf,
    __nv_bfloat16* __restrict__ dst0, __nv_bfloat16* __restrict__ dst1,
    float scale, int mode)
{
    extern __shared__ char smem[];
    const unsigned sb0 = smem_u32(smem);
    const int t = threadIdx.x, lane = t & 31, wid = t >> 5;
    const int wm = (wid & 3) * 32, wn = (wid >> 2) * 64;
    const int n0 = blockIdx.x * 128, m0 = blockIdx.y * 128;

    const __nv_bfloat16* srcs[4] = {
        g_a0 + (size_t)m0 * ND, g_a1 + (size_t)m0 * ND,
        g_w0 + (size_t)n0 * ND, g_w1 + (size_t)n0 * ND };

    float acc[2][8][4];
#pragma unroll
    for (int mt = 0; mt < 2; mt++)
#pragma unroll
        for (int nt = 0; nt < 8; nt++)
#pragma unroll
            for (int r = 0; r < 4; r++) acc[mt][nt][r] = 0.f;

    const int arow = (lane & 7) | (lane & 8);
    const int acol = (lane & 16) >> 1;
    const int brow = (lane & 7) | ((lane & 16) >> 1);
    const int bcol = lane & 8;

#define ISSUE(c) do {                                                          \
    const unsigned sb = sb0 + ((c) & 1) * STAGE_B;                             \
    const int k0 = (c) * BK;                                                   \
    _Pragma("unroll")                                                          \
    for (int s = 0; s < 4; s++) {                                              \
        _Pragma("unroll")                                                      \
        for (int i = 0; i < 2; i++) {                                          \
            const int u = t + i * 256;                                         \
            const int row = u >> 2, seg = u & 3;                               \
            cpasync16(sb + s * TILE_B + (row * ASTR + seg * 8) * 2,            \
                      srcs[s] + (size_t)row * ND + k0 + seg * 8);              \
        }                                                                      \
    }                                                                          \
    cp_commit();                                                               \
} while (0)

    ISSUE(0);
    for (int c = 0; c < ND / BK; c++) {
        if (c + 1 < ND / BK) { ISSUE(c + 1); cp_wait1(); }
        else                 { cp_wait0(); }
        __syncthreads();

        const unsigned sb = sb0 + (c & 1) * STAGE_B;
#pragma unroll
        for (int ks = 0; ks < 2; ks++) {
            const int kc = ks * 16;
            unsigned af[2][2][4];
#pragma unroll
            for (int sp = 0; sp < 2; sp++)
#pragma unroll
                for (int mt = 0; mt < 2; mt++)
                    ldsm4(af[sp][mt][0], af[sp][mt][1], af[sp][mt][2], af[sp][mt][3],
                          sb + sp * TILE_B +
                          (unsigned)(((wm + mt * 16 + arow) * ASTR + kc + acol) * 2));
            unsigned bf[2][4][4];
#pragma unroll
            for (int sp = 0; sp < 2; sp++)
#pragma unroll
                for (int np = 0; np < 4; np++)
                    ldsm4(bf[sp][np][0], bf[sp][np][1], bf[sp][np][2], bf[sp][np][3],
                          sb + (2 + sp) * TILE_B +
                          (unsigned)(((wn + np * 16 + brow) * ASTR + kc + bcol) * 2));
#pragma unroll
            for (int mt = 0; mt < 2; mt++)
#pragma unroll
                for (int nt = 0; nt < 8; nt++) {
                    const int np = nt >> 1, half = (nt & 1) * 2;
                    mma16816(acc[mt][nt], af[0][mt], bf[0][np][half], bf[0][np][half + 1]);
                    mma16816(acc[mt][nt], af[0][mt], bf[1][np][half], bf[1][np][half + 1]);
                    mma16816(acc[mt][nt], af[1][mt], bf[0][np][half], bf[0][np][half + 1]);
                }
        }
        __syncthreads();
    }
#undef ISSUE

#pragma unroll
    for (int mt = 0; mt < 2; mt++)
#pragma unroll
        for (int nt = 0; nt < 8; nt++) {
            const int cc = n0 + wn + nt * 8 + (lane & 3) * 2;
            const float b0 = bias[cc], b1 = bias[cc + 1];
            const float v0 = (acc[mt][nt][0] + b0) * scale;
            const float v1 = (acc[mt][nt][1] + b1) * scale;
            const float v2 = (acc[mt][nt][2] + b0) * scale;
            const float v3 = (acc[mt][nt][3] + b1) * scale;
            const int r0 = m0 + wm + mt * 16 + (lane >> 2);
            if (mode == 0) {
                dstf[(size_t)r0 * ND + cc]           = v0;
                dstf[(size_t)r0 * ND + cc + 1]       = v1;
                dstf[(size_t)(r0 + 8) * ND + cc]     = v2;
                dstf[(size_t)(r0 + 8) * ND + cc + 1] = v3;
            } else {
                const int bb = r0 >> 11, h = cc >> 6, d = cc & 63;
                unsigned hi, lo;
                split2(v0, v1, hi, lo);
                size_t o = ((size_t)(bb * NH + h) * NL + (r0 & (NL - 1))) * DH + d;
                *(unsigned*)(dst0 + o) = hi;
                *(unsigned*)(dst1 + o) = lo;
                split2(v2, v3, hi, lo);
                o = ((size_t)(bb * NH + h) * NL + ((r0 + 8) & (NL - 1))) * DH + d;
                *(unsigned*)(dst0 + o) = hi;
                *(unsigned*)(dst1 + o) = lo;
            }
        }
}

// ---------------------------------------------------------------------------
// Fused flash-style attention (QT=64): per (b, h, 64-q tile), 256 threads.
// Per 128-k chunk: warp w computes S subtile [64 q][16 k] (k-cols w*16..+16)
// via 3-split bf16 mma, masks+exps in registers (per 16-row mt slice),
// repacks to PV a-frags, multiplies by V chunk. Normalization deferred.
// ---------------------------------------------------------------------------
__global__ void __launch_bounds__(256, 1) attn_fused_kernel(
    float* __restrict__ attn_out)
{
    extern __shared__ char smem[];
    const unsigned sb = smem_u32(smem);
    const int t = threadIdx.x, lane = t & 31, w = t >> 5;
    const int q0 = blockIdx.x * QT;
    const int h = blockIdx.y, b = blockIdx.z;
    const int bh = b * NH + h;

    const __nv_bfloat16* kp0 = g_k0 + (size_t)bh * NL * DH;
    const __nv_bfloat16* kp1 = g_k1 + (size_t)bh * NL * DH;
    const __nv_bfloat16* vp0 = g_vt0 + (size_t)bh * DH * NL;
    const __nv_bfloat16* vp1 = g_vt1 + (size_t)bh * DH * NL;
    const __nv_bfloat16* qp0 = g_q0 + (size_t)bh * NL * DH;
    const __nv_bfloat16* qp1 = g_q1 + (size_t)bh * NL * DH;

    const int arow = (lane & 7) | (lane & 8);
    const int acol = (lane & 16) >> 1;
    const int brow = (lane & 7) | ((lane & 16) >> 1);
    const int bcol = lane & 8;

    // Q tile [64 rows x 64 d] x 2 splits -> smem (joins chunk-0 group)
#pragma unroll
    for (int i = 0; i < 4; i++) {
        const int u = t + i * 256;
        const int s = u >> 9, r = (u >> 3) & 63, seg = u & 7;
        cpasync16(sb + QOFF + s * QSPL + r * (KST * 2) + seg * 16,
                  (s ? qp1 : qp0) + (size_t)(q0 + r) * DH + seg * 8);
    }

    const unsigned* mb = g_mbits;

#define AISSUE(c) do {                                                           \
    const unsigned st_ = sb + ((c) & 1) * ASTAGE;                                \
    const int kt_ = (c) * KCH;                                                   \
    _Pragma("unroll")                                                            \
    for (int i = 0; i < 8; i++) {                                                \
        const int u = t + i * 256;                                               \
        const int s = u >> 10, r = (u >> 3) & 127, seg = u & 7;                  \
        cpasync16(st_ + s * KTILE + r * (KST * 2) + seg * 16,                    \
                  (s ? kp1 : kp0) + (size_t)(kt_ + r) * DH + seg * 8);           \
    }                                                                            \
    _Pragma("unroll")                                                            \
    for (int i = 0; i < 8; i++) {                                                \
        const int u = t + i * 256;                                               \
        const int s = u >> 10, r = (u >> 4) & 63, seg = u & 15;                  \
        cpasync16(st_ + 2 * KTILE + s * VTILE + r * (VST * 2) + seg * 16,        \
                  (s ? vp1 : vp0) + (size_t)r * NL + kt_ + seg * 8);             \
    }                                                                            \
    if (t < QT)                                                                  \
        cpasync16(st_ + MSK_OFF + t * 16,                                        \
                  mb + ((size_t)b * NL + q0 + t) * (NL / 32) + (kt_ >> 5));      \
    cp_commit();                                                                 \
} while (0)

    float accv[4][8][4];
#pragma unroll
    for (int mt = 0; mt < 4; mt++)
#pragma unroll
        for (int nt = 0; nt < 8; nt++)
#pragma unroll
            for (int r = 0; r < 4; r++) accv[mt][nt][r] = 0.f;
    float rs[4][2];
#pragma unroll
    for (int mt = 0; mt < 4; mt++) { rs[mt][0] = 0.f; rs[mt][1] = 0.f; }

    AISSUE(0);
    for (int c = 0; c < NL / KCH; c++) {
        if (c + 1 < NL / KCH) { AISSUE(c + 1); cp_wait1(); }
        else                  { cp_wait0(); }
        __syncthreads();
        const unsigned st = sb + (c & 1) * ASTAGE;
        const int kt = c * KCH;

        // ---- QK: S subtile [64][16] ----
        float accs[4][2][4];
#pragma unroll
        for (int mt = 0; mt < 4; mt++)
#pragma unroll
            for (int nt = 0; nt < 2; nt++)
#pragma unroll
                for (int r = 0; r < 4; r++) accs[mt][nt][r] = 0.f;

#pragma unroll
        for (int ks = 0; ks < 4; ks++) {
            const int kc = ks * 16;
            unsigned bk[2][4];
#pragma unroll
            for (int s = 0; s < 2; s++)
                ldsm4(bk[s][0], bk[s][1], bk[s][2], bk[s][3],
                      st + s * KTILE +
                      (unsigned)((w * 16 + brow) * (KST * 2) + (kc + bcol) * 2));
#pragma unroll
            for (int mt = 0; mt < 4; mt++) {
                unsigned aq0[4], aq1[4];
                ldsm4(aq0[0], aq0[1], aq0[2], aq0[3],
                      sb + QOFF +
                      (unsigned)((mt * 16 + arow) * (KST * 2) + (kc + acol) * 2));
                ldsm4(aq1[0], aq1[1], aq1[2], aq1[3],
                      sb + QOFF + QSPL +
                      (unsigned)((mt * 16 + arow) * (KST * 2) + (kc + acol) * 2));
#pragma unroll
                for (int nt = 0; nt < 2; nt++) {
                    mma16816(accs[mt][nt], aq0, bk[0][nt * 2], bk[0][nt * 2 + 1]);
                    mma16816(accs[mt][nt], aq0, bk[1][nt * 2], bk[1][nt * 2 + 1]);
                    mma16816(accs[mt][nt], aq1, bk[0][nt * 2], bk[0][nt * 2 + 1]);
                }
            }
        }

        // ---- V fragments (hoisted once per chunk) ----
        unsigned bv[2][4][4];
#pragma unroll
        for (int s = 0; s < 2; s++)
#pragma unroll
            for (int np = 0; np < 4; np++)
                ldsm4(bv[s][np][0], bv[s][np][1], bv[s][np][2], bv[s][np][3],
                      st + 2 * KTILE + s * VTILE +
                      (unsigned)((np * 16 + brow) * (VST * 2) + (w * 16 + bcol) * 2));

        // ---- per-mt: mask + exp + repack + PV ----
#pragma unroll
        for (int mt = 0; mt < 4; mt++) {
            const int r = lane >> 2;
            const unsigned mw0 = *(const unsigned*)(smem + (c & 1) * ASTAGE + MSK_OFF +
                                                    (mt * 16 + r) * 16 + (w >> 1) * 4);
            const unsigned mw1 = *(const unsigned*)(smem + (c & 1) * ASTAGE + MSK_OFF +
                                                    (mt * 16 + r + 8) * 16 + (w >> 1) * 4);
            const int bbase = (w & 1) * 16;
            float p[2][4];
#pragma unroll
            for (int nt = 0; nt < 2; nt++) {
                const int xb = bbase + nt * 8 + 2 * (lane & 3);
                p[nt][0] = ((mw0 >> xb) & 1)       ? 0.f : __expf(accs[mt][nt][0]);
                p[nt][1] = ((mw0 >> (xb + 1)) & 1) ? 0.f : __expf(accs[mt][nt][1]);
                p[nt][2] = ((mw1 >> xb) & 1)       ? 0.f : __expf(accs[mt][nt][2]);
                p[nt][3] = ((mw1 >> (xb + 1)) & 1) ? 0.f : __expf(accs[mt][nt][3]);
            }
            rs[mt][0] += p[0][0] + p[0][1] + p[1][0] + p[1][1];
            rs[mt][1] += p[0][2] + p[0][3] + p[1][2] + p[1][3];
            if (h == 0) {
                const size_t base = ((size_t)b * NL + q0 + mt * 16 + r) * NL + kt + w * 16;
                const int cc = 2 * (lane & 3);
                *(float2*)(attn_out + base + cc)               = make_float2(p[0][0], p[0][1]);
                *(float2*)(attn_out + base + 8 + cc)           = make_float2(p[1][0], p[1][1]);
                *(float2*)(attn_out + base + (size_t)8 * NL + cc)     = make_float2(p[0][2], p[0][3]);
                *(float2*)(attn_out + base + (size_t)8 * NL + 8 + cc) = make_float2(p[1][2], p[1][3]);
            }
            unsigned ap0[4], ap1[4];
            split2(p[0][0], p[0][1], ap0[0], ap1[0]);
            split2(p[0][2], p[0][3], ap0[1], ap1[1]);
            split2(p[1][0], p[1][1], ap0[2], ap1[2]);
            split2(p[1][2], p[1][3], ap0[3], ap1[3]);
#pragma unroll
            for (int nt = 0; nt < 8; nt++) {
                const int np = nt >> 1, hf = (nt & 1) * 2;
                mma16816(accv[mt][nt], ap0, bv[0][np][hf], bv[0][np][hf + 1]);
                mma16816(accv[mt][nt], ap0, bv[1][np][hf], bv[1][np][hf + 1]);
                mma16816(accv[mt][nt], ap1, bv[0][np][hf], bv[0][np][hf + 1]);
            }
        }
        __syncthreads();
    }
#undef AISSUE

    // ---- row-sum reduce ----
#pragma unroll
    for (int mt = 0; mt < 4; mt++)
#pragma unroll
        for (int hf = 0; hf < 2; hf++) {
            float v = rs[mt][hf];
            v += __shfl_xor_sync(0xffffffffu, v, 1);
            v += __shfl_xor_sync(0xffffffffu, v, 2);
            if ((lane & 3) == 0)
                *(float*)(smem + RSPOFF + (w * QT + mt * 16 + hf * 8 + (lane >> 2)) * 4) = v;
        }

    // ---- PV cross-warp reduce via swizzled smem (reuses stage area) ----
    float* red = (float*)smem;
#pragma unroll
    for (int mt = 0; mt < 4; mt++)
#pragma unroll
        for (int nt = 0; nt < 8; nt++) {
            const int r0 = mt * 16 + (lane >> 2);
            const int cc = nt * 8 + 2 * (lane & 3);
            *(float2*)&red[(w * QT + r0) * 64 + (cc ^ ((r0 & 3) << 3))] =
                make_float2(accv[mt][nt][0], accv[mt][nt][1]);
            const int r1 = r0 + 8;
            *(float2*)&red[(w * QT + r1) * 64 + (cc ^ ((r1 & 3) << 3))] =
                make_float2(accv[mt][nt][2], accv[mt][nt][3]);
        }
    __syncthreads();

    float* invs = (float*)(smem + INVOFF);
    if (t < QT) {
        float s = 0.f;
#pragma unroll
        for (int ww = 0; ww < 8; ww++)
            s += *(float*)(smem + RSPOFF + (ww * QT + t) * 4);
        invs[t] = 1.f / s;
        if (h == 0) g_rsum[(size_t)b * NL + q0 + t] = s;
    }
    __syncthreads();

    for (int idx = t; idx < QT * DH / 2; idx += 256) {
        const int q = idx >> 5, dp = idx & 31;
        const int d0 = dp * 2, sw = (q & 3) << 3;
        float s0 = 0.f, s1 = 0.f;
#pragma unroll
        for (int ww = 0; ww < 8; ww++) {
            const float* rr = &red[(ww * QT + q) * 64];
            s0 += rr[d0 ^ sw];
            s1 += rr[(d0 + 1) ^ sw];
        }
        const float inv = invs[q];
        s0 *= inv; s1 *= inv;
        unsigned hi, lo;
        split2(s0, s1, hi, lo);
        const size_t off = ((size_t)(b * NL + q0 + q)) * ND + h * DH + d0;
        *(unsigned*)(g_a0 + off) = hi;
        *(unsigned*)(g_a1 + off) = lo;
    }
}

// ---------------------------------------------------------------------------
extern "C" void kernel_launch(void* const* d_in, const int* in_sizes, int n_in,
                              void* d_out, int out_size)
{
    const float* key   = (const float*)d_in[0];
    const float* value = (const float*)d_in[1];
    const float* query = (const float*)d_in[2];
    const int*   mask  = (const int*)d_in[3];
    const float* Wk = (const float*)d_in[4];
    const float* bk = (const float*)d_in[5];
    const float* Wv = (const float*)d_in[6];
    const float* bv = (const float*)d_in[7];
    const float* Wq = (const float*)d_in[8];
    const float* bq = (const float*)d_in[9];
    const float* Wo = (const float*)d_in[10];
    const float* bo = (const float*)d_in[11];

    float* out      = (float*)d_out;
    float* attn_out = out + (size_t)NB * NL * ND;

    __nv_bfloat16 *k0, *k1, *q0, *q1, *v0, *v1;
    cudaGetSymbolAddress((void**)&k0, g_k0);
    cudaGetSymbolAddress((void**)&k1, g_k1);
    cudaGetSymbolAddress((void**)&q0, g_q0);
    cudaGetSymbolAddress((void**)&q1, g_q1);
    cudaGetSymbolAddress((void**)&v0, g_v0);
    cudaGetSymbolAddress((void**)&v1, g_v1);

    static int attr_set = 0;
    if (!attr_set) {
        cudaFuncSetAttribute(gemm_mma_kernel, cudaFuncAttributeMaxDynamicSharedMemorySize, GSMEM);
        cudaFuncSetAttribute(attn_fused_kernel, cudaFuncAttributeMaxDynamicSharedMemorySize, ASMEM);
        attr_set = 1;
    }

    const int convA_blocks = (NB * NL * ND) / (4 * 256);
    const dim3 convW_grid(ND / 32, ND / 32);
    const dim3 convW_block(32, 8);
    const dim3 gemm_grid(ND / 128, (NB * NL) / 128);

    convA_kernel<<<convA_blocks, 256>>>(key);
    convW_kernel<<<convW_grid, convW_block>>>(Wk);
    gemm_mma_kernel<<<gemm_grid, 256, GSMEM>>>(bk, nullptr, k0, k1, 1.0f, 1);

    convA_kernel<<<convA_blocks, 256>>>(value);
    convW_kernel<<<convW_grid, convW_block>>>(Wv);
    gemm_mma_kernel<<<gemm_grid, 256, GSMEM>>>(bv, nullptr, v0, v1, 1.0f, 1);

    convA_kernel<<<convA_blocks, 256>>>(query);
    convW_kernel<<<convW_grid, convW_block>>>(Wq);
    gemm_mma_kernel<<<gemm_grid, 256, GSMEM>>>(bq, nullptr, q0, q1, 0.125f, 1);

    vtrans_kernel<<<dim3(NL / 64, NB * NH), 256>>>();
    mask2bits_kernel<<<1024, 256>>>(mask);

    const dim3 attn_grid(NL / QT, NH, NB);   // 32 x 16 x 4
    attn_fused_kernel<<<attn_grid, 256, ASMEM>>>(attn_out);
    norm_attn_kernel<<<NB * NL, 256>>>(attn_out);

    convW_kernel<<<convW_grid, convW_block>>>(Wo);
    gemm_mma_kernel<<<gemm_grid, 256, GSMEM>>>(bo, out, nullptr, nullptr, 1.0f, 0);
}

// round 13
// speedup vs baseline: 3.9282x; 1.3310x over previous
#include <cuda_runtime.h>
#include <cuda_bf16.h>
#include <cuda_fp16.h>

#define NB 4
#define NL 2048
#define ND 1024
#define NH 16
#define DH 64

// ---------------- mma.sync GEMM config (round-9 proven) ----------------
#define BK    32
#define ASTR  40
#define TILE_B (128*ASTR*2)
#define STAGE_B (4*TILE_B)
#define GSMEM  (2*STAGE_B)
#define APLANE ((size_t)NB*NL*ND)
#define WPLANE ((size_t)ND*ND)

// ---------------- fused fp16 attention config (QT=64) ----------------
#define QT    64
#define KCH   128
#define KST   72                      // K smem row stride (fp16)
#define VST   136                     // V smem row stride (fp16)
#define KTILE (KCH*KST*2)             // 18432 B (single plane)
#define VTILE (64*VST*2)              // 17408 B (single plane)
#define VOFF  KTILE
#define MSK_OFF (KTILE + VTILE)       // 35840
#define ASTAGE  (MSK_OFF + QT*16)     // 36864
#define QOFF    (2*ASTAGE)            // 73728
#define QSPL    (QT*KST*2)            // 9216 (single plane)
// epilogue red buffer: 8 warps x QT rows x 64 floats = 131072 B (from smem 0)
#define RED_B   (8*QT*64*4)           // 131072
#define RSPOFF  RED_B                 // 131072 (above red!)
#define INVOFF  (RSPOFF + 8*QT*4)     // 133120
#define ASMEM   (INVOFF + QT*4)       // 133376

// ---- cp.async ----
__device__ __forceinline__ void cpasync16(unsigned dst, const void* src) {
    asm volatile("cp.async.cg.shared.global [%0], [%1], 16;" :: "r"(dst), "l"(src) : "memory");
}
__device__ __forceinline__ void cp_commit() { asm volatile("cp.async.commit_group;" ::: "memory"); }
__device__ __forceinline__ void cp_wait0()  { asm volatile("cp.async.wait_group 0;" ::: "memory"); }
__device__ __forceinline__ void cp_wait1()  { asm volatile("cp.async.wait_group 1;" ::: "memory"); }
__device__ __forceinline__ unsigned smem_u32(const void* p) {
    unsigned a;
    asm("{ .reg .u64 t; cvta.to.shared.u64 t, %1; cvt.u32.u64 %0, t; }" : "=r"(a) : "l"(p));
    return a;
}
// ---- tensor-core (baseline PTX) ----
__device__ __forceinline__ void ldsm4(unsigned& r0, unsigned& r1,
                                      unsigned& r2, unsigned& r3, unsigned addr) {
    asm volatile("ldmatrix.sync.aligned.m8n8.x4.shared.b16 {%0,%1,%2,%3}, [%4];"
                 : "=r"(r0), "=r"(r1), "=r"(r2), "=r"(r3) : "r"(addr));
}
__device__ __forceinline__ void mma16816(float* d, const unsigned* a,
                                         unsigned b0, unsigned b1) {
    asm volatile(
        "mma.sync.aligned.m16n8k16.row.col.f32.bf16.bf16.f32 "
        "{%0,%1,%2,%3}, {%4,%5,%6,%7}, {%8,%9}, {%0,%1,%2,%3};"
        : "+f"(d[0]), "+f"(d[1]), "+f"(d[2]), "+f"(d[3])
        : "r"(a[0]), "r"(a[1]), "r"(a[2]), "r"(a[3]), "r"(b0), "r"(b1));
}
__device__ __forceinline__ void mma16816h(float* d, const unsigned* a,
                                          unsigned b0, unsigned b1) {
    asm volatile(
        "mma.sync.aligned.m16n8k16.row.col.f32.f16.f16.f32 "
        "{%0,%1,%2,%3}, {%4,%5,%6,%7}, {%8,%9}, {%0,%1,%2,%3};"
        : "+f"(d[0]), "+f"(d[1]), "+f"(d[2]), "+f"(d[3])
        : "r"(a[0]), "r"(a[1]), "r"(a[2]), "r"(a[3]), "r"(b0), "r"(b1));
}
// pack two f32 into bf16x2 / f16x2 (lo = pe, hi = po)
__device__ __forceinline__ unsigned pkbf2(float pe, float po) {
    unsigned d;
    asm("cvt.rn.bf16x2.f32 %0, %1, %2;" : "=r"(d) : "f"(po), "f"(pe));
    return d;
}
__device__ __forceinline__ unsigned pkhf2(float pe, float po) {
    unsigned d;
    asm("cvt.rn.f16x2.f32 %0, %1, %2;" : "=r"(d) : "f"(po), "f"(pe));
    return d;
}
// split pair (pe,po) -> bf16 hi word + residual lo word
__device__ __forceinline__ void split2(float pe, float po, unsigned& hi, unsigned& lo) {
    hi = pkbf2(pe, po);
    const float re = pe - __uint_as_float(hi << 16);
    const float ro = po - __uint_as_float(hi & 0xFFFF0000u);
    lo = pkbf2(re, ro);
}

// Scratch device globals
__device__ __nv_bfloat16 g_a0[3 * APLANE];
__device__ __nv_bfloat16 g_a1[3 * APLANE];
__device__ __nv_bfloat16 g_w0[3 * WPLANE];
__device__ __nv_bfloat16 g_w1[3 * WPLANE];
__device__ __half g_kh[APLANE];    // K  [bh][l][d] fp16
__device__ __half g_qh[APLANE];    // Q  [bh][l][d] fp16 (pre-scaled)
__device__ __half g_vh[APLANE];    // V  [bh][l][d] fp16
__device__ __half g_vth[APLANE];   // V^T [bh][d][l] fp16
__device__ unsigned g_mbits[(size_t)NB * NL * (NL / 32)];
__device__ float    g_rsum[(size_t)NB * NL];

// ---------------------------------------------------------------------------
// convA (batched y=3): fp32 [M,1024] -> bf16 hi/lo splits, plane blockIdx.y
// ---------------------------------------------------------------------------
__global__ void convA_kernel(const float* __restrict__ s0,
                             const float* __restrict__ s1,
                             const float* __restrict__ s2)
{
    const int z = blockIdx.y;
    const float* src = (z == 0) ? s0 : (z == 1) ? s1 : s2;
    const size_t i = ((size_t)blockIdx.x * 256 + threadIdx.x) * 4;
    const float4 v = *(const float4*)(src + i);
    unsigned h0, l0, h1, l1;
    split2(v.x, v.y, h0, l0);
    split2(v.z, v.w, h1, l1);
    __nv_bfloat16* a0 = g_a0 + (size_t)z * APLANE;
    __nv_bfloat16* a1 = g_a1 + (size_t)z * APLANE;
    *(unsigned*)(a0 + i)     = h0;
    *(unsigned*)(a0 + i + 2) = h1;
    *(unsigned*)(a1 + i)     = l0;
    *(unsigned*)(a1 + i + 2) = l1;
}

// ---------------------------------------------------------------------------
// convW (batched via grid.z): fp32 W[k][n] -> transposed bf16 splits [n][k]
// ---------------------------------------------------------------------------
__global__ void convW_kernel(const float* __restrict__ W0,
                             const float* __restrict__ W1,
                             const float* __restrict__ W2)
{
    const int z = blockIdx.z;
    const float* W = (z == 0) ? W0 : (z == 1) ? W1 : W2;
    __shared__ float tile[32][33];
    const int k0 = blockIdx.y * 32, n0 = blockIdx.x * 32;
    for (int r = threadIdx.y; r < 32; r += 8)
        tile[r][threadIdx.x] = W[(size_t)(k0 + r) * ND + n0 + threadIdx.x];
    __syncthreads();
    __nv_bfloat16* w0 = g_w0 + (size_t)z * WPLANE;
    __nv_bfloat16* w1 = g_w1 + (size_t)z * WPLANE;
    for (int r = threadIdx.y; r < 32; r += 8) {
        const float v = tile[threadIdx.x][r];
        const size_t o = (size_t)(n0 + r) * ND + k0 + threadIdx.x;
        __nv_bfloat16 hi = __float2bfloat16(v);
        w0[o] = hi;
        w1[o] = __float2bfloat16(v - __bfloat162float(hi));
    }
}

// ---------------------------------------------------------------------------
// vtrans: g_vh [bh][l][d] -> g_vth [bh][d][l] (single fp16 plane)
// ---------------------------------------------------------------------------
__global__ void vtrans_kernel()
{
    __shared__ __half tl[64][65];
    const int bh = blockIdx.y;
    const int l0 = blockIdx.x * 64;
    const size_t pin = (size_t)bh * NL * DH;
#pragma unroll
    for (int i = 0; i < 8; i++) {
        const int u = threadIdx.x + i * 256;
        const int li = u >> 5, dp = u & 31;
        const __half2 v = *(const __half2*)(g_vh + pin + (size_t)(l0 + li) * DH + dp * 2);
        tl[li][dp * 2]     = __low2half(v);
        tl[li][dp * 2 + 1] = __high2half(v);
    }
    __syncthreads();
    const size_t pout = (size_t)bh * DH * NL;
#pragma unroll
    for (int i = 0; i < 8; i++) {
        const int u = threadIdx.x + i * 256;
        const int d = u >> 5, lp = u & 31;
        __half2 v = __halves2half2(tl[lp * 2][d], tl[lp * 2 + 1][d]);
        *(__half2*)(g_vth + pout + (size_t)d * NL + l0 + lp * 2) = v;
    }
}

// ---------------------------------------------------------------------------
// mask2bits: int32 mask -> bit-packed words
// ---------------------------------------------------------------------------
__global__ void mask2bits_kernel(const int* __restrict__ mask)
{
    const int gw = (blockIdx.x * 256 + threadIdx.x) >> 5;
    const int lane = threadIdx.x & 31;
    const int nwords = NB * NL * (NL / 32);
    const int step = (gridDim.x * 256) >> 5;
    for (int wv = gw; wv < nwords; wv += step) {
        const int v = mask[(size_t)wv * 32 + lane];
        const unsigned bits = __ballot_sync(0xffffffffu, v != 0);
        if (lane == 0) g_mbits[wv] = bits;
    }
}

// ---------------------------------------------------------------------------
// norm_attn: attn_out rows /= rsum
// ---------------------------------------------------------------------------
__global__ void norm_attn_kernel(float* __restrict__ attn_out)
{
    const int row = blockIdx.x;
    const float inv = 1.f / g_rsum[row];
    float4* p = (float4*)(attn_out + (size_t)row * NL);
    for (int i = threadIdx.x; i < NL / 4; i += 256) {
        float4 v = p[i];
        v.x *= inv; v.y *= inv; v.z *= inv; v.w *= inv;
        p[i] = v;
    }
}

// ---------------------------------------------------------------------------
// Shared GEMM mainloop body (3x bf16-split). Produces acc[2][8][4].
// ---------------------------------------------------------------------------
#define GEMM_MAINLOOP(Aptr0, Aptr1, Wptr0, Wptr1)                                 \
    const __nv_bfloat16* srcs[4] = { Aptr0, Aptr1, Wptr0, Wptr1 };                \
    float acc[2][8][4];                                                           \
    _Pragma("unroll")                                                             \
    for (int mt = 0; mt < 2; mt++)                                                \
        _Pragma("unroll")                                                         \
        for (int nt = 0; nt < 8; nt++)                                            \
            _Pragma("unroll")                                                     \
            for (int r = 0; r < 4; r++) acc[mt][nt][r] = 0.f;                     \
    const int arow = (lane & 7) | (lane & 8);                                     \
    const int acol = (lane & 16) >> 1;                                            \
    const int brow = (lane & 7) | ((lane & 16) >> 1);                             \
    const int bcol = lane & 8;                                                    \
    {                                                                             \
        const unsigned sb = sb0;                                                  \
        _Pragma("unroll")                                                         \
        for (int s = 0; s < 4; s++)                                               \
            _Pragma("unroll")                                                     \
            for (int i = 0; i < 2; i++) {                                         \
                const int u = t + i * 256;                                        \
                const int row = u >> 2, seg = u & 3;                              \
                cpasync16(sb + s * TILE_B + (row * ASTR + seg * 8) * 2,           \
                          srcs[s] + (size_t)row * ND + seg * 8);                  \
            }                                                                     \
        cp_commit();                                                              \
    }                                                                             \
    for (int c = 0; c < ND / BK; c++) {                                           \
        if (c + 1 < ND / BK) {                                                    \
            const unsigned sb = sb0 + ((c + 1) & 1) * STAGE_B;                    \
            const int k0 = (c + 1) * BK;                                          \
            _Pragma("unroll")                                                     \
            for (int s = 0; s < 4; s++)                                           \
                _Pragma("unroll")                                                 \
                for (int i = 0; i < 2; i++) {                                     \
                    const int u = t + i * 256;                                    \
                    const int row = u >> 2, seg = u & 3;                          \
                    cpasync16(sb + s * TILE_B + (row * ASTR + seg * 8) * 2,       \
                              srcs[s] + (size_t)row * ND + k0 + seg * 8);         \
                }                                                                 \
            cp_commit(); cp_wait1();                                              \
        } else { cp_wait0(); }                                                    \
        __syncthreads();                                                          \
        const unsigned sb = sb0 + (c & 1) * STAGE_B;                              \
        _Pragma("unroll")                                                         \
        for (int ks = 0; ks < 2; ks++) {                                          \
            const int kc = ks * 16;                                               \
            unsigned af[2][2][4];                                                 \
            _Pragma("unroll")                                                     \
            for (int sp = 0; sp < 2; sp++)                                        \
                _Pragma("unroll")                                                 \
                for (int mt = 0; mt < 2; mt++)                                    \
                    ldsm4(af[sp][mt][0], af[sp][mt][1], af[sp][mt][2], af[sp][mt][3], \
                          sb + sp * TILE_B +                                      \
                          (unsigned)(((wm + mt * 16 + arow) * ASTR + kc + acol) * 2)); \
            unsigned bf[2][4][4];                                                 \
            _Pragma("unroll")                                                     \
            for (int sp = 0; sp < 2; sp++)                                        \
                _Pragma("unroll")                                                 \
                for (int np = 0; np < 4; np++)                                    \
                    ldsm4(bf[sp][np][0], bf[sp][np][1], bf[sp][np][2], bf[sp][np][3], \
                          sb + (2 + sp) * TILE_B +                                \
                          (unsigned)(((wn + np * 16 + brow) * ASTR + kc + bcol) * 2)); \
            _Pragma("unroll")                                                     \
            for (int mt = 0; mt < 2; mt++)                                        \
                _Pragma("unroll")                                                 \
                for (int nt = 0; nt < 8; nt++) {                                  \
                    const int np = nt >> 1, half = (nt & 1) * 2;                  \
                    mma16816(acc[mt][nt], af[0][mt], bf[0][np][half], bf[0][np][half + 1]); \
                    mma16816(acc[mt][nt], af[0][mt], bf[1][np][half], bf[1][np][half + 1]); \
                    mma16816(acc[mt][nt], af[1][mt], bf[0][np][half], bf[0][np][half + 1]); \
                }                                                                 \
        }                                                                         \
        __syncthreads();                                                          \
    }

// ---------------------------------------------------------------------------
// Batched projection GEMM (grid.z = 3): (A_z @ W_z + bias_z)*scale_z -> fp16
// scatter [b,h,l,d] into g_kh / g_vh / g_qh.
// ---------------------------------------------------------------------------
__global__ void __launch_bounds__(256, 1) gemm_proj_kernel(
    const float* __restrict__ b0p, const float* __restrict__ b1p,
    const float* __restrict__ b2p)
{
    extern __shared__ char smem[];
    const unsigned sb0 = smem_u32(smem);
    const int t = threadIdx.x, lane = t & 31, wid = t >> 5;
    const int wm = (wid & 3) * 32, wn = (wid >> 2) * 64;
    const int n0 = blockIdx.x * 128, m0 = blockIdx.y * 128;
    const int z = blockIdx.z;
    const float* bias = (z == 0) ? b0p : (z == 1) ? b1p : b2p;
    __half* dsth = (z == 0) ? g_kh : (z == 1) ? g_vh : g_qh;
    const float scale = (z == 2) ? 0.125f : 1.0f;

    GEMM_MAINLOOP(g_a0 + z * APLANE + (size_t)m0 * ND,
                  g_a1 + z * APLANE + (size_t)m0 * ND,
                  g_w0 + z * WPLANE + (size_t)n0 * ND,
                  g_w1 + z * WPLANE + (size_t)n0 * ND)

#pragma unroll
    for (int mt = 0; mt < 2; mt++)
#pragma unroll
        for (int nt = 0; nt < 8; nt++) {
            const int cc = n0 + wn + nt * 8 + (lane & 3) * 2;
            const float b0 = bias[cc], b1 = bias[cc + 1];
            const float v0 = (acc[mt][nt][0] + b0) * scale;
            const float v1 = (acc[mt][nt][1] + b1) * scale;
            const float v2 = (acc[mt][nt][2] + b0) * scale;
            const float v3 = (acc[mt][nt][3] + b1) * scale;
            const int r0 = m0 + wm + mt * 16 + (lane >> 2);
            const int bb = r0 >> 11, h = cc >> 6, d = cc & 63;
            size_t o = ((size_t)(bb * NH + h) * NL + (r0 & (NL - 1))) * DH + d;
            *(unsigned*)(dsth + o) = pkhf2(v0, v1);
            o = ((size_t)(bb * NH + h) * NL + ((r0 + 8) & (NL - 1))) * DH + d;
            *(unsigned*)(dsth + o) = pkhf2(v2, v3);
        }
}

// ---------------------------------------------------------------------------
// Output GEMM: (ctx @ Wo + bo) -> fp32 [m][n]
// ---------------------------------------------------------------------------
__global__ void __launch_bounds__(256, 1) gemm_out_kernel(
    const float* __restrict__ bias, float* __restrict__ dstf)
{
    extern __shared__ char smem[];
    const unsigned sb0 = smem_u32(smem);
    const int t = threadIdx.x, lane = t & 31, wid = t >> 5;
    const int wm = (wid & 3) * 32, wn = (wid >> 2) * 64;
    const int n0 = blockIdx.x * 128, m0 = blockIdx.y * 128;

    GEMM_MAINLOOP(g_a0 + (size_t)m0 * ND, g_a1 + (size_t)m0 * ND,
                  g_w0 + (size_t)n0 * ND, g_w1 + (size_t)n0 * ND)

#pragma unroll
    for (int mt = 0; mt < 2; mt++)
#pragma unroll
        for (int nt = 0; nt < 8; nt++) {
            const int cc = n0 + wn + nt * 8 + (lane & 3) * 2;
            const float b0 = bias[cc], b1 = bias[cc + 1];
            const int r0 = m0 + wm + mt * 16 + (lane >> 2);
            dstf[(size_t)r0 * ND + cc]           = acc[mt][nt][0] + b0;
            dstf[(size_t)r0 * ND + cc + 1]       = acc[mt][nt][1] + b1;
            dstf[(size_t)(r0 + 8) * ND + cc]     = acc[mt][nt][2] + b0;
            dstf[(size_t)(r0 + 8) * ND + cc + 1] = acc[mt][nt][3] + b1;
        }
}

// ---------------------------------------------------------------------------
// Fused fp16 flash attention: per (b, h, 64-q tile), 256 threads, 8 warps.
// Single-plane fp16 Q/K/V: QK = 1 mma, PV = 1 mma per 16x8 tile.
// ---------------------------------------------------------------------------
__global__ void __launch_bounds__(256, 1) attn_fused_kernel(
    float* __restrict__ attn_out)
{
    extern __shared__ char smem[];
    const unsigned sb = smem_u32(smem);
    const int t = threadIdx.x, lane = t & 31, w = t >> 5;
    const int q0 = blockIdx.x * QT;
    const int h = blockIdx.y, b = blockIdx.z;
    const int bh = b * NH + h;

    const __half* kph = g_kh + (size_t)bh * NL * DH;
    const __half* vph = g_vth + (size_t)bh * DH * NL;
    const __half* qph = g_qh + (size_t)bh * NL * DH;

    const int arow = (lane & 7) | (lane & 8);
    const int acol = (lane & 16) >> 1;
    const int brow = (lane & 7) | ((lane & 16) >> 1);
    const int bcol = lane & 8;

    // Q tile [64 x 64] fp16 -> smem (joins chunk-0 group)
#pragma unroll
    for (int i = 0; i < 2; i++) {
        const int u = t + i * 256;
        const int r = u >> 3, seg = u & 7;
        cpasync16(sb + QOFF + r * (KST * 2) + seg * 16,
                  qph + (size_t)(q0 + r) * DH + seg * 8);
    }

    const unsigned* mb = g_mbits;

#define AISSUE(c) do {                                                           \
    const unsigned st_ = sb + ((c) & 1) * ASTAGE;                                \
    const int kt_ = (c) * KCH;                                                   \
    _Pragma("unroll")                                                            \
    for (int i = 0; i < 4; i++) {                                                \
        const int u = t + i * 256;                                               \
        const int r = u >> 3, seg = u & 7;                                       \
        cpasync16(st_ + r * (KST * 2) + seg * 16,                                \
                  kph + (size_t)(kt_ + r) * DH + seg * 8);                       \
    }                                                                            \
    _Pragma("unroll")                                                            \
    for (int i = 0; i < 4; i++) {                                                \
        const int u = t + i * 256;                                               \
        const int r = u >> 4, seg = u & 15;                                      \
        cpasync16(st_ + VOFF + r * (VST * 2) + seg * 16,                         \
                  vph + (size_t)r * NL + kt_ + seg * 8);                         \
    }                                                                            \
    if (t < QT)                                                                  \
        cpasync16(st_ + MSK_OFF + t * 16,                                        \
                  mb + ((size_t)b * NL + q0 + t) * (NL / 32) + (kt_ >> 5));      \
    cp_commit();                                                                 \
} while (0)

    float accv[4][8][4];
#pragma unroll
    for (int mt = 0; mt < 4; mt++)
#pragma unroll
        for (int nt = 0; nt < 8; nt++)
#pragma unroll
            for (int r = 0; r < 4; r++) accv[mt][nt][r] = 0.f;
    float rs[4][2];
#pragma unroll
    for (int mt = 0; mt < 4; mt++) { rs[mt][0] = 0.f; rs[mt][1] = 0.f; }

    AISSUE(0);
    for (int c = 0; c < NL / KCH; c++) {
        if (c + 1 < NL / KCH) { AISSUE(c + 1); cp_wait1(); }
        else                  { cp_wait0(); }
        __syncthreads();
        const unsigned st = sb + (c & 1) * ASTAGE;
        const int kt = c * KCH;

        // ---- QK: S subtile [64][16], single fp16 mma ----
        float accs[4][2][4];
#pragma unroll
        for (int mt = 0; mt < 4; mt++)
#pragma unroll
            for (int nt = 0; nt < 2; nt++)
#pragma unroll
                for (int r = 0; r < 4; r++) accs[mt][nt][r] = 0.f;

#pragma unroll
        for (int ks = 0; ks < 4; ks++) {
            const int kc = ks * 16;
            unsigned bk[4];
            ldsm4(bk[0], bk[1], bk[2], bk[3],
                  st + (unsigned)((w * 16 + brow) * (KST * 2) + (kc + bcol) * 2));
#pragma unroll
            for (int mt = 0; mt < 4; mt++) {
                unsigned aq[4];
                ldsm4(aq[0], aq[1], aq[2], aq[3],
                      sb + QOFF +
                      (unsigned)((mt * 16 + arow) * (KST * 2) + (kc + acol) * 2));
                mma16816h(accs[mt][0], aq, bk[0], bk[1]);
                mma16816h(accs[mt][1], aq, bk[2], bk[3]);
            }
        }

        // ---- V fragments ----
        unsigned bv[4][4];
#pragma unroll
        for (int np = 0; np < 4; np++)
            ldsm4(bv[np][0], bv[np][1], bv[np][2], bv[np][3],
                  st + VOFF +
                  (unsigned)((np * 16 + brow) * (VST * 2) + (w * 16 + bcol) * 2));

        // ---- per-mt: mask + exp + fp16 pack + PV ----
#pragma unroll
        for (int mt = 0; mt < 4; mt++) {
            const int r = lane >> 2;
            const unsigned mw0 = *(const unsigned*)(smem + (c & 1) * ASTAGE + MSK_OFF +
                                                    (mt * 16 + r) * 16 + (w >> 1) * 4);
            const unsigned mw1 = *(const unsigned*)(smem + (c & 1) * ASTAGE + MSK_OFF +
                                                    (mt * 16 + r + 8) * 16 + (w >> 1) * 4);
            const int bbase = (w & 1) * 16;
            float p[2][4];
#pragma unroll
            for (int nt = 0; nt < 2; nt++) {
                const int xb = bbase + nt * 8 + 2 * (lane & 3);
                p[nt][0] = ((mw0 >> xb) & 1)       ? 0.f : __expf(accs[mt][nt][0]);
                p[nt][1] = ((mw0 >> (xb + 1)) & 1) ? 0.f : __expf(accs[mt][nt][1]);
                p[nt][2] = ((mw1 >> xb) & 1)       ? 0.f : __expf(accs[mt][nt][2]);
                p[nt][3] = ((mw1 >> (xb + 1)) & 1) ? 0.f : __expf(accs[mt][nt][3]);
            }
            rs[mt][0] += p[0][0] + p[0][1] + p[1][0] + p[1][1];
            rs[mt][1] += p[0][2] + p[0][3] + p[1][2] + p[1][3];
            if (h == 0) {
                const size_t base = ((size_t)b * NL + q0 + mt * 16 + r) * NL + kt + w * 16;
                const int cc = 2 * (lane & 3);
                *(float2*)(attn_out + base + cc)               = make_float2(p[0][0], p[0][1]);
                *(float2*)(attn_out + base + 8 + cc)           = make_float2(p[1][0], p[1][1]);
                *(float2*)(attn_out + base + (size_t)8 * NL + cc)     = make_float2(p[0][2], p[0][3]);
                *(float2*)(attn_out + base + (size_t)8 * NL + 8 + cc) = make_float2(p[1][2], p[1][3]);
            }
            unsigned ap[4];
            ap[0] = pkhf2(p[0][0], p[0][1]);
            ap[1] = pkhf2(p[0][2], p[0][3]);
            ap[2] = pkhf2(p[1][0], p[1][1]);
            ap[3] = pkhf2(p[1][2], p[1][3]);
#pragma unroll
            for (int nt = 0; nt < 8; nt++) {
                const int np = nt >> 1, hf = (nt & 1) * 2;
                mma16816h(accv[mt][nt], ap, bv[np][hf], bv[np][hf + 1]);
            }
        }
        __syncthreads();
    }
#undef AISSUE

    // ---- row-sum reduce (RSPOFF lives ABOVE the red region) ----
#pragma unroll
    for (int mt = 0; mt < 4; mt++)
#pragma unroll
        for (int hf = 0; hf < 2; hf++) {
            float v = rs[mt][hf];
            v += __shfl_xor_sync(0xffffffffu, v, 1);
            v += __shfl_xor_sync(0xffffffffu, v, 2);
            if ((lane & 3) == 0)
                *(float*)(smem + RSPOFF + (w * QT + mt * 16 + hf * 8 + (lane >> 2)) * 4) = v;
        }

    // ---- PV cross-warp reduce via swizzled smem (red = bytes [0, RED_B)) ----
    float* red = (float*)smem;
#pragma unroll
    for (int mt = 0; mt < 4; mt++)
#pragma unroll
        for (int nt = 0; nt < 8; nt++) {
            const int r0 = mt * 16 + (lane >> 2);
            const int cc = nt * 8 + 2 * (lane & 3);
            *(float2*)&red[(w * QT + r0) * 64 + (cc ^ ((r0 & 3) << 3))] =
                make_float2(accv[mt][nt][0], accv[mt][nt][1]);
            const int r1 = r0 + 8;
            *(float2*)&red[(w * QT + r1) * 64 + (cc ^ ((r1 & 3) << 3))] =
                make_float2(accv[mt][nt][2], accv[mt][nt][3]);
        }
    __syncthreads();

    float* invs = (float*)(smem + INVOFF);
    if (t < QT) {
        float s = 0.f;
#pragma unroll
        for (int ww = 0; ww < 8; ww++)
            s += *(float*)(smem + RSPOFF + (ww * QT + t) * 4);
        invs[t] = 1.f / s;
        if (h == 0) g_rsum[(size_t)b * NL + q0 + t] = s;
    }
    __syncthreads();

    for (int idx = t; idx < QT * DH / 2; idx += 256) {
        const int q = idx >> 5, dp = idx & 31;
        const int d0 = dp * 2, sw = (q & 3) << 3;
        float s0 = 0.f, s1 = 0.f;
#pragma unroll
        for (int ww = 0; ww < 8; ww++) {
            const float* rr = &red[(ww * QT + q) * 64];
            s0 += rr[d0 ^ sw];
            s1 += rr[(d0 + 1) ^ sw];
        }
        const float inv = invs[q];
        s0 *= inv; s1 *= inv;
        unsigned hi, lo;
        split2(s0, s1, hi, lo);
        const size_t off = ((size_t)(b * NL + q0 + q)) * ND + h * DH + d0;
        *(unsigned*)(g_a0 + off) = hi;
        *(unsigned*)(g_a1 + off) = lo;
    }
}

// ---------------------------------------------------------------------------
extern "C" void kernel_launch(void* const* d_in, const int* in_sizes, int n_in,
                              void* d_out, int out_size)
{
    const float* key   = (const float*)d_in[0];
    const float* value = (const float*)d_in[1];
    const float* query = (const float*)d_in[2];
    const int*   mask  = (const int*)d_in[3];
    const float* Wk = (const float*)d_in[4];
    const float* bk = (const float*)d_in[5];
    const float* Wv = (const float*)d_in[6];
    const float* bv = (const float*)d_in[7];
    const float* Wq = (const float*)d_in[8];
    const float* bq = (const float*)d_in[9];
    const float* Wo = (const float*)d_in[10];
    const float* bo = (const float*)d_in[11];

    float* out      = (float*)d_out;
    float* attn_out = out + (size_t)NB * NL * ND;

    static int attr_set = 0;
    if (!attr_set) {
        cudaFuncSetAttribute(gemm_proj_kernel, cudaFuncAttributeMaxDynamicSharedMemorySize, GSMEM);
        cudaFuncSetAttribute(gemm_out_kernel, cudaFuncAttributeMaxDynamicSharedMemorySize, GSMEM);
        cudaFuncSetAttribute(attn_fused_kernel, cudaFuncAttributeMaxDynamicSharedMemorySize, ASMEM);
        attr_set = 1;
    }

    const int convA_blocks = (NB * NL * ND) / (4 * 256);       // 8192
    const dim3 gemm_grid(ND / 128, (NB * NL) / 128, 3);        // 8 x 64 x 3

    convA_kernel<<<dim3(convA_blocks, 3), 256>>>(key, value, query);
    convW_kernel<<<dim3(ND / 32, ND / 32, 3), dim3(32, 8)>>>(Wk, Wv, Wq);
    gemm_proj_kernel<<<gemm_grid, 256, GSMEM>>>(bk, bv, bq);

    vtrans_kernel<<<dim3(NL / 64, NB * NH), 256>>>();
    mask2bits_kernel<<<1024, 256>>>(mask);

    const dim3 attn_grid(NL / QT, NH, NB);   // 32 x 16 x 4
    attn_fused_kernel<<<attn_grid, 256, ASMEM>>>(attn_out);
    norm_attn_kernel<<<NB * NL, 256>>>(attn_out);

    convW_kernel<<<dim3(ND / 32, ND / 32, 1), dim3(32, 8)>>>(Wo, Wo, Wo);
    gemm_out_kernel<<<dim3(ND / 128, (NB * NL) / 128), 256, GSMEM>>>(bo, out);
}

// round 14
// speedup vs baseline: 3.9604x; 1.0082x over previous
#include <cuda_runtime.h>
#include <cuda_bf16.h>
#include <cuda_fp16.h>

#define NB 4
#define NL 2048
#define ND 1024
#define NH 16
#define DH 64

// ---------------- mma.sync GEMM config (512-thread variant) ----------------
#define BK    32
#define ASTR  40
#define TILE_B (128*ASTR*2)
#define STAGE_B (4*TILE_B)
#define GSMEM  (2*STAGE_B)
#define APLANE ((size_t)NB*NL*ND)
#define WPLANE ((size_t)ND*ND)

// ---------------- fused fp16 attention config (QT=64, round-13 proven) -----
#define QT    64
#define KCH   128
#define KST   72
#define VST   136
#define KTILE (KCH*KST*2)
#define VTILE (64*VST*2)
#define VOFF  KTILE
#define MSK_OFF (KTILE + VTILE)
#define ASTAGE  (MSK_OFF + QT*16)
#define QOFF    (2*ASTAGE)
#define QSPL    (QT*KST*2)
#define RED_B   (8*QT*64*4)
#define RSPOFF  RED_B
#define INVOFF  (RSPOFF + 8*QT*4)
#define ASMEM   (INVOFF + QT*4)

// ---- cp.async ----
__device__ __forceinline__ void cpasync16(unsigned dst, const void* src) {
    asm volatile("cp.async.cg.shared.global [%0], [%1], 16;" :: "r"(dst), "l"(src) : "memory");
}
__device__ __forceinline__ void cp_commit() { asm volatile("cp.async.commit_group;" ::: "memory"); }
__device__ __forceinline__ void cp_wait0()  { asm volatile("cp.async.wait_group 0;" ::: "memory"); }
__device__ __forceinline__ void cp_wait1()  { asm volatile("cp.async.wait_group 1;" ::: "memory"); }
__device__ __forceinline__ unsigned smem_u32(const void* p) {
    unsigned a;
    asm("{ .reg .u64 t; cvta.to.shared.u64 t, %1; cvt.u32.u64 %0, t; }" : "=r"(a) : "l"(p));
    return a;
}
// ---- tensor-core (baseline PTX) ----
__device__ __forceinline__ void ldsm4(unsigned& r0, unsigned& r1,
                                      unsigned& r2, unsigned& r3, unsigned addr) {
    asm volatile("ldmatrix.sync.aligned.m8n8.x4.shared.b16 {%0,%1,%2,%3}, [%4];"
                 : "=r"(r0), "=r"(r1), "=r"(r2), "=r"(r3) : "r"(addr));
}
__device__ __forceinline__ void mma16816(float* d, const unsigned* a,
                                         unsigned b0, unsigned b1) {
    asm volatile(
        "mma.sync.aligned.m16n8k16.row.col.f32.bf16.bf16.f32 "
        "{%0,%1,%2,%3}, {%4,%5,%6,%7}, {%8,%9}, {%0,%1,%2,%3};"
        : "+f"(d[0]), "+f"(d[1]), "+f"(d[2]), "+f"(d[3])
        : "r"(a[0]), "r"(a[1]), "r"(a[2]), "r"(a[3]), "r"(b0), "r"(b1));
}
__device__ __forceinline__ void mma16816h(float* d, const unsigned* a,
                                          unsigned b0, unsigned b1) {
    asm volatile(
        "mma.sync.aligned.m16n8k16.row.col.f32.f16.f16.f32 "
        "{%0,%1,%2,%3}, {%4,%5,%6,%7}, {%8,%9}, {%0,%1,%2,%3};"
        : "+f"(d[0]), "+f"(d[1]), "+f"(d[2]), "+f"(d[3])
        : "r"(a[0]), "r"(a[1]), "r"(a[2]), "r"(a[3]), "r"(b0), "r"(b1));
}
__device__ __forceinline__ unsigned pkbf2(float pe, float po) {
    unsigned d;
    asm("cvt.rn.bf16x2.f32 %0, %1, %2;" : "=r"(d) : "f"(po), "f"(pe));
    return d;
}
__device__ __forceinline__ unsigned pkhf2(float pe, float po) {
    unsigned d;
    asm("cvt.rn.f16x2.f32 %0, %1, %2;" : "=r"(d) : "f"(po), "f"(pe));
    return d;
}
__device__ __forceinline__ void split2(float pe, float po, unsigned& hi, unsigned& lo) {
    hi = pkbf2(pe, po);
    const float re = pe - __uint_as_float(hi << 16);
    const float ro = po - __uint_as_float(hi & 0xFFFF0000u);
    lo = pkbf2(re, ro);
}

// Scratch device globals
__device__ __nv_bfloat16 g_a0[3 * APLANE];
__device__ __nv_bfloat16 g_a1[3 * APLANE];
__device__ __nv_bfloat16 g_w0[4 * WPLANE];
__device__ __nv_bfloat16 g_w1[4 * WPLANE];
__device__ __half g_kh[APLANE];
__device__ __half g_qh[APLANE];
__device__ __half g_vh[APLANE];
__device__ __half g_vth[APLANE];
__device__ unsigned g_mbits[(size_t)NB * NL * (NL / 32)];
__device__ float    g_rsum[(size_t)NB * NL];

// ---------------------------------------------------------------------------
// convA (batched y=3): fp32 [M,1024] -> bf16 hi/lo splits
// ---------------------------------------------------------------------------
__global__ void convA_kernel(const float* __restrict__ s0,
                             const float* __restrict__ s1,
                             const float* __restrict__ s2)
{
    const int z = blockIdx.y;
    const float* src = (z == 0) ? s0 : (z == 1) ? s1 : s2;
    const size_t i = ((size_t)blockIdx.x * 256 + threadIdx.x) * 4;
    const float4 v = *(const float4*)(src + i);
    unsigned h0, l0, h1, l1;
    split2(v.x, v.y, h0, l0);
    split2(v.z, v.w, h1, l1);
    __nv_bfloat16* a0 = g_a0 + (size_t)z * APLANE;
    __nv_bfloat16* a1 = g_a1 + (size_t)z * APLANE;
    *(unsigned*)(a0 + i)     = h0;
    *(unsigned*)(a0 + i + 2) = h1;
    *(unsigned*)(a1 + i)     = l0;
    *(unsigned*)(a1 + i + 2) = l1;
}

// ---------------------------------------------------------------------------
// convW (batched z=4): fp32 W[k][n] -> transposed bf16 splits [n][k]
// ---------------------------------------------------------------------------
__global__ void convW_kernel(const float* __restrict__ W0,
                             const float* __restrict__ W1,
                             const float* __restrict__ W2,
                             const float* __restrict__ W3)
{
    const int z = blockIdx.z;
    const float* W = (z == 0) ? W0 : (z == 1) ? W1 : (z == 2) ? W2 : W3;
    __shared__ float tile[32][33];
    const int k0 = blockIdx.y * 32, n0 = blockIdx.x * 32;
    for (int r = threadIdx.y; r < 32; r += 8)
        tile[r][threadIdx.x] = W[(size_t)(k0 + r) * ND + n0 + threadIdx.x];
    __syncthreads();
    __nv_bfloat16* w0 = g_w0 + (size_t)z * WPLANE;
    __nv_bfloat16* w1 = g_w1 + (size_t)z * WPLANE;
    for (int r = threadIdx.y; r < 32; r += 8) {
        const float v = tile[threadIdx.x][r];
        const size_t o = (size_t)(n0 + r) * ND + k0 + threadIdx.x;
        __nv_bfloat16 hi = __float2bfloat16(v);
        w0[o] = hi;
        w1[o] = __float2bfloat16(v - __bfloat162float(hi));
    }
}

// ---------------------------------------------------------------------------
// vtrans: g_vh [bh][l][d] -> g_vth [bh][d][l]
// ---------------------------------------------------------------------------
__global__ void vtrans_kernel()
{
    __shared__ __half tl[64][65];
    const int bh = blockIdx.y;
    const int l0 = blockIdx.x * 64;
    const size_t pin = (size_t)bh * NL * DH;
#pragma unroll
    for (int i = 0; i < 8; i++) {
        const int u = threadIdx.x + i * 256;
        const int li = u >> 5, dp = u & 31;
        const __half2 v = *(const __half2*)(g_vh + pin + (size_t)(l0 + li) * DH + dp * 2);
        tl[li][dp * 2]     = __low2half(v);
        tl[li][dp * 2 + 1] = __high2half(v);
    }
    __syncthreads();
    const size_t pout = (size_t)bh * DH * NL;
#pragma unroll
    for (int i = 0; i < 8; i++) {
        const int u = threadIdx.x + i * 256;
        const int d = u >> 5, lp = u & 31;
        __half2 v = __halves2half2(tl[lp * 2][d], tl[lp * 2 + 1][d]);
        *(__half2*)(g_vth + pout + (size_t)d * NL + l0 + lp * 2) = v;
    }
}

// ---------------------------------------------------------------------------
// mask2bits
// ---------------------------------------------------------------------------
__global__ void mask2bits_kernel(const int* __restrict__ mask)
{
    const int gw = (blockIdx.x * 256 + threadIdx.x) >> 5;
    const int lane = threadIdx.x & 31;
    const int nwords = NB * NL * (NL / 32);
    const int step = (gridDim.x * 256) >> 5;
    for (int wv = gw; wv < nwords; wv += step) {
        const int v = mask[(size_t)wv * 32 + lane];
        const unsigned bits = __ballot_sync(0xffffffffu, v != 0);
        if (lane == 0) g_mbits[wv] = bits;
    }
}

// ---------------------------------------------------------------------------
// norm_attn
// ---------------------------------------------------------------------------
__global__ void norm_attn_kernel(float* __restrict__ attn_out)
{
    const int row = blockIdx.x;
    const float inv = 1.f / g_rsum[row];
    float4* p = (float4*)(attn_out + (size_t)row * NL);
    for (int i = threadIdx.x; i < NL / 4; i += 256) {
        float4 v = p[i];
        v.x *= inv; v.y *= inv; v.z *= inv; v.w *= inv;
        p[i] = v;
    }
}

// ---------------------------------------------------------------------------
// Shared GEMM mainloop (3x bf16-split), 512 threads / 16 warps.
// Warp tile 32x32: wm = (wid&3)*32, wn = (wid>>2)*32. acc[2][4][4].
// ---------------------------------------------------------------------------
#define GEMM_MAINLOOP(Aptr0, Aptr1, Wptr0, Wptr1)                                 \
    const __nv_bfloat16* srcs[4] = { Aptr0, Aptr1, Wptr0, Wptr1 };                \
    float acc[2][4][4];                                                           \
    _Pragma("unroll")                                                             \
    for (int mt = 0; mt < 2; mt++)                                                \
        _Pragma("unroll")                                                         \
        for (int nt = 0; nt < 4; nt++)                                            \
            _Pragma("unroll")                                                     \
            for (int r = 0; r < 4; r++) acc[mt][nt][r] = 0.f;                     \
    const int arow = (lane & 7) | (lane & 8);                                     \
    const int acol = (lane & 16) >> 1;                                            \
    const int brow = (lane & 7) | ((lane & 16) >> 1);                             \
    const int bcol = lane & 8;                                                    \
    {                                                                             \
        const unsigned sb = sb0;                                                  \
        const int row = t >> 2, seg = t & 3;                                      \
        _Pragma("unroll")                                                         \
        for (int s = 0; s < 4; s++)                                               \
            cpasync16(sb + s * TILE_B + (row * ASTR + seg * 8) * 2,               \
                      srcs[s] + (size_t)row * ND + seg * 8);                      \
        cp_commit();                                                              \
    }                                                                             \
    for (int c = 0; c < ND / BK; c++) {                                           \
        if (c + 1 < ND / BK) {                                                    \
            const unsigned sb = sb0 + ((c + 1) & 1) * STAGE_B;                    \
            const int k0 = (c + 1) * BK;                                          \
            const int row = t >> 2, seg = t & 3;                                  \
            _Pragma("unroll")                                                     \
            for (int s = 0; s < 4; s++)                                           \
                cpasync16(sb + s * TILE_B + (row * ASTR + seg * 8) * 2,           \
                          srcs[s] + (size_t)row * ND + k0 + seg * 8);             \
            cp_commit(); cp_wait1();                                              \
        } else { cp_wait0(); }                                                    \
        __syncthreads();                                                          \
        const unsigned sb = sb0 + (c & 1) * STAGE_B;                              \
        _Pragma("unroll")                                                         \
        for (int ks = 0; ks < 2; ks++) {                                          \
            const int kc = ks * 16;                                               \
            unsigned af[2][2][4];                                                 \
            _Pragma("unroll")                                                     \
            for (int sp = 0; sp < 2; sp++)                                        \
                _Pragma("unroll")                                                 \
                for (int mt = 0; mt < 2; mt++)                                    \
                    ldsm4(af[sp][mt][0], af[sp][mt][1], af[sp][mt][2], af[sp][mt][3], \
                          sb + sp * TILE_B +                                      \
                          (unsigned)(((wm + mt * 16 + arow) * ASTR + kc + acol) * 2)); \
            unsigned bf[2][2][4];                                                 \
            _Pragma("unroll")                                                     \
            for (int sp = 0; sp < 2; sp++)                                        \
                _Pragma("unroll")                                                 \
                for (int np = 0; np < 2; np++)                                    \
                    ldsm4(bf[sp][np][0], bf[sp][np][1], bf[sp][np][2], bf[sp][np][3], \
                          sb + (2 + sp) * TILE_B +                                \
                          (unsigned)(((wn + np * 16 + brow) * ASTR + kc + bcol) * 2)); \
            _Pragma("unroll")                                                     \
            for (int mt = 0; mt < 2; mt++)                                        \
                _Pragma("unroll")                                                 \
                for (int nt = 0; nt < 4; nt++) {                                  \
                    const int np = nt >> 1, half = (nt & 1) * 2;                  \
                    mma16816(acc[mt][nt], af[0][mt], bf[0][np][half], bf[0][np][half + 1]); \
                    mma16816(acc[mt][nt], af[0][mt], bf[1][np][half], bf[1][np][half + 1]); \
                    mma16816(acc[mt][nt], af[1][mt], bf[0][np][half], bf[0][np][half + 1]); \
                }                                                                 \
        }                                                                         \
        __syncthreads();                                                          \
    }

// ---------------------------------------------------------------------------
// Batched projection GEMM (grid.z = 3, 512 threads): -> fp16 scatter
// ---------------------------------------------------------------------------
__global__ void __launch_bounds__(512, 1) gemm_proj_kernel(
    const float* __restrict__ b0p, const float* __restrict__ b1p,
    const float* __restrict__ b2p)
{
    extern __shared__ char smem[];
    const unsigned sb0 = smem_u32(smem);
    const int t = threadIdx.x, lane = t & 31, wid = t >> 5;
    const int wm = (wid & 3) * 32, wn = (wid >> 2) * 32;
    const int n0 = blockIdx.x * 128, m0 = blockIdx.y * 128;
    const int z = blockIdx.z;
    const float* bias = (z == 0) ? b0p : (z == 1) ? b1p : b2p;
    __half* dsth = (z == 0) ? g_kh : (z == 1) ? g_vh : g_qh;
    const float scale = (z == 2) ? 0.125f : 1.0f;

    GEMM_MAINLOOP(g_a0 + z * APLANE + (size_t)m0 * ND,
                  g_a1 + z * APLANE + (size_t)m0 * ND,
                  g_w0 + z * WPLANE + (size_t)n0 * ND,
                  g_w1 + z * WPLANE + (size_t)n0 * ND)

#pragma unroll
    for (int mt = 0; mt < 2; mt++)
#pragma unroll
        for (int nt = 0; nt < 4; nt++) {
            const int cc = n0 + wn + nt * 8 + (lane & 3) * 2;
            const float b0 = bias[cc], b1 = bias[cc + 1];
            const float v0 = (acc[mt][nt][0] + b0) * scale;
            const float v1 = (acc[mt][nt][1] + b1) * scale;
            const float v2 = (acc[mt][nt][2] + b0) * scale;
            const float v3 = (acc[mt][nt][3] + b1) * scale;
            const int r0 = m0 + wm + mt * 16 + (lane >> 2);
            const int bb = r0 >> 11, h = cc >> 6, d = cc & 63;
            size_t o = ((size_t)(bb * NH + h) * NL + (r0 & (NL - 1))) * DH + d;
            *(unsigned*)(dsth + o) = pkhf2(v0, v1);
            o = ((size_t)(bb * NH + h) * NL + ((r0 + 8) & (NL - 1))) * DH + d;
            *(unsigned*)(dsth + o) = pkhf2(v2, v3);
        }
}

// ---------------------------------------------------------------------------
// Output GEMM (512 threads): (ctx @ Wo + bo) -> fp32
// ---------------------------------------------------------------------------
__global__ void __launch_bounds__(512, 1) gemm_out_kernel(
    const float* __restrict__ bias, float* __restrict__ dstf)
{
    extern __shared__ char smem[];
    const unsigned sb0 = smem_u32(smem);
    const int t = threadIdx.x, lane = t & 31, wid = t >> 5;
    const int wm = (wid & 3) * 32, wn = (wid >> 2) * 32;
    const int n0 = blockIdx.x * 128, m0 = blockIdx.y * 128;

    GEMM_MAINLOOP(g_a0 + (size_t)m0 * ND, g_a1 + (size_t)m0 * ND,
                  g_w0 + 3 * WPLANE + (size_t)n0 * ND,
                  g_w1 + 3 * WPLANE + (size_t)n0 * ND)

#pragma unroll
    for (int mt = 0; mt < 2; mt++)
#pragma unroll
        for (int nt = 0; nt < 4; nt++) {
            const int cc = n0 + wn + nt * 8 + (lane & 3) * 2;
            const float b0 = bias[cc], b1 = bias[cc + 1];
            const int r0 = m0 + wm + mt * 16 + (lane >> 2);
            dstf[(size_t)r0 * ND + cc]           = acc[mt][nt][0] + b0;
            dstf[(size_t)r0 * ND + cc + 1]       = acc[mt][nt][1] + b1;
            dstf[(size_t)(r0 + 8) * ND + cc]     = acc[mt][nt][2] + b0;
            dstf[(size_t)(r0 + 8) * ND + cc + 1] = acc[mt][nt][3] + b1;
        }
}

// ---------------------------------------------------------------------------
// Fused fp16 flash attention (round-13 proven, unchanged)
// ---------------------------------------------------------------------------
__global__ void __launch_bounds__(256, 1) attn_fused_kernel(
    float* __restrict__ attn_out)
{
    extern __shared__ char smem[];
    const unsigned sb = smem_u32(smem);
    const int t = threadIdx.x, lane = t & 31, w = t >> 5;
    const int q0 = blockIdx.x * QT;
    const int h = blockIdx.y, b = blockIdx.z;
    const int bh = b * NH + h;

    const __half* kph = g_kh + (size_t)bh * NL * DH;
    const __half* vph = g_vth + (size_t)bh * DH * NL;
    const __half* qph = g_qh + (size_t)bh * NL * DH;

    const int arow = (lane & 7) | (lane & 8);
    const int acol = (lane & 16) >> 1;
    const int brow = (lane & 7) | ((lane & 16) >> 1);
    const int bcol = lane & 8;

#pragma unroll
    for (int i = 0; i < 2; i++) {
        const int u = t + i * 256;
        const int r = u >> 3, seg = u & 7;
        cpasync16(sb + QOFF + r * (KST * 2) + seg * 16,
                  qph + (size_t)(q0 + r) * DH + seg * 8);
    }

    const unsigned* mb = g_mbits;

#define AISSUE(c) do {                                                           \
    const unsigned st_ = sb + ((c) & 1) * ASTAGE;                                \
    const int kt_ = (c) * KCH;                                                   \
    _Pragma("unroll")                                                            \
    for (int i = 0; i < 4; i++) {                                                \
        const int u = t + i * 256;                                               \
        const int r = u >> 3, seg = u & 7;                                       \
        cpasync16(st_ + r * (KST * 2) + seg * 16,                                \
                  kph + (size_t)(kt_ + r) * DH + seg * 8);                       \
    }                                                                            \
    _Pragma("unroll")                                                            \
    for (int i = 0; i < 4; i++) {                                                \
        const int u = t + i * 256;                                               \
        const int r = u >> 4, seg = u & 15;                                      \
        cpasync16(st_ + VOFF + r * (VST * 2) + seg * 16,                         \
                  vph + (size_t)r * NL + kt_ + seg * 8);                         \
    }                                                                            \
    if (t < QT)                                                                  \
        cpasync16(st_ + MSK_OFF + t * 16,                                        \
                  mb + ((size_t)b * NL + q0 + t) * (NL / 32) + (kt_ >> 5));      \
    cp_commit();                                                                 \
} while (0)

    float accv[4][8][4];
#pragma unroll
    for (int mt = 0; mt < 4; mt++)
#pragma unroll
        for (int nt = 0; nt < 8; nt++)
#pragma unroll
            for (int r = 0; r < 4; r++) accv[mt][nt][r] = 0.f;
    float rs[4][2];
#pragma unroll
    for (int mt = 0; mt < 4; mt++) { rs[mt][0] = 0.f; rs[mt][1] = 0.f; }

    AISSUE(0);
    for (int c = 0; c < NL / KCH; c++) {
        if (c + 1 < NL / KCH) { AISSUE(c + 1); cp_wait1(); }
        else                  { cp_wait0(); }
        __syncthreads();
        const unsigned st = sb + (c & 1) * ASTAGE;
        const int kt = c * KCH;

        float accs[4][2][4];
#pragma unroll
        for (int mt = 0; mt < 4; mt++)
#pragma unroll
            for (int nt = 0; nt < 2; nt++)
#pragma unroll
                for (int r = 0; r < 4; r++) accs[mt][nt][r] = 0.f;

#pragma unroll
        for (int ks = 0; ks < 4; ks++) {
            const int kc = ks * 16;
            unsigned bk[4];
            ldsm4(bk[0], bk[1], bk[2], bk[3],
                  st + (unsigned)((w * 16 + brow) * (KST * 2) + (kc + bcol) * 2));
#pragma unroll
            for (int mt = 0; mt < 4; mt++) {
                unsigned aq[4];
                ldsm4(aq[0], aq[1], aq[2], aq[3],
                      sb + QOFF +
                      (unsigned)((mt * 16 + arow) * (KST * 2) + (kc + acol) * 2));
                mma16816h(accs[mt][0], aq, bk[0], bk[1]);
                mma16816h(accs[mt][1], aq, bk[2], bk[3]);
            }
        }

        unsigned bv[4][4];
#pragma unroll
        for (int np = 0; np < 4; np++)
            ldsm4(bv[np][0], bv[np][1], bv[np][2], bv[np][3],
                  st + VOFF +
                  (unsigned)((np * 16 + brow) * (VST * 2) + (w * 16 + bcol) * 2));

#pragma unroll
        for (int mt = 0; mt < 4; mt++) {
            const int r = lane >> 2;
            const unsigned mw0 = *(const unsigned*)(smem + (c & 1) * ASTAGE + MSK_OFF +
                                                    (mt * 16 + r) * 16 + (w >> 1) * 4);
            const unsigned mw1 = *(const unsigned*)(smem + (c & 1) * ASTAGE + MSK_OFF +
                                                    (mt * 16 + r + 8) * 16 + (w >> 1) * 4);
            const int bbase = (w & 1) * 16;
            float p[2][4];
#pragma unroll
            for (int nt = 0; nt < 2; nt++) {
                const int xb = bbase + nt * 8 + 2 * (lane & 3);
                p[nt][0] = ((mw0 >> xb) & 1)       ? 0.f : __expf(accs[mt][nt][0]);
                p[nt][1] = ((mw0 >> (xb + 1)) & 1) ? 0.f : __expf(accs[mt][nt][1]);
                p[nt][2] = ((mw1 >> xb) & 1)       ? 0.f : __expf(accs[mt][nt][2]);
                p[nt][3] = ((mw1 >> (xb + 1)) & 1) ? 0.f : __expf(accs[mt][nt][3]);
            }
            rs[mt][0] += p[0][0] + p[0][1] + p[1][0] + p[1][1];
            rs[mt][1] += p[0][2] + p[0][3] + p[1][2] + p[1][3];
            if (h == 0) {
                const size_t base = ((size_t)b * NL + q0 + mt * 16 + r) * NL + kt + w * 16;
                const int cc = 2 * (lane & 3);
                *(float2*)(attn_out + base + cc)               = make_float2(p[0][0], p[0][1]);
                *(float2*)(attn_out + base + 8 + cc)           = make_float2(p[1][0], p[1][1]);
                *(float2*)(attn_out + base + (size_t)8 * NL + cc)     = make_float2(p[0][2], p[0][3]);
                *(float2*)(attn_out + base + (size_t)8 * NL + 8 + cc) = make_float2(p[1][2], p[1][3]);
            }
            unsigned ap[4];
            ap[0] = pkhf2(p[0][0], p[0][1]);
            ap[1] = pkhf2(p[0][2], p[0][3]);
            ap[2] = pkhf2(p[1][0], p[1][1]);
            ap[3] = pkhf2(p[1][2], p[1][3]);
#pragma unroll
            for (int nt = 0; nt < 8; nt++) {
                const int np = nt >> 1, hf = (nt & 1) * 2;
                mma16816h(accv[mt][nt], ap, bv[np][hf], bv[np][hf + 1]);
            }
        }
        __syncthreads();
    }
#undef AISSUE

#pragma unroll
    for (int mt = 0; mt < 4; mt++)
#pragma unroll
        for (int hf = 0; hf < 2; hf++) {
            float v = rs[mt][hf];
            v += __shfl_xor_sync(0xffffffffu, v, 1);
            v += __shfl_xor_sync(0xffffffffu, v, 2);
            if ((lane & 3) == 0)
                *(float*)(smem + RSPOFF + (w * QT + mt * 16 + hf * 8 + (lane >> 2)) * 4) = v;
        }

    float* red = (float*)smem;
#pragma unroll
    for (int mt = 0; mt < 4; mt++)
#pragma unroll
        for (int nt = 0; nt < 8; nt++) {
            const int r0 = mt * 16 + (lane >> 2);
            const int cc = nt * 8 + 2 * (lane & 3);
            *(float2*)&red[(w * QT + r0) * 64 + (cc ^ ((r0 & 3) << 3))] =
                make_float2(accv[mt][nt][0], accv[mt][nt][1]);
            const int r1 = r0 + 8;
            *(float2*)&red[(w * QT + r1) * 64 + (cc ^ ((r1 & 3) << 3))] =
                make_float2(accv[mt][nt][2], accv[mt][nt][3]);
        }
    __syncthreads();

    float* invs = (float*)(smem + INVOFF);
    if (t < QT) {
        float s = 0.f;
#pragma unroll
        for (int ww = 0; ww < 8; ww++)
            s += *(float*)(smem + RSPOFF + (ww * QT + t) * 4);
        invs[t] = 1.f / s;
        if (h == 0) g_rsum[(size_t)b * NL + q0 + t] = s;
    }
    __syncthreads();

    for (int idx = t; idx < QT * DH / 2; idx += 256) {
        const int q = idx >> 5, dp = idx & 31;
        const int d0 = dp * 2, sw = (q & 3) << 3;
        float s0 = 0.f, s1 = 0.f;
#pragma unroll
        for (int ww = 0; ww < 8; ww++) {
            const float* rr = &red[(ww * QT + q) * 64];
            s0 += rr[d0 ^ sw];
            s1 += rr[(d0 + 1) ^ sw];
        }
        const float inv = invs[q];
        s0 *= inv; s1 *= inv;
        unsigned hi, lo;
        split2(s0, s1, hi, lo);
        const size_t off = ((size_t)(b * NL + q0 + q)) * ND + h * DH + d0;
        *(unsigned*)(g_a0 + off) = hi;
        *(unsigned*)(g_a1 + off) = lo;
    }
}

// ---------------------------------------------------------------------------
extern "C" void kernel_launch(void* const* d_in, const int* in_sizes, int n_in,
                              void* d_out, int out_size)
{
    const float* key   = (const float*)d_in[0];
    const float* value = (const float*)d_in[1];
    const float* query = (const float*)d_in[2];
    const int*   mask  = (const int*)d_in[3];
    const float* Wk = (const float*)d_in[4];
    const float* bk = (const float*)d_in[5];
    const float* Wv = (const float*)d_in[6];
    const float* bv = (const float*)d_in[7];
    const float* Wq = (const float*)d_in[8];
    const float* bq = (const float*)d_in[9];
    const float* Wo = (const float*)d_in[10];
    const float* bo = (const float*)d_in[11];

    float* out      = (float*)d_out;
    float* attn_out = out + (size_t)NB * NL * ND;

    static int attr_set = 0;
    if (!attr_set) {
        cudaFuncSetAttribute(gemm_proj_kernel, cudaFuncAttributeMaxDynamicSharedMemorySize, GSMEM);
        cudaFuncSetAttribute(gemm_out_kernel, cudaFuncAttributeMaxDynamicSharedMemorySize, GSMEM);
        cudaFuncSetAttribute(attn_fused_kernel, cudaFuncAttributeMaxDynamicSharedMemorySize, ASMEM);
        attr_set = 1;
    }

    const int convA_blocks = (NB * NL * ND) / (4 * 256);       // 8192
    const dim3 gemm_grid(ND / 128, (NB * NL) / 128, 3);        // 8 x 64 x 3

    convA_kernel<<<dim3(convA_blocks, 3), 256>>>(key, value, query);
    convW_kernel<<<dim3(ND / 32, ND / 32, 4), dim3(32, 8)>>>(Wk, Wv, Wq, Wo);
    gemm_proj_kernel<<<gemm_grid, 512, GSMEM>>>(bk, bv, bq);

    vtrans_kernel<<<dim3(NL / 64, NB * NH), 256>>>();
    mask2bits_kernel<<<1024, 256>>>(mask);

    const dim3 attn_grid(NL / QT, NH, NB);   // 32 x 16 x 4
    attn_fused_kernel<<<attn_grid, 256, ASMEM>>>(attn_out);
    norm_attn_kernel<<<NB * NL, 256>>>(attn_out);

    gemm_out_kernel<<<dim3(ND / 128, (NB * NL) / 128), 512, GSMEM>>>(bo, out);
}

// round 15
// speedup vs baseline: 4.6938x; 1.1852x over previous
#include <cuda_runtime.h>
#include <cuda_bf16.h>
#include <cuda_fp16.h>

#define NB 4
#define NL 2048
#define ND 1024
#define NH 16
#define DH 64

// ---------------- mma.sync GEMM config (fp16 2-split, 512 threads) ---------
#define BK    32
#define ASTR  40
#define TILE_B (128*ASTR*2)          // 10240 B per tile (fp16)
#define STAGE_B (3*TILE_B)           // 30720 B per stage (A0, A1, B)
#define GSMEM  (2*STAGE_B)           // 61440 B
#define APLANE ((size_t)NB*NL*ND)
#define WPLANE ((size_t)ND*ND)

// ---------------- fused fp16 attention config (QT=64, round-13 proven) -----
#define QT    64
#define KCH   128
#define KST   72
#define VST   136
#define KTILE (KCH*KST*2)
#define VTILE (64*VST*2)
#define VOFF  KTILE
#define MSK_OFF (KTILE + VTILE)
#define ASTAGE  (MSK_OFF + QT*16)
#define QOFF    (2*ASTAGE)
#define QSPL    (QT*KST*2)
#define RED_B   (8*QT*64*4)
#define RSPOFF  RED_B
#define INVOFF  (RSPOFF + 8*QT*4)
#define ASMEM   (INVOFF + QT*4)

// ---- cp.async ----
__device__ __forceinline__ void cpasync16(unsigned dst, const void* src) {
    asm volatile("cp.async.cg.shared.global [%0], [%1], 16;" :: "r"(dst), "l"(src) : "memory");
}
__device__ __forceinline__ void cp_commit() { asm volatile("cp.async.commit_group;" ::: "memory"); }
__device__ __forceinline__ void cp_wait0()  { asm volatile("cp.async.wait_group 0;" ::: "memory"); }
__device__ __forceinline__ void cp_wait1()  { asm volatile("cp.async.wait_group 1;" ::: "memory"); }
__device__ __forceinline__ unsigned smem_u32(const void* p) {
    unsigned a;
    asm("{ .reg .u64 t; cvta.to.shared.u64 t, %1; cvt.u32.u64 %0, t; }" : "=r"(a) : "l"(p));
    return a;
}
// ---- tensor-core (baseline PTX) ----
__device__ __forceinline__ void ldsm4(unsigned& r0, unsigned& r1,
                                      unsigned& r2, unsigned& r3, unsigned addr) {
    asm volatile("ldmatrix.sync.aligned.m8n8.x4.shared.b16 {%0,%1,%2,%3}, [%4];"
                 : "=r"(r0), "=r"(r1), "=r"(r2), "=r"(r3) : "r"(addr));
}
__device__ __forceinline__ void mma16816h(float* d, const unsigned* a,
                                          unsigned b0, unsigned b1) {
    asm volatile(
        "mma.sync.aligned.m16n8k16.row.col.f32.f16.f16.f32 "
        "{%0,%1,%2,%3}, {%4,%5,%6,%7}, {%8,%9}, {%0,%1,%2,%3};"
        : "+f"(d[0]), "+f"(d[1]), "+f"(d[2]), "+f"(d[3])
        : "r"(a[0]), "r"(a[1]), "r"(a[2]), "r"(a[3]), "r"(b0), "r"(b1));
}
__device__ __forceinline__ unsigned pkhf2(float pe, float po) {
    unsigned d;
    asm("cvt.rn.f16x2.f32 %0, %1, %2;" : "=r"(d) : "f"(po), "f"(pe));
    return d;
}
// fp16 2-split: hi = f16x2(pe,po), lo = f16x2 of residuals
__device__ __forceinline__ void split2h(float pe, float po, unsigned& hi, unsigned& lo) {
    hi = pkhf2(pe, po);
    const __half2 h = *reinterpret_cast<const __half2*>(&hi);
    lo = pkhf2(pe - __half2float(__low2half(h)), po - __half2float(__high2half(h)));
}

// Scratch device globals
__device__ __half g_a0h[3 * APLANE];   // A hi planes (K/V/Q inputs; plane 0 reused for ctx)
__device__ __half g_a1h[3 * APLANE];   // A residual planes
__device__ __half g_w0h[4 * WPLANE];   // W^T fp16 planes (Wk, Wv, Wq, Wo)
__device__ __half g_kh[APLANE];
__device__ __half g_qh[APLANE];
__device__ __half g_vh[APLANE];
__device__ __half g_vth[APLANE];
__device__ unsigned g_mbits[(size_t)NB * NL * (NL / 32)];
__device__ float    g_rsum[(size_t)NB * NL];

// ---------------------------------------------------------------------------
// convA (batched y=3): fp32 [M,1024] -> fp16 hi/lo splits
// ---------------------------------------------------------------------------
__global__ void convA_kernel(const float* __restrict__ s0,
                             const float* __restrict__ s1,
                             const float* __restrict__ s2)
{
    const int z = blockIdx.y;
    const float* src = (z == 0) ? s0 : (z == 1) ? s1 : s2;
    const size_t i = ((size_t)blockIdx.x * 256 + threadIdx.x) * 4;
    const float4 v = *(const float4*)(src + i);
    unsigned h0, l0, h1, l1;
    split2h(v.x, v.y, h0, l0);
    split2h(v.z, v.w, h1, l1);
    __half* a0 = g_a0h + (size_t)z * APLANE;
    __half* a1 = g_a1h + (size_t)z * APLANE;
    *(unsigned*)(a0 + i)     = h0;
    *(unsigned*)(a0 + i + 2) = h1;
    *(unsigned*)(a1 + i)     = l0;
    *(unsigned*)(a1 + i + 2) = l1;
}

// ---------------------------------------------------------------------------
// convW (batched z=4): fp32 W[k][n] -> transposed single fp16 plane [n][k]
// ---------------------------------------------------------------------------
__global__ void convW_kernel(const float* __restrict__ W0,
                             const float* __restrict__ W1,
                             const float* __restrict__ W2,
                             const float* __restrict__ W3)
{
    const int z = blockIdx.z;
    const float* W = (z == 0) ? W0 : (z == 1) ? W1 : (z == 2) ? W2 : W3;
    __shared__ float tile[32][33];
    const int k0 = blockIdx.y * 32, n0 = blockIdx.x * 32;
    for (int r = threadIdx.y; r < 32; r += 8)
        tile[r][threadIdx.x] = W[(size_t)(k0 + r) * ND + n0 + threadIdx.x];
    __syncthreads();
    __half* w0 = g_w0h + (size_t)z * WPLANE;
    for (int r = threadIdx.y; r < 32; r += 8) {
        const float v = tile[threadIdx.x][r];
        w0[(size_t)(n0 + r) * ND + k0 + threadIdx.x] = __float2half(v);
    }
}

// ---------------------------------------------------------------------------
// vtrans: g_vh [bh][l][d] -> g_vth [bh][d][l]
// ---------------------------------------------------------------------------
__global__ void vtrans_kernel()
{
    __shared__ __half tl[64][65];
    const int bh = blockIdx.y;
    const int l0 = blockIdx.x * 64;
    const size_t pin = (size_t)bh * NL * DH;
#pragma unroll
    for (int i = 0; i < 8; i++) {
        const int u = threadIdx.x + i * 256;
        const int li = u >> 5, dp = u & 31;
        const __half2 v = *(const __half2*)(g_vh + pin + (size_t)(l0 + li) * DH + dp * 2);
        tl[li][dp * 2]     = __low2half(v);
        tl[li][dp * 2 + 1] = __high2half(v);
    }
    __syncthreads();
    const size_t pout = (size_t)bh * DH * NL;
#pragma unroll
    for (int i = 0; i < 8; i++) {
        const int u = threadIdx.x + i * 256;
        const int d = u >> 5, lp = u & 31;
        __half2 v = __halves2half2(tl[lp * 2][d], tl[lp * 2 + 1][d]);
        *(__half2*)(g_vth + pout + (size_t)d * NL + l0 + lp * 2) = v;
    }
}

// ---------------------------------------------------------------------------
// mask2bits
// ---------------------------------------------------------------------------
__global__ void mask2bits_kernel(const int* __restrict__ mask)
{
    const int gw = (blockIdx.x * 256 + threadIdx.x) >> 5;
    const int lane = threadIdx.x & 31;
    const int nwords = NB * NL * (NL / 32);
    const int step = (gridDim.x * 256) >> 5;
    for (int wv = gw; wv < nwords; wv += step) {
        const int v = mask[(size_t)wv * 32 + lane];
        const unsigned bits = __ballot_sync(0xffffffffu, v != 0);
        if (lane == 0) g_mbits[wv] = bits;
    }
}

// ---------------------------------------------------------------------------
// norm_attn
// ---------------------------------------------------------------------------
__global__ void norm_attn_kernel(float* __restrict__ attn_out)
{
    const int row = blockIdx.x;
    const float inv = 1.f / g_rsum[row];
    float4* p = (float4*)(attn_out + (size_t)row * NL);
    for (int i = threadIdx.x; i < NL / 4; i += 256) {
        float4 v = p[i];
        v.x *= inv; v.y *= inv; v.z *= inv; v.w *= inv;
        p[i] = v;
    }
}

// ---------------------------------------------------------------------------
// Shared GEMM mainloop (fp16 2-split: a0*b + a1*b), 512 threads / 16 warps.
// Warp tile 32x32. Tiles per stage: A0, A1, B (single fp16 weight plane).
// ---------------------------------------------------------------------------
#define GEMM_MAINLOOP(Aptr0, Aptr1, Wptr0)                                        \
    const __half* srcs[3] = { Aptr0, Aptr1, Wptr0 };                              \
    float acc[2][4][4];                                                           \
    _Pragma("unroll")                                                             \
    for (int mt = 0; mt < 2; mt++)                                                \
        _Pragma("unroll")                                                         \
        for (int nt = 0; nt < 4; nt++)                                            \
            _Pragma("unroll")                                                     \
            for (int r = 0; r < 4; r++) acc[mt][nt][r] = 0.f;                     \
    const int arow = (lane & 7) | (lane & 8);                                     \
    const int acol = (lane & 16) >> 1;                                            \
    const int brow = (lane & 7) | ((lane & 16) >> 1);                             \
    const int bcol = lane & 8;                                                    \
    {                                                                             \
        const unsigned sb = sb0;                                                  \
        const int row = t >> 2, seg = t & 3;                                      \
        _Pragma("unroll")                                                         \
        for (int s = 0; s < 3; s++)                                               \
            cpasync16(sb + s * TILE_B + (row * ASTR + seg * 8) * 2,               \
                      srcs[s] + (size_t)row * ND + seg * 8);                      \
        cp_commit();                                                              \
    }                                                                             \
    for (int c = 0; c < ND / BK; c++) {                                           \
        if (c + 1 < ND / BK) {                                                    \
            const unsigned sb = sb0 + ((c + 1) & 1) * STAGE_B;                    \
            const int k0 = (c + 1) * BK;                                          \
            const int row = t >> 2, seg = t & 3;                                  \
            _Pragma("unroll")                                                     \
            for (int s = 0; s < 3; s++)                                           \
                cpasync16(sb + s * TILE_B + (row * ASTR + seg * 8) * 2,           \
                          srcs[s] + (size_t)row * ND + k0 + seg * 8);             \
            cp_commit(); cp_wait1();                                              \
        } else { cp_wait0(); }                                                    \
        __syncthreads();                                                          \
        const unsigned sb = sb0 + (c & 1) * STAGE_B;                              \
        _Pragma("unroll")                                                         \
        for (int ks = 0; ks < 2; ks++) {                                          \
            const int kc = ks * 16;                                               \
            unsigned af[2][2][4];                                                 \
            _Pragma("unroll")                                                     \
            for (int sp = 0; sp < 2; sp++)                                        \
                _Pragma("unroll")                                                 \
                for (int mt = 0; mt < 2; mt++)                                    \
                    ldsm4(af[sp][mt][0], af[sp][mt][1], af[sp][mt][2], af[sp][mt][3], \
                          sb + sp * TILE_B +                                      \
                          (unsigned)(((wm + mt * 16 + arow) * ASTR + kc + acol) * 2)); \
            unsigned bf[2][4];                                                    \
            _Pragma("unroll")                                                     \
            for (int np = 0; np < 2; np++)                                        \
                ldsm4(bf[np][0], bf[np][1], bf[np][2], bf[np][3],                 \
                      sb + 2 * TILE_B +                                           \
                      (unsigned)(((wn + np * 16 + brow) * ASTR + kc + bcol) * 2)); \
            _Pragma("unroll")                                                     \
            for (int mt = 0; mt < 2; mt++)                                        \
                _Pragma("unroll")                                                 \
                for (int nt = 0; nt < 4; nt++) {                                  \
                    const int np = nt >> 1, half = (nt & 1) * 2;                  \
                    mma16816h(acc[mt][nt], af[0][mt], bf[np][half], bf[np][half + 1]); \
                    mma16816h(acc[mt][nt], af[1][mt], bf[np][half], bf[np][half + 1]); \
                }                                                                 \
        }                                                                         \
        __syncthreads();                                                          \
    }

// ---------------------------------------------------------------------------
// Batched projection GEMM (grid.z = 3, 512 threads): -> fp16 scatter
// ---------------------------------------------------------------------------
__global__ void __launch_bounds__(512, 1) gemm_proj_kernel(
    const float* __restrict__ b0p, const float* __restrict__ b1p,
    const float* __restrict__ b2p)
{
    extern __shared__ char smem[];
    const unsigned sb0 = smem_u32(smem);
    const int t = threadIdx.x, lane = t & 31, wid = t >> 5;
    const int wm = (wid & 3) * 32, wn = (wid >> 2) * 32;
    const int n0 = blockIdx.x * 128, m0 = blockIdx.y * 128;
    const int z = blockIdx.z;
    const float* bias = (z == 0) ? b0p : (z == 1) ? b1p : b2p;
    __half* dsth = (z == 0) ? g_kh : (z == 1) ? g_vh : g_qh;
    const float scale = (z == 2) ? 0.125f : 1.0f;

    GEMM_MAINLOOP(g_a0h + z * APLANE + (size_t)m0 * ND,
                  g_a1h + z * APLANE + (size_t)m0 * ND,
                  g_w0h + z * WPLANE + (size_t)n0 * ND)

#pragma unroll
    for (int mt = 0; mt < 2; mt++)
#pragma unroll
        for (int nt = 0; nt < 4; nt++) {
            const int cc = n0 + wn + nt * 8 + (lane & 3) * 2;
            const float b0 = bias[cc], b1 = bias[cc + 1];
            const float v0 = (acc[mt][nt][0] + b0) * scale;
            const float v1 = (acc[mt][nt][1] + b1) * scale;
            const float v2 = (acc[mt][nt][2] + b0) * scale;
            const float v3 = (acc[mt][nt][3] + b1) * scale;
            const int r0 = m0 + wm + mt * 16 + (lane >> 2);
            const int bb = r0 >> 11, h = cc >> 6, d = cc & 63;
            size_t o = ((size_t)(bb * NH + h) * NL + (r0 & (NL - 1))) * DH + d;
            *(unsigned*)(dsth + o) = pkhf2(v0, v1);
            o = ((size_t)(bb * NH + h) * NL + ((r0 + 8) & (NL - 1))) * DH + d;
            *(unsigned*)(dsth + o) = pkhf2(v2, v3);
        }
}

// ---------------------------------------------------------------------------
// Output GEMM (512 threads): (ctx @ Wo + bo) -> fp32
// ---------------------------------------------------------------------------
__global__ void __launch_bounds__(512, 1) gemm_out_kernel(
    const float* __restrict__ bias, float* __restrict__ dstf)
{
    extern __shared__ char smem[];
    const unsigned sb0 = smem_u32(smem);
    const int t = threadIdx.x, lane = t & 31, wid = t >> 5;
    const int wm = (wid & 3) * 32, wn = (wid >> 2) * 32;
    const int n0 = blockIdx.x * 128, m0 = blockIdx.y * 128;

    GEMM_MAINLOOP(g_a0h + (size_t)m0 * ND, g_a1h + (size_t)m0 * ND,
                  g_w0h + 3 * WPLANE + (size_t)n0 * ND)

#pragma unroll
    for (int mt = 0; mt < 2; mt++)
#pragma unroll
        for (int nt = 0; nt < 4; nt++) {
            const int cc = n0 + wn + nt * 8 + (lane & 3) * 2;
            const float b0 = bias[cc], b1 = bias[cc + 1];
            const int r0 = m0 + wm + mt * 16 + (lane >> 2);
            dstf[(size_t)r0 * ND + cc]           = acc[mt][nt][0] + b0;
            dstf[(size_t)r0 * ND + cc + 1]       = acc[mt][nt][1] + b1;
            dstf[(size_t)(r0 + 8) * ND + cc]     = acc[mt][nt][2] + b0;
            dstf[(size_t)(r0 + 8) * ND + cc + 1] = acc[mt][nt][3] + b1;
        }
}

// ---------------------------------------------------------------------------
// Fused fp16 flash attention (round-13 proven; epilogue emits fp16 splits)
// ---------------------------------------------------------------------------
__global__ void __launch_bounds__(256, 1) attn_fused_kernel(
    float* __restrict__ attn_out)
{
    extern __shared__ char smem[];
    const unsigned sb = smem_u32(smem);
    const int t = threadIdx.x, lane = t & 31, w = t >> 5;
    const int q0 = blockIdx.x * QT;
    const int h = blockIdx.y, b = blockIdx.z;
    const int bh = b * NH + h;

    const __half* kph = g_kh + (size_t)bh * NL * DH;
    const __half* vph = g_vth + (size_t)bh * DH * NL;
    const __half* qph = g_qh + (size_t)bh * NL * DH;

    const int arow = (lane & 7) | (lane & 8);
    const int acol = (lane & 16) >> 1;
    const int brow = (lane & 7) | ((lane & 16) >> 1);
    const int bcol = lane & 8;

#pragma unroll
    for (int i = 0; i < 2; i++) {
        const int u = t + i * 256;
        const int r = u >> 3, seg = u & 7;
        cpasync16(sb + QOFF + r * (KST * 2) + seg * 16,
                  qph + (size_t)(q0 + r) * DH + seg * 8);
    }

    const unsigned* mb = g_mbits;

#define AISSUE(c) do {                                                           \
    const unsigned st_ = sb + ((c) & 1) * ASTAGE;                                \
    const int kt_ = (c) * KCH;                                                   \
    _Pragma("unroll")                                                            \
    for (int i = 0; i < 4; i++) {                                                \
        const int u = t + i * 256;                                               \
        const int r = u >> 3, seg = u & 7;                                       \
        cpasync16(st_ + r * (KST * 2) + seg * 16,                                \
                  kph + (size_t)(kt_ + r) * DH + seg * 8);                       \
    }                                                                            \
    _Pragma("unroll")                                                            \
    for (int i = 0; i < 4; i++) {                                                \
        const int u = t + i * 256;                                               \
        const int r = u >> 4, seg = u & 15;                                      \
        cpasync16(st_ + VOFF + r * (VST * 2) + seg * 16,                         \
                  vph + (size_t)r * NL + kt_ + seg * 8);                         \
    }                                                                            \
    if (t < QT)                                                                  \
        cpasync16(st_ + MSK_OFF + t * 16,                                        \
                  mb + ((size_t)b * NL + q0 + t) * (NL / 32) + (kt_ >> 5));      \
    cp_commit();                                                                 \
} while (0)

    float accv[4][8][4];
#pragma unroll
    for (int mt = 0; mt < 4; mt++)
#pragma unroll
        for (int nt = 0; nt < 8; nt++)
#pragma unroll
            for (int r = 0; r < 4; r++) accv[mt][nt][r] = 0.f;
    float rs[4][2];
#pragma unroll
    for (int mt = 0; mt < 4; mt++) { rs[mt][0] = 0.f; rs[mt][1] = 0.f; }

    AISSUE(0);
    for (int c = 0; c < NL / KCH; c++) {
        if (c + 1 < NL / KCH) { AISSUE(c + 1); cp_wait1(); }
        else                  { cp_wait0(); }
        __syncthreads();
        const unsigned st = sb + (c & 1) * ASTAGE;
        const int kt = c * KCH;

        float accs[4][2][4];
#pragma unroll
        for (int mt = 0; mt < 4; mt++)
#pragma unroll
            for (int nt = 0; nt < 2; nt++)
#pragma unroll
                for (int r = 0; r < 4; r++) accs[mt][nt][r] = 0.f;

#pragma unroll
        for (int ks = 0; ks < 4; ks++) {
            const int kc = ks * 16;
            unsigned bk[4];
            ldsm4(bk[0], bk[1], bk[2], bk[3],
                  st + (unsigned)((w * 16 + brow) * (KST * 2) + (kc + bcol) * 2));
#pragma unroll
            for (int mt = 0; mt < 4; mt++) {
                unsigned aq[4];
                ldsm4(aq[0], aq[1], aq[2], aq[3],
                      sb + QOFF +
                      (unsigned)((mt * 16 + arow) * (KST * 2) + (kc + acol) * 2));
                mma16816h(accs[mt][0], aq, bk[0], bk[1]);
                mma16816h(accs[mt][1], aq, bk[2], bk[3]);
            }
        }

        unsigned bv[4][4];
#pragma unroll
        for (int np = 0; np < 4; np++)
            ldsm4(bv[np][0], bv[np][1], bv[np][2], bv[np][3],
                  st + VOFF +
                  (unsigned)((np * 16 + brow) * (VST * 2) + (w * 16 + bcol) * 2));

#pragma unroll
        for (int mt = 0; mt < 4; mt++) {
            const int r = lane >> 2;
            const unsigned mw0 = *(const unsigned*)(smem + (c & 1) * ASTAGE + MSK_OFF +
                                                    (mt * 16 + r) * 16 + (w >> 1) * 4);
            const unsigned mw1 = *(const unsigned*)(smem + (c & 1) * ASTAGE + MSK_OFF +
                                                    (mt * 16 + r + 8) * 16 + (w >> 1) * 4);
            const int bbase = (w & 1) * 16;
            float p[2][4];
#pragma unroll
            for (int nt = 0; nt < 2; nt++) {
                const int xb = bbase + nt * 8 + 2 * (lane & 3);
                p[nt][0] = ((mw0 >> xb) & 1)       ? 0.f : __expf(accs[mt][nt][0]);
                p[nt][1] = ((mw0 >> (xb + 1)) & 1) ? 0.f : __expf(accs[mt][nt][1]);
                p[nt][2] = ((mw1 >> xb) & 1)       ? 0.f : __expf(accs[mt][nt][2]);
                p[nt][3] = ((mw1 >> (xb + 1)) & 1) ? 0.f : __expf(accs[mt][nt][3]);
            }
            rs[mt][0] += p[0][0] + p[0][1] + p[1][0] + p[1][1];
            rs[mt][1] += p[0][2] + p[0][3] + p[1][2] + p[1][3];
            if (h == 0) {
                const size_t base = ((size_t)b * NL + q0 + mt * 16 + r) * NL + kt + w * 16;
                const int cc = 2 * (lane & 3);
                *(float2*)(attn_out + base + cc)               = make_float2(p[0][0], p[0][1]);
                *(float2*)(attn_out + base + 8 + cc)           = make_float2(p[1][0], p[1][1]);
                *(float2*)(attn_out + base + (size_t)8 * NL + cc)     = make_float2(p[0][2], p[0][3]);
                *(float2*)(attn_out + base + (size_t)8 * NL + 8 + cc) = make_float2(p[1][2], p[1][3]);
            }
            unsigned ap[4];
            ap[0] = pkhf2(p[0][0], p[0][1]);
            ap[1] = pkhf2(p[0][2], p[0][3]);
            ap[2] = pkhf2(p[1][0], p[1][1]);
            ap[3] = pkhf2(p[1][2], p[1][3]);
#pragma unroll
            for (int nt = 0; nt < 8; nt++) {
                const int np = nt >> 1, hf = (nt & 1) * 2;
                mma16816h(accv[mt][nt], ap, bv[np][hf], bv[np][hf + 1]);
            }
        }
        __syncthreads();
    }
#undef AISSUE

#pragma unroll
    for (int mt = 0; mt < 4; mt++)
#pragma unroll
        for (int hf = 0; hf < 2; hf++) {
            float v = rs[mt][hf];
            v += __shfl_xor_sync(0xffffffffu, v, 1);
            v += __shfl_xor_sync(0xffffffffu, v, 2);
            if ((lane & 3) == 0)
                *(float*)(smem + RSPOFF + (w * QT + mt * 16 + hf * 8 + (lane >> 2)) * 4) = v;
        }

    float* red = (float*)smem;
#pragma unroll
    for (int mt = 0; mt < 4; mt++)
#pragma unroll
        for (int nt = 0; nt < 8; nt++) {
            const int r0 = mt * 16 + (lane >> 2);
            const int cc = nt * 8 + 2 * (lane & 3);
            *(float2*)&red[(w * QT + r0) * 64 + (cc ^ ((r0 & 3) << 3))] =
                make_float2(accv[mt][nt][0], accv[mt][nt][1]);
            const int r1 = r0 + 8;
            *(float2*)&red[(w * QT + r1) * 64 + (cc ^ ((r1 & 3) << 3))] =
                make_float2(accv[mt][nt][2], accv[mt][nt][3]);
        }
    __syncthreads();

    float* invs = (float*)(smem + INVOFF);
    if (t < QT) {
        float s = 0.f;
#pragma unroll
        for (int ww = 0; ww < 8; ww++)
            s += *(float*)(smem + RSPOFF + (ww * QT + t) * 4);
        invs[t] = 1.f / s;
        if (h == 0) g_rsum[(size_t)b * NL + q0 + t] = s;
    }
    __syncthreads();

    for (int idx = t; idx < QT * DH / 2; idx += 256) {
        const int q = idx >> 5, dp = idx & 31;
        const int d0 = dp * 2, sw = (q & 3) << 3;
        float s0 = 0.f, s1 = 0.f;
#pragma unroll
        for (int ww = 0; ww < 8; ww++) {
            const float* rr = &red[(ww * QT + q) * 64];
            s0 += rr[d0 ^ sw];
            s1 += rr[(d0 + 1) ^ sw];
        }
        const float inv = invs[q];
        s0 *= inv; s1 *= inv;
        unsigned hi, lo;
        split2h(s0, s1, hi, lo);
        const size_t off = ((size_t)(b * NL + q0 + q)) * ND + h * DH + d0;
        *(unsigned*)(g_a0h + off) = hi;
        *(unsigned*)(g_a1h + off) = lo;
    }
}

// ---------------------------------------------------------------------------
extern "C" void kernel_launch(void* const* d_in, const int* in_sizes, int n_in,
                              void* d_out, int out_size)
{
    const float* key   = (const float*)d_in[0];
    const float* value = (const float*)d_in[1];
    const float* query = (const float*)d_in[2];
    const int*   mask  = (const int*)d_in[3];
    const float* Wk = (const float*)d_in[4];
    const float* bk = (const float*)d_in[5];
    const float* Wv = (const float*)d_in[6];
    const float* bv = (const float*)d_in[7];
    const float* Wq = (const float*)d_in[8];
    const float* bq = (const float*)d_in[9];
    const float* Wo = (const float*)d_in[10];
    const float* bo = (const float*)d_in[11];

    float* out      = (float*)d_out;
    float* attn_out = out + (size_t)NB * NL * ND;

    static int attr_set = 0;
    if (!attr_set) {
        cudaFuncSetAttribute(gemm_proj_kernel, cudaFuncAttributeMaxDynamicSharedMemorySize, GSMEM);
        cudaFuncSetAttribute(gemm_out_kernel, cudaFuncAttributeMaxDynamicSharedMemorySize, GSMEM);
        cudaFuncSetAttribute(attn_fused_kernel, cudaFuncAttributeMaxDynamicSharedMemorySize, ASMEM);
        attr_set = 1;
    }

    const int convA_blocks = (NB * NL * ND) / (4 * 256);       // 8192
    const dim3 gemm_grid(ND / 128, (NB * NL) / 128, 3);        // 8 x 64 x 3

    convA_kernel<<<dim3(convA_blocks, 3), 256>>>(key, value, query);
    convW_kernel<<<dim3(ND / 32, ND / 32, 4), dim3(32, 8)>>>(Wk, Wv, Wq, Wo);
    gemm_proj_kernel<<<gemm_grid, 512, GSMEM>>>(bk, bv, bq);

    vtrans_kernel<<<dim3(NL / 64, NB * NH), 256>>>();
    mask2bits_kernel<<<1024, 256>>>(mask);

    const dim3 attn_grid(NL / QT, NH, NB);   // 32 x 16 x 4
    attn_fused_kernel<<<attn_grid, 256, ASMEM>>>(attn_out);
    norm_attn_kernel<<<NB * NL, 256>>>(attn_out);

    gemm_out_kernel<<<dim3(ND / 128, (NB * NL) / 128), 512, GSMEM>>>(bo, out);
}

// round 16
// speedup vs baseline: 5.2504x; 1.1186x over previous
#include <cuda_runtime.h>
#include <cuda_bf16.h>
#include <cuda_fp16.h>

#define NB 4
#define NL 2048
#define ND 1024
#define NH 16
#define DH 64

// ---------------- mma.sync GEMM config (fp16 2-split, 512 thr, 2 CTA/SM) ---
#define BK    32
#define ASTR  40
#define TILE_B (128*ASTR*2)          // 10240 B per tile (fp16)
#define STAGE_B (3*TILE_B)           // 30720 B per stage (A0, A1, B)
#define GSMEM  (2*STAGE_B)           // 61440 B
#define APLANE ((size_t)NB*NL*ND)
#define WPLANE ((size_t)ND*ND)

// ---------------- fused fp16 attention config (QT=64, round-13 proven) -----
#define QT    64
#define KCH   128
#define KST   72
#define VST   136
#define KTILE (KCH*KST*2)
#define VTILE (64*VST*2)
#define VOFF  KTILE
#define MSK_OFF (KTILE + VTILE)
#define ASTAGE  (MSK_OFF + QT*16)
#define QOFF    (2*ASTAGE)
#define QSPL    (QT*KST*2)
#define RED_B   (8*QT*64*4)
#define RSPOFF  RED_B
#define INVOFF  (RSPOFF + 8*QT*4)
#define ASMEM   (INVOFF + QT*4)

// ---- cp.async ----
__device__ __forceinline__ void cpasync16(unsigned dst, const void* src) {
    asm volatile("cp.async.cg.shared.global [%0], [%1], 16;" :: "r"(dst), "l"(src) : "memory");
}
__device__ __forceinline__ void cp_commit() { asm volatile("cp.async.commit_group;" ::: "memory"); }
__device__ __forceinline__ void cp_wait0()  { asm volatile("cp.async.wait_group 0;" ::: "memory"); }
__device__ __forceinline__ void cp_wait1()  { asm volatile("cp.async.wait_group 1;" ::: "memory"); }
__device__ __forceinline__ unsigned smem_u32(const void* p) {
    unsigned a;
    asm("{ .reg .u64 t; cvta.to.shared.u64 t, %1; cvt.u32.u64 %0, t; }" : "=r"(a) : "l"(p));
    return a;
}
// ---- tensor-core (baseline PTX) ----
__device__ __forceinline__ void ldsm4(unsigned& r0, unsigned& r1,
                                      unsigned& r2, unsigned& r3, unsigned addr) {
    asm volatile("ldmatrix.sync.aligned.m8n8.x4.shared.b16 {%0,%1,%2,%3}, [%4];"
                 : "=r"(r0), "=r"(r1), "=r"(r2), "=r"(r3) : "r"(addr));
}
__device__ __forceinline__ void mma16816h(float* d, const unsigned* a,
                                          unsigned b0, unsigned b1) {
    asm volatile(
        "mma.sync.aligned.m16n8k16.row.col.f32.f16.f16.f32 "
        "{%0,%1,%2,%3}, {%4,%5,%6,%7}, {%8,%9}, {%0,%1,%2,%3};"
        : "+f"(d[0]), "+f"(d[1]), "+f"(d[2]), "+f"(d[3])
        : "r"(a[0]), "r"(a[1]), "r"(a[2]), "r"(a[3]), "r"(b0), "r"(b1));
}
__device__ __forceinline__ unsigned pkhf2(float pe, float po) {
    unsigned d;
    asm("cvt.rn.f16x2.f32 %0, %1, %2;" : "=r"(d) : "f"(po), "f"(pe));
    return d;
}
// fp16 2-split: hi = f16x2(pe,po), lo = f16x2 of residuals
__device__ __forceinline__ void split2h(float pe, float po, unsigned& hi, unsigned& lo) {
    hi = pkhf2(pe, po);
    const __half2 h = *reinterpret_cast<const __half2*>(&hi);
    lo = pkhf2(pe - __half2float(__low2half(h)), po - __half2float(__high2half(h)));
}

// Scratch device globals
__device__ __half g_a0h[3 * APLANE];   // A hi planes (K/V/Q inputs; plane 0 reused for ctx)
__device__ __half g_a1h[3 * APLANE];   // A residual planes
__device__ __half g_w0h[4 * WPLANE];   // W^T fp16 planes (Wk, Wv, Wq, Wo)
__device__ __half g_kh[APLANE];
__device__ __half g_qh[APLANE];
__device__ __half g_vh[APLANE];
__device__ __half g_vth[APLANE];
__device__ unsigned g_mbits[(size_t)NB * NL * (NL / 32)];
__device__ float    g_rsum[(size_t)NB * NL];

// ---------------------------------------------------------------------------
// convA (batched y=3): fp32 [M,1024] -> fp16 hi/lo splits
// ---------------------------------------------------------------------------
__global__ void convA_kernel(const float* __restrict__ s0,
                             const float* __restrict__ s1,
                             const float* __restrict__ s2)
{
    const int z = blockIdx.y;
    const float* src = (z == 0) ? s0 : (z == 1) ? s1 : s2;
    const size_t i = ((size_t)blockIdx.x * 256 + threadIdx.x) * 4;
    const float4 v = *(const float4*)(src + i);
    unsigned h0, l0, h1, l1;
    split2h(v.x, v.y, h0, l0);
    split2h(v.z, v.w, h1, l1);
    __half* a0 = g_a0h + (size_t)z * APLANE;
    __half* a1 = g_a1h + (size_t)z * APLANE;
    *(unsigned*)(a0 + i)     = h0;
    *(unsigned*)(a0 + i + 2) = h1;
    *(unsigned*)(a1 + i)     = l0;
    *(unsigned*)(a1 + i + 2) = l1;
}

// ---------------------------------------------------------------------------
// convW (batched z=4): fp32 W[k][n] -> transposed single fp16 plane [n][k]
// ---------------------------------------------------------------------------
__global__ void convW_kernel(const float* __restrict__ W0,
                             const float* __restrict__ W1,
                             const float* __restrict__ W2,
                             const float* __restrict__ W3)
{
    const int z = blockIdx.z;
    const float* W = (z == 0) ? W0 : (z == 1) ? W1 : (z == 2) ? W2 : W3;
    __shared__ float tile[32][33];
    const int k0 = blockIdx.y * 32, n0 = blockIdx.x * 32;
    for (int r = threadIdx.y; r < 32; r += 8)
        tile[r][threadIdx.x] = W[(size_t)(k0 + r) * ND + n0 + threadIdx.x];
    __syncthreads();
    __half* w0 = g_w0h + (size_t)z * WPLANE;
    for (int r = threadIdx.y; r < 32; r += 8) {
        const float v = tile[threadIdx.x][r];
        w0[(size_t)(n0 + r) * ND + k0 + threadIdx.x] = __float2half(v);
    }
}

// ---------------------------------------------------------------------------
// vtrans: g_vh [bh][l][d] -> g_vth [bh][d][l]
// ---------------------------------------------------------------------------
__global__ void vtrans_kernel()
{
    __shared__ __half tl[64][65];
    const int bh = blockIdx.y;
    const int l0 = blockIdx.x * 64;
    const size_t pin = (size_t)bh * NL * DH;
#pragma unroll
    for (int i = 0; i < 8; i++) {
        const int u = threadIdx.x + i * 256;
        const int li = u >> 5, dp = u & 31;
        const __half2 v = *(const __half2*)(g_vh + pin + (size_t)(l0 + li) * DH + dp * 2);
        tl[li][dp * 2]     = __low2half(v);
        tl[li][dp * 2 + 1] = __high2half(v);
    }
    __syncthreads();
    const size_t pout = (size_t)bh * DH * NL;
#pragma unroll
    for (int i = 0; i < 8; i++) {
        const int u = threadIdx.x + i * 256;
        const int d = u >> 5, lp = u & 31;
        __half2 v = __halves2half2(tl[lp * 2][d], tl[lp * 2 + 1][d]);
        *(__half2*)(g_vth + pout + (size_t)d * NL + l0 + lp * 2) = v;
    }
}

// ---------------------------------------------------------------------------
// mask2bits
// ---------------------------------------------------------------------------
__global__ void mask2bits_kernel(const int* __restrict__ mask)
{
    const int gw = (blockIdx.x * 256 + threadIdx.x) >> 5;
    const int lane = threadIdx.x & 31;
    const int nwords = NB * NL * (NL / 32);
    const int step = (gridDim.x * 256) >> 5;
    for (int wv = gw; wv < nwords; wv += step) {
        const int v = mask[(size_t)wv * 32 + lane];
        const unsigned bits = __ballot_sync(0xffffffffu, v != 0);
        if (lane == 0) g_mbits[wv] = bits;
    }
}

// ---------------------------------------------------------------------------
// norm_attn
// ---------------------------------------------------------------------------
__global__ void norm_attn_kernel(float* __restrict__ attn_out)
{
    const int row = blockIdx.x;
    const float inv = 1.f / g_rsum[row];
    float4* p = (float4*)(attn_out + (size_t)row * NL);
    for (int i = threadIdx.x; i < NL / 4; i += 256) {
        float4 v = p[i];
        v.x *= inv; v.y *= inv; v.z *= inv; v.w *= inv;
        p[i] = v;
    }
}

// ---------------------------------------------------------------------------
// Shared GEMM mainloop (fp16 2-split), register-lean for 2 CTAs/SM.
// Per ks: load bf[2][4] once; per split load transient af[2][4], 8 mma.
// Live regs ~ acc(32) + bf(8) + af(8) + idx -> fits 63-reg cap.
// ---------------------------------------------------------------------------
#define GEMM_MAINLOOP(Aptr0, Aptr1, Wptr0)                                        \
    const __half* srcs[3] = { Aptr0, Aptr1, Wptr0 };                              \
    float acc[2][4][4];                                                           \
    _Pragma("unroll")                                                             \
    for (int mt = 0; mt < 2; mt++)                                                \
        _Pragma("unroll")                                                         \
        for (int nt = 0; nt < 4; nt++)                                            \
            _Pragma("unroll")                                                     \
            for (int r = 0; r < 4; r++) acc[mt][nt][r] = 0.f;                     \
    const int arow = (lane & 7) | (lane & 8);                                     \
    const int acol = (lane & 16) >> 1;                                            \
    const int brow = (lane & 7) | ((lane & 16) >> 1);                             \
    const int bcol = lane & 8;                                                    \
    {                                                                             \
        const unsigned sb = sb0;                                                  \
        const int row = t >> 2, seg = t & 3;                                      \
        _Pragma("unroll")                                                         \
        for (int s = 0; s < 3; s++)                                               \
            cpasync16(sb + s * TILE_B + (row * ASTR + seg * 8) * 2,               \
                      srcs[s] + (size_t)row * ND + seg * 8);                      \
        cp_commit();                                                              \
    }                                                                             \
    for (int c = 0; c < ND / BK; c++) {                                           \
        if (c + 1 < ND / BK) {                                                    \
            const unsigned sb = sb0 + ((c + 1) & 1) * STAGE_B;                    \
            const int k0 = (c + 1) * BK;                                          \
            const int row = t >> 2, seg = t & 3;                                  \
            _Pragma("unroll")                                                     \
            for (int s = 0; s < 3; s++)                                           \
                cpasync16(sb + s * TILE_B + (row * ASTR + seg * 8) * 2,           \
                          srcs[s] + (size_t)row * ND + k0 + seg * 8);             \
            cp_commit(); cp_wait1();                                              \
        } else { cp_wait0(); }                                                    \
        __syncthreads();                                                          \
        const unsigned sb = sb0 + (c & 1) * STAGE_B;                              \
        _Pragma("unroll")                                                         \
        for (int ks = 0; ks < 2; ks++) {                                          \
            const int kc = ks * 16;                                               \
            unsigned bf[2][4];                                                    \
            _Pragma("unroll")                                                     \
            for (int np = 0; np < 2; np++)                                        \
                ldsm4(bf[np][0], bf[np][1], bf[np][2], bf[np][3],                 \
                      sb + 2 * TILE_B +                                           \
                      (unsigned)(((wn + np * 16 + brow) * ASTR + kc + bcol) * 2)); \
            _Pragma("unroll")                                                     \
            for (int sp = 0; sp < 2; sp++) {                                      \
                unsigned af[2][4];                                                \
                _Pragma("unroll")                                                 \
                for (int mt = 0; mt < 2; mt++)                                    \
                    ldsm4(af[mt][0], af[mt][1], af[mt][2], af[mt][3],             \
                          sb + sp * TILE_B +                                      \
                          (unsigned)(((wm + mt * 16 + arow) * ASTR + kc + acol) * 2)); \
                _Pragma("unroll")                                                 \
                for (int mt = 0; mt < 2; mt++)                                    \
                    _Pragma("unroll")                                             \
                    for (int nt = 0; nt < 4; nt++) {                              \
                        const int np = nt >> 1, half = (nt & 1) * 2;              \
                        mma16816h(acc[mt][nt], af[mt], bf[np][half], bf[np][half + 1]); \
                    }                                                             \
            }                                                                     \
        }                                                                         \
        __syncthreads();                                                          \
    }

// ---------------------------------------------------------------------------
// Batched projection GEMM (grid.z = 3, 512 threads, 2 CTA/SM): -> fp16 scatter
// ---------------------------------------------------------------------------
__global__ void __launch_bounds__(512, 2) gemm_proj_kernel(
    const float* __restrict__ b0p, const float* __restrict__ b1p,
    const float* __restrict__ b2p)
{
    extern __shared__ char smem[];
    const unsigned sb0 = smem_u32(smem);
    const int t = threadIdx.x, lane = t & 31, wid = t >> 5;
    const int wm = (wid & 3) * 32, wn = (wid >> 2) * 32;
    const int n0 = blockIdx.x * 128, m0 = blockIdx.y * 128;
    const int z = blockIdx.z;
    const float* bias = (z == 0) ? b0p : (z == 1) ? b1p : b2p;
    __half* dsth = (z == 0) ? g_kh : (z == 1) ? g_vh : g_qh;
    const float scale = (z == 2) ? 0.125f : 1.0f;

    GEMM_MAINLOOP(g_a0h + z * APLANE + (size_t)m0 * ND,
                  g_a1h + z * APLANE + (size_t)m0 * ND,
                  g_w0h + z * WPLANE + (size_t)n0 * ND)

#pragma unroll
    for (int mt = 0; mt < 2; mt++)
#pragma unroll
        for (int nt = 0; nt < 4; nt++) {
            const int cc = n0 + wn + nt * 8 + (lane & 3) * 2;
            const float b0 = bias[cc], b1 = bias[cc + 1];
            const float v0 = (acc[mt][nt][0] + b0) * scale;
            const float v1 = (acc[mt][nt][1] + b1) * scale;
            const float v2 = (acc[mt][nt][2] + b0) * scale;
            const float v3 = (acc[mt][nt][3] + b1) * scale;
            const int r0 = m0 + wm + mt * 16 + (lane >> 2);
            const int bb = r0 >> 11, h = cc >> 6, d = cc & 63;
            size_t o = ((size_t)(bb * NH + h) * NL + (r0 & (NL - 1))) * DH + d;
            *(unsigned*)(dsth + o) = pkhf2(v0, v1);
            o = ((size_t)(bb * NH + h) * NL + ((r0 + 8) & (NL - 1))) * DH + d;
            *(unsigned*)(dsth + o) = pkhf2(v2, v3);
        }
}

// ---------------------------------------------------------------------------
// Output GEMM (512 threads, 2 CTA/SM): (ctx @ Wo + bo) -> fp32
// ---------------------------------------------------------------------------
__global__ void __launch_bounds__(512, 2) gemm_out_kernel(
    const float* __restrict__ bias, float* __restrict__ dstf)
{
    extern __shared__ char smem[];
    const unsigned sb0 = smem_u32(smem);
    const int t = threadIdx.x, lane = t & 31, wid = t >> 5;
    const int wm = (wid & 3) * 32, wn = (wid >> 2) * 32;
    const int n0 = blockIdx.x * 128, m0 = blockIdx.y * 128;

    GEMM_MAINLOOP(g_a0h + (size_t)m0 * ND, g_a1h + (size_t)m0 * ND,
                  g_w0h + 3 * WPLANE + (size_t)n0 * ND)

#pragma unroll
    for (int mt = 0; mt < 2; mt++)
#pragma unroll
        for (int nt = 0; nt < 4; nt++) {
            const int cc = n0 + wn + nt * 8 + (lane & 3) * 2;
            const float b0 = bias[cc], b1 = bias[cc + 1];
            const int r0 = m0 + wm + mt * 16 + (lane >> 2);
            dstf[(size_t)r0 * ND + cc]           = acc[mt][nt][0] + b0;
            dstf[(size_t)r0 * ND + cc + 1]       = acc[mt][nt][1] + b1;
            dstf[(size_t)(r0 + 8) * ND + cc]     = acc[mt][nt][2] + b0;
            dstf[(size_t)(r0 + 8) * ND + cc + 1] = acc[mt][nt][3] + b1;
        }
}

// ---------------------------------------------------------------------------
// Fused fp16 flash attention (round-13 proven; epilogue emits fp16 splits)
// ---------------------------------------------------------------------------
__global__ void __launch_bounds__(256, 1) attn_fused_kernel(
    float* __restrict__ attn_out)
{
    extern __shared__ char smem[];
    const unsigned sb = smem_u32(smem);
    const int t = threadIdx.x, lane = t & 31, w = t >> 5;
    const int q0 = blockIdx.x * QT;
    const int h = blockIdx.y, b = blockIdx.z;
    const int bh = b * NH + h;

    const __half* kph = g_kh + (size_t)bh * NL * DH;
    const __half* vph = g_vth + (size_t)bh * DH * NL;
    const __half* qph = g_qh + (size_t)bh * NL * DH;

    const int arow = (lane & 7) | (lane & 8);
    const int acol = (lane & 16) >> 1;
    const int brow = (lane & 7) | ((lane & 16) >> 1);
    const int bcol = lane & 8;

#pragma unroll
    for (int i = 0; i < 2; i++) {
        const int u = t + i * 256;
        const int r = u >> 3, seg = u & 7;
        cpasync16(sb + QOFF + r * (KST * 2) + seg * 16,
                  qph + (size_t)(q0 + r) * DH + seg * 8);
    }

    const unsigned* mb = g_mbits;

#define AISSUE(c) do {                                                           \
    const unsigned st_ = sb + ((c) & 1) * ASTAGE;                                \
    const int kt_ = (c) * KCH;                                                   \
    _Pragma("unroll")                                                            \
    for (int i = 0; i < 4; i++) {                                                \
        const int u = t + i * 256;                                               \
        const int r = u >> 3, seg = u & 7;                                       \
        cpasync16(st_ + r * (KST * 2) + seg * 16,                                \
                  kph + (size_t)(kt_ + r) * DH + seg * 8);                       \
    }                                                                            \
    _Pragma("unroll")                                                            \
    for (int i = 0; i < 4; i++) {                                                \
        const int u = t + i * 256;                                               \
        const int r = u >> 4, seg = u & 15;                                      \
        cpasync16(st_ + VOFF + r * (VST * 2) + seg * 16,                         \
                  vph + (size_t)r * NL + kt_ + seg * 8);                         \
    }                                                                            \
    if (t < QT)                                                                  \
        cpasync16(st_ + MSK_OFF + t * 16,                                        \
                  mb + ((size_t)b * NL + q0 + t) * (NL / 32) + (kt_ >> 5));      \
    cp_commit();                                                                 \
} while (0)

    float accv[4][8][4];
#pragma unroll
    for (int mt = 0; mt < 4; mt++)
#pragma unroll
        for (int nt = 0; nt < 8; nt++)
#pragma unroll
            for (int r = 0; r < 4; r++) accv[mt][nt][r] = 0.f;
    float rs[4][2];
#pragma unroll
    for (int mt = 0; mt < 4; mt++) { rs[mt][0] = 0.f; rs[mt][1] = 0.f; }

    AISSUE(0);
    for (int c = 0; c < NL / KCH; c++) {
        if (c + 1 < NL / KCH) { AISSUE(c + 1); cp_wait1(); }
        else                  { cp_wait0(); }
        __syncthreads();
        const unsigned st = sb + (c & 1) * ASTAGE;
        const int kt = c * KCH;

        float accs[4][2][4];
#pragma unroll
        for (int mt = 0; mt < 4; mt++)
#pragma unroll
            for (int nt = 0; nt < 2; nt++)
#pragma unroll
                for (int r = 0; r < 4; r++) accs[mt][nt][r] = 0.f;

#pragma unroll
        for (int ks = 0; ks < 4; ks++) {
            const int kc = ks * 16;
            unsigned bk[4];
            ldsm4(bk[0], bk[1], bk[2], bk[3],
                  st + (unsigned)((w * 16 + brow) * (KST * 2) + (kc + bcol) * 2));
#pragma unroll
            for (int mt = 0; mt < 4; mt++) {
                unsigned aq[4];
                ldsm4(aq[0], aq[1], aq[2], aq[3],
                      sb + QOFF +
                      (unsigned)((mt * 16 + arow) * (KST * 2) + (kc + acol) * 2));
                mma16816h(accs[mt][0], aq, bk[0], bk[1]);
                mma16816h(accs[mt][1], aq, bk[2], bk[3]);
            }
        }

        unsigned bv[4][4];
#pragma unroll
        for (int np = 0; np < 4; np++)
            ldsm4(bv[np][0], bv[np][1], bv[np][2], bv[np][3],
                  st + VOFF +
                  (unsigned)((np * 16 + brow) * (VST * 2) + (w * 16 + bcol) * 2));

#pragma unroll
        for (int mt = 0; mt < 4; mt++) {
            const int r = lane >> 2;
            const unsigned mw0 = *(const unsigned*)(smem + (c & 1) * ASTAGE + MSK_OFF +
                                                    (mt * 16 + r) * 16 + (w >> 1) * 4);
            const unsigned mw1 = *(const unsigned*)(smem + (c & 1) * ASTAGE + MSK_OFF +
                                                    (mt * 16 + r + 8) * 16 + (w >> 1) * 4);
            const int bbase = (w & 1) * 16;
            float p[2][4];
#pragma unroll
            for (int nt = 0; nt < 2; nt++) {
                const int xb = bbase + nt * 8 + 2 * (lane & 3);
                p[nt][0] = ((mw0 >> xb) & 1)       ? 0.f : __expf(accs[mt][nt][0]);
                p[nt][1] = ((mw0 >> (xb + 1)) & 1) ? 0.f : __expf(accs[mt][nt][1]);
                p[nt][2] = ((mw1 >> xb) & 1)       ? 0.f : __expf(accs[mt][nt][2]);
                p[nt][3] = ((mw1 >> (xb + 1)) & 1) ? 0.f : __expf(accs[mt][nt][3]);
            }
            rs[mt][0] += p[0][0] + p[0][1] + p[1][0] + p[1][1];
            rs[mt][1] += p[0][2] + p[0][3] + p[1][2] + p[1][3];
            if (h == 0) {
                const size_t base = ((size_t)b * NL + q0 + mt * 16 + r) * NL + kt + w * 16;
                const int cc = 2 * (lane & 3);
                *(float2*)(attn_out + base + cc)               = make_float2(p[0][0], p[0][1]);
                *(float2*)(attn_out + base + 8 + cc)           = make_float2(p[1][0], p[1][1]);
                *(float2*)(attn_out + base + (size_t)8 * NL + cc)     = make_float2(p[0][2], p[0][3]);
                *(float2*)(attn_out + base + (size_t)8 * NL + 8 + cc) = make_float2(p[1][2], p[1][3]);
            }
            unsigned ap[4];
            ap[0] = pkhf2(p[0][0], p[0][1]);
            ap[1] = pkhf2(p[0][2], p[0][3]);
            ap[2] = pkhf2(p[1][0], p[1][1]);
            ap[3] = pkhf2(p[1][2], p[1][3]);
#pragma unroll
            for (int nt = 0; nt < 8; nt++) {
                const int np = nt >> 1, hf = (nt & 1) * 2;
                mma16816h(accv[mt][nt], ap, bv[np][hf], bv[np][hf + 1]);
            }
        }
        __syncthreads();
    }
#undef AISSUE

#pragma unroll
    for (int mt = 0; mt < 4; mt++)
#pragma unroll
        for (int hf = 0; hf < 2; hf++) {
            float v = rs[mt][hf];
            v += __shfl_xor_sync(0xffffffffu, v, 1);
            v += __shfl_xor_sync(0xffffffffu, v, 2);
            if ((lane & 3) == 0)
                *(float*)(smem + RSPOFF + (w * QT + mt * 16 + hf * 8 + (lane >> 2)) * 4) = v;
        }

    float* red = (float*)smem;
#pragma unroll
    for (int mt = 0; mt < 4; mt++)
#pragma unroll
        for (int nt = 0; nt < 8; nt++) {
            const int r0 = mt * 16 + (lane >> 2);
            const int cc = nt * 8 + 2 * (lane & 3);
            *(float2*)&red[(w * QT + r0) * 64 + (cc ^ ((r0 & 3) << 3))] =
                make_float2(accv[mt][nt][0], accv[mt][nt][1]);
            const int r1 = r0 + 8;
            *(float2*)&red[(w * QT + r1) * 64 + (cc ^ ((r1 & 3) << 3))] =
                make_float2(accv[mt][nt][2], accv[mt][nt][3]);
        }
    __syncthreads();

    float* invs = (float*)(smem + INVOFF);
    if (t < QT) {
        float s = 0.f;
#pragma unroll
        for (int ww = 0; ww < 8; ww++)
            s += *(float*)(smem + RSPOFF + (ww * QT + t) * 4);
        invs[t] = 1.f / s;
        if (h == 0) g_rsum[(size_t)b * NL + q0 + t] = s;
    }
    __syncthreads();

    for (int idx = t; idx < QT * DH / 2; idx += 256) {
        const int q = idx >> 5, dp = idx & 31;
        const int d0 = dp * 2, sw = (q & 3) << 3;
        float s0 = 0.f, s1 = 0.f;
#pragma unroll
        for (int ww = 0; ww < 8; ww++) {
            const float* rr = &red[(ww * QT + q) * 64];
            s0 += rr[d0 ^ sw];
            s1 += rr[(d0 + 1) ^ sw];
        }
        const float inv = invs[q];
        s0 *= inv; s1 *= inv;
        unsigned hi, lo;
        split2h(s0, s1, hi, lo);
        const size_t off = ((size_t)(b * NL + q0 + q)) * ND + h * DH + d0;
        *(unsigned*)(g_a0h + off) = hi;
        *(unsigned*)(g_a1h + off) = lo;
    }
}

// ---------------------------------------------------------------------------
extern "C" void kernel_launch(void* const* d_in, const int* in_sizes, int n_in,
                              void* d_out, int out_size)
{
    const float* key   = (const float*)d_in[0];
    const float* value = (const float*)d_in[1];
    const float* query = (const float*)d_in[2];
    const int*   mask  = (const int*)d_in[3];
    const float* Wk = (const float*)d_in[4];
    const float* bk = (const float*)d_in[5];
    const float* Wv = (const float*)d_in[6];
    const float* bv = (const float*)d_in[7];
    const float* Wq = (const float*)d_in[8];
    const float* bq = (const float*)d_in[9];
    const float* Wo = (const float*)d_in[10];
    const float* bo = (const float*)d_in[11];

    float* out      = (float*)d_out;
    float* attn_out = out + (size_t)NB * NL * ND;

    static int attr_set = 0;
    if (!attr_set) {
        cudaFuncSetAttribute(gemm_proj_kernel, cudaFuncAttributeMaxDynamicSharedMemorySize, GSMEM);
        cudaFuncSetAttribute(gemm_out_kernel, cudaFuncAttributeMaxDynamicSharedMemorySize, GSMEM);
        cudaFuncSetAttribute(attn_fused_kernel, cudaFuncAttributeMaxDynamicSharedMemorySize, ASMEM);
        attr_set = 1;
    }

    const int convA_blocks = (NB * NL * ND) / (4 * 256);       // 8192
    const dim3 gemm_grid(ND / 128, (NB * NL) / 128, 3);        // 8 x 64 x 3

    convA_kernel<<<dim3(convA_blocks, 3), 256>>>(key, value, query);
    convW_kernel<<<dim3(ND / 32, ND / 32, 4), dim3(32, 8)>>>(Wk, Wv, Wq, Wo);
    gemm_proj_kernel<<<gemm_grid, 512, GSMEM>>>(bk, bv, bq);

    vtrans_kernel<<<dim3(NL / 64, NB * NH), 256>>>();
    mask2bits_kernel<<<1024, 256>>>(mask);

    const dim3 attn_grid(NL / QT, NH, NB);   // 32 x 16 x 4
    attn_fused_kernel<<<attn_grid, 256, ASMEM>>>(attn_out);
    norm_attn_kernel<<<NB * NL, 256>>>(attn_out);

    gemm_out_kernel<<<dim3(ND / 128, (NB * NL) / 128), 512, GSMEM>>>(bo, out);
}